// round 1
// baseline (speedup 1.0000x reference)
#include <cuda_runtime.h>
#include <math.h>

// ---------------- problem constants ----------------
#define BATCH   16
#define CH      256
#define NTOK    4096      // GRID*GRID
#define GRIDW   64
#define HEADS   8
#define HD      32
#define NQ      8
#define WS      8
#define NWD     8         // windows per dim
#define NWIN    64        // windows per batch
#define KVLEN   72        // 64 + NQ
#define HP      16        // pooled grid
#define HP2     256       // pooled positions per batch
#define SCALE   0.17677669529663687f  // 1/sqrt(32)

// ---------------- scratch (device globals, no allocs) ----------------
__device__ float g_xn   [(long)BATCH*NTOK*CH];      // 16.7M
__device__ float g_pooled[(long)BATCH*HP2*CH];      // 1M
__device__ float g_kpool [(long)BATCH*HP2*CH];
__device__ float g_vpool [(long)BATCH*HP2*CH];
__device__ float g_qin   [BATCH*NQ*CH];
__device__ float g_gk    [BATCH*NQ*CH];
__device__ float g_gv    [BATCH*NQ*CH];
__device__ float g_qkv  [(long)BATCH*NTOK*3*CH];    // 50.3M
__device__ float g_attout[(long)BATCH*NTOK*CH];
__device__ float g_xnew [(long)BATCH*NTOK*CH];
__device__ float g_xm   [(long)BATCH*NTOK*CH];
__device__ float g_h    [(long)BATCH*NTOK*4*CH];    // 67M

// ---------------- layernorm: one block per row of 256 ----------------
__global__ void layernorm_kernel(const float* __restrict__ x,
                                 const float* __restrict__ g,
                                 const float* __restrict__ b,
                                 float* __restrict__ out) {
    long row = blockIdx.x;
    int t = threadIdx.x;
    float v = x[row*CH + t];
    __shared__ float red[8];
    __shared__ float stat[2];
    int lane = t & 31, warp = t >> 5;
    float s = v;
    #pragma unroll
    for (int o = 16; o; o >>= 1) s += __shfl_xor_sync(~0u, s, o);
    if (lane == 0) red[warp] = s;
    __syncthreads();
    if (t == 0) {
        float z = 0.f;
        #pragma unroll
        for (int i = 0; i < 8; i++) z += red[i];
        stat[0] = z * (1.f/CH);
    }
    __syncthreads();
    float m = stat[0];
    float d = v - m;
    s = d*d;
    #pragma unroll
    for (int o = 16; o; o >>= 1) s += __shfl_xor_sync(~0u, s, o);
    if (lane == 0) red[warp] = s;
    __syncthreads();
    if (t == 0) {
        float z = 0.f;
        #pragma unroll
        for (int i = 0; i < 8; i++) z += red[i];
        stat[1] = rsqrtf(z * (1.f/CH) + 1e-5f);
    }
    __syncthreads();
    out[row*CH + t] = d * stat[1] * g[t] + b[t];
}

// ---------------- 4x4 avg pool: pooled[b][hw][c] ----------------
__global__ void pool_kernel(const float* __restrict__ xn, float* __restrict__ pooled) {
    int bidx = blockIdx.x;             // b*256 + hw
    int b = bidx >> 8, hw = bidx & 255;
    int py = hw >> 4, px = hw & 15;
    int c = threadIdx.x;
    float s = 0.f;
    #pragma unroll
    for (int dy = 0; dy < 4; dy++)
        #pragma unroll
        for (int dx = 0; dx < 4; dx++) {
            int n = (py*4 + dy)*GRIDW + px*4 + dx;
            s += xn[((long)b*NTOK + n)*CH + c];
        }
    pooled[(long)bidx*CH + c] = s * (1.f/16.f);
}

// ---------------- generic SGEMM: out[M,O] = A[M,K] @ W[O,K]^T + bias ----
// EPI: 0 = bias only; 1 = BN (e0=mean,e1=var,e2=gamma,e3=beta);
//      2 = exact GELU; 3 = residual add (e0 = resid[M,O])
template<int EPI>
__global__ void gemm_kernel(const float* __restrict__ A, const float* __restrict__ W,
                            const float* __restrict__ bias, float* __restrict__ out,
                            int M, int K, int O,
                            const float* __restrict__ e0, const float* __restrict__ e1,
                            const float* __restrict__ e2, const float* __restrict__ e3) {
    __shared__ float As[16][68];
    __shared__ float Bs[16][68];
    int tid = threadIdx.x;
    int m0 = blockIdx.y * 64;
    int o0 = blockIdx.x * 64;
    int tx = tid & 15, ty = tid >> 4;
    float acc[4][4] = {};
    for (int k0 = 0; k0 < K; k0 += 16) {
        #pragma unroll
        for (int i = 0; i < 4; i++) {
            int idx = tid + i*256;
            int r = idx >> 4, kk = idx & 15;
            As[kk][r] = A[(long)(m0 + r)*K + k0 + kk];
            Bs[kk][r] = W[(long)(o0 + r)*K + k0 + kk];
        }
        __syncthreads();
        #pragma unroll
        for (int kk = 0; kk < 16; kk++) {
            float4 av = *(const float4*)&As[kk][ty*4];
            float4 bv = *(const float4*)&Bs[kk][tx*4];
            float a[4] = {av.x, av.y, av.z, av.w};
            float bb[4] = {bv.x, bv.y, bv.z, bv.w};
            #pragma unroll
            for (int i = 0; i < 4; i++)
                #pragma unroll
                for (int j = 0; j < 4; j++)
                    acc[i][j] = fmaf(a[i], bb[j], acc[i][j]);
        }
        __syncthreads();
    }
    #pragma unroll
    for (int i = 0; i < 4; i++) {
        int m = m0 + ty*4 + i;
        #pragma unroll
        for (int j = 0; j < 4; j++) {
            int o = o0 + tx*4 + j;
            float y = acc[i][j] + bias[o];
            if (EPI == 1) {
                y = (y - e0[o]) * rsqrtf(e1[o] + 1e-5f) * e2[o] + e3[o];
            } else if (EPI == 2) {
                y = 0.5f * y * (1.0f + erff(y * 0.70710678118654752f));
            } else if (EPI == 3) {
                y += e0[(long)m*O + o];
            }
            out[(long)m*O + o] = y;
        }
    }
}

// ---------------- global cross-attention pooling path -----------------
// one block per (b, h): q = 8x32 (query_tokens), k/v = 256x32
__global__ void global_attn_kernel(const float* __restrict__ kpool,
                                   const float* __restrict__ vpool,
                                   const float* __restrict__ qtok,
                                   float* __restrict__ qin) {
    int b = blockIdx.x >> 3, h = blockIdx.x & 7;
    __shared__ float qs[NQ][HD];
    __shared__ float lg[NQ][HP2];
    int tid = threadIdx.x;
    { int q = tid >> 5, d = tid & 31; qs[q][d] = qtok[q*CH + h*HD + d]; }
    __syncthreads();
    // thread tid = key index
    float kreg[HD];
    const float* kr = kpool + ((long)b*HP2 + tid)*CH + h*HD;
    #pragma unroll
    for (int d = 0; d < HD; d++) kreg[d] = kr[d];
    #pragma unroll
    for (int q = 0; q < NQ; q++) {
        float s = 0.f;
        #pragma unroll
        for (int d = 0; d < HD; d++) s = fmaf(qs[q][d], kreg[d], s);
        lg[q][tid] = s * SCALE;
    }
    __syncthreads();
    // softmax: warp w handles row w
    int w = tid >> 5, lane = tid & 31;
    {
        float m = -1e30f;
        for (int j = lane; j < HP2; j += 32) m = fmaxf(m, lg[w][j]);
        #pragma unroll
        for (int o = 16; o; o >>= 1) m = fmaxf(m, __shfl_xor_sync(~0u, m, o));
        float s = 0.f;
        for (int j = lane; j < HP2; j += 32) { float e = __expf(lg[w][j] - m); lg[w][j] = e; s += e; }
        #pragma unroll
        for (int o = 16; o; o >>= 1) s += __shfl_xor_sync(~0u, s, o);
        float inv = 1.f / s;
        for (int j = lane; j < HP2; j += 32) lg[w][j] *= inv;
    }
    __syncthreads();
    int q = tid >> 5, d = tid & 31;
    float acc = 0.f;
    const float* vb = vpool + (long)b*HP2*CH + h*HD + d;
    for (int kk = 0; kk < HP2; kk++) acc = fmaf(lg[q][kk], vb[(long)kk*CH], acc);
    // qin = qout + broadcast query_tokens
    qin[(b*NQ + q)*CH + h*HD + d] = acc + qtok[q*CH + h*HD + d];
}

// ---------------- window attention ------------------------------------
// one block per (window, head). blockIdx.x = win*8 + h; win = (b*8+wy)*8+wx
__global__ void window_attn_kernel(const float* __restrict__ qkv,
                                   const float* __restrict__ gk,
                                   const float* __restrict__ gv,
                                   const float* __restrict__ rpb,
                                   float* __restrict__ attn_out,
                                   float* __restrict__ attout) {
    int h   = blockIdx.x & 7;
    int win = blockIdx.x >> 3;
    int wx = win & 7, wy = (win >> 3) & 7, b = win >> 6;
    int n_base = (wy*WS)*GRIDW + wx*WS;   // token = n_base + iy*64 + ix

    __shared__ float qs[64][33];
    __shared__ float ks[KVLEN][33];
    __shared__ float vs[KVLEN][33];
    __shared__ float lg[64][KVLEN];
    int tid = threadIdx.x;

    for (int idx = tid; idx < 64*HD; idx += 256) {
        int i = idx >> 5, d = idx & 31;
        int n = n_base + (i >> 3)*GRIDW + (i & 7);
        qs[i][d] = qkv[((long)b*NTOK + n)*(3*CH) + h*HD + d] * SCALE;
    }
    for (int idx = tid; idx < KVLEN*HD; idx += 256) {
        int j = idx >> 5, d = idx & 31;
        if (j < 64) {
            int n = n_base + (j >> 3)*GRIDW + (j & 7);
            long base = ((long)b*NTOK + n)*(3*CH) + h*HD + d;
            ks[j][d] = qkv[base + CH];
            vs[j][d] = qkv[base + 2*CH];
        } else {
            int nq = j - 64;
            ks[j][d] = gk[(b*NQ + nq)*CH + h*HD + d];
            vs[j][d] = gv[(b*NQ + nq)*CH + h*HD + d];
        }
    }
    __syncthreads();

    // logits + relative position bias
    for (int idx = tid; idx < 64*KVLEN; idx += 256) {
        int i = idx / KVLEN, j = idx - i*KVLEN;
        float s = 0.f;
        #pragma unroll
        for (int d = 0; d < HD; d++) s = fmaf(qs[i][d], ks[j][d], s);
        if (j < 64) {
            int diy = (i >> 3) - (j >> 3) + 7;
            int dix = (i & 7) - (j & 7) + 7;
            s += rpb[(diy*15 + dix)*HEADS + h];
        }
        lg[i][j] = s;
    }
    __syncthreads();

    // softmax over 72 per row; 8 warps x 8 rounds
    int wp = tid >> 5, lane = tid & 31;
    for (int it = 0; it < 8; it++) {
        int i = it*8 + wp;
        float m = -1e30f;
        for (int j = lane; j < KVLEN; j += 32) m = fmaxf(m, lg[i][j]);
        #pragma unroll
        for (int o = 16; o; o >>= 1) m = fmaxf(m, __shfl_xor_sync(~0u, m, o));
        float s = 0.f;
        for (int j = lane; j < KVLEN; j += 32) { float e = __expf(lg[i][j] - m); lg[i][j] = e; s += e; }
        #pragma unroll
        for (int o = 16; o; o >>= 1) s += __shfl_xor_sync(~0u, s, o);
        float inv = 1.f / s;
        for (int j = lane; j < KVLEN; j += 32) lg[i][j] *= inv;
    }
    __syncthreads();

    // emit attention probabilities (output #2): layout (B_, H, 64, 72)
    long abase = ((long)(win*HEADS + h))*64*KVLEN;
    for (int idx = tid; idx < 64*KVLEN; idx += 256) {
        int i = idx / KVLEN, j = idx - i*KVLEN;
        attn_out[abase + idx] = lg[i][j];
    }

    // AV: token-order write into attout
    for (int it = 0; it < 8; it++) {
        int i = it*8 + wp;
        int d = lane;
        float acc = 0.f;
        #pragma unroll
        for (int j = 0; j < KVLEN; j++) acc = fmaf(lg[i][j], vs[j][d], acc);
        int n = n_base + (i >> 3)*GRIDW + (i & 7);
        attout[((long)b*NTOK + n)*CH + h*HD + d] = acc;
    }
}

// ---------------- host launch ------------------------------------------
extern "C" void kernel_launch(void* const* d_in, const int* in_sizes, int n_in,
                              void* d_out, int out_size) {
    const float* x       = (const float*)d_in[0];
    const float* qtok    = (const float*)d_in[1];
    const float* kproj_w = (const float*)d_in[2];
    const float* kproj_b = (const float*)d_in[3];
    const float* kbn_g   = (const float*)d_in[4];
    const float* kbn_b   = (const float*)d_in[5];
    const float* kbn_m   = (const float*)d_in[6];
    const float* kbn_v   = (const float*)d_in[7];
    const float* vproj_w = (const float*)d_in[8];
    const float* vproj_b = (const float*)d_in[9];
    const float* vbn_g   = (const float*)d_in[10];
    const float* vbn_b   = (const float*)d_in[11];
    const float* vbn_m   = (const float*)d_in[12];
    const float* vbn_v   = (const float*)d_in[13];
    const float* ck_w    = (const float*)d_in[14];
    const float* ck_b    = (const float*)d_in[15];
    const float* cv_w    = (const float*)d_in[16];
    const float* cv_b    = (const float*)d_in[17];
    const float* rpb     = (const float*)d_in[18];
    const float* qkv_w   = (const float*)d_in[19];
    const float* qkv_b   = (const float*)d_in[20];
    const float* proj_w  = (const float*)d_in[21];
    const float* proj_b  = (const float*)d_in[22];
    const float* n1_g    = (const float*)d_in[23];
    const float* n1_b    = (const float*)d_in[24];
    const float* n2_g    = (const float*)d_in[25];
    const float* n2_b    = (const float*)d_in[26];
    const float* fc1_w   = (const float*)d_in[27];
    const float* fc1_b   = (const float*)d_in[28];
    const float* fc2_w   = (const float*)d_in[29];
    const float* fc2_b   = (const float*)d_in[30];

    float* out_x    = (float*)d_out;
    float* out_attn = out_x + (long)BATCH*NTOK*CH;

    float *xn, *pooled, *kpool, *vpool, *qin, *gk, *gv, *qkv, *attout, *xnew, *xm, *hbuf;
    cudaGetSymbolAddress((void**)&xn,     g_xn);
    cudaGetSymbolAddress((void**)&pooled, g_pooled);
    cudaGetSymbolAddress((void**)&kpool,  g_kpool);
    cudaGetSymbolAddress((void**)&vpool,  g_vpool);
    cudaGetSymbolAddress((void**)&qin,    g_qin);
    cudaGetSymbolAddress((void**)&gk,     g_gk);
    cudaGetSymbolAddress((void**)&gv,     g_gv);
    cudaGetSymbolAddress((void**)&qkv,    g_qkv);
    cudaGetSymbolAddress((void**)&attout, g_attout);
    cudaGetSymbolAddress((void**)&xnew,   g_xnew);
    cudaGetSymbolAddress((void**)&xm,     g_xm);
    cudaGetSymbolAddress((void**)&hbuf,   g_h);

    const int M = BATCH*NTOK;   // 65536

    // 1. LN1
    layernorm_kernel<<<M, 256>>>(x, n1_g, n1_b, xn);
    // 2. 4x4 avg pool
    pool_kernel<<<BATCH*HP2, 256>>>(xn, pooled);
    // 3/4. k,v projection + BN   (M=4096, K=256, O=256)
    gemm_kernel<1><<<dim3(4, 64), 256>>>(pooled, kproj_w, kproj_b, kpool,
                                         BATCH*HP2, CH, CH, kbn_m, kbn_v, kbn_g, kbn_b);
    gemm_kernel<1><<<dim3(4, 64), 256>>>(pooled, vproj_w, vproj_b, vpool,
                                         BATCH*HP2, CH, CH, vbn_m, vbn_v, vbn_g, vbn_b);
    // 5. global cross-attention -> qin = qout + q
    global_attn_kernel<<<BATCH*HEADS, 256>>>(kpool, vpool, qtok, qin);
    // 6/7. ck, cv  (M=128, K=256, O=256)
    gemm_kernel<0><<<dim3(4, 2), 256>>>(qin, ck_w, ck_b, gk, BATCH*NQ, CH, CH, 0, 0, 0, 0);
    gemm_kernel<0><<<dim3(4, 2), 256>>>(qin, cv_w, cv_b, gv, BATCH*NQ, CH, CH, 0, 0, 0, 0);
    // 8. qkv projection (token order; window partition is pure indexing later)
    gemm_kernel<0><<<dim3(12, 1024), 256>>>(xn, qkv_w, qkv_b, qkv, M, CH, 3*CH, 0, 0, 0, 0);
    // 9. window attention (writes attn probs to d_out + token-order AV output)
    window_attn_kernel<<<BATCH*NWIN*HEADS, 256>>>(qkv, gk, gv, rpb, out_attn, attout);
    // 10. proj + residual (shortcut = original x); window reverse is implicit
    gemm_kernel<3><<<dim3(4, 1024), 256>>>(attout, proj_w, proj_b, xnew, M, CH, CH, x, 0, 0, 0);
    // 11. LN2
    layernorm_kernel<<<M, 256>>>(xnew, n2_g, n2_b, xm);
    // 12. fc1 + exact GELU
    gemm_kernel<2><<<dim3(16, 1024), 256>>>(xm, fc1_w, fc1_b, hbuf, M, CH, 4*CH, 0, 0, 0, 0);
    // 13. fc2 + residual -> final x into d_out
    gemm_kernel<3><<<dim3(4, 1024), 256>>>(hbuf, fc2_w, fc2_b, out_x, M, 4*CH, CH, xnew, 0, 0, 0);
}

// round 2
// speedup vs baseline: 1.4057x; 1.4057x over previous
#include <cuda_runtime.h>
#include <math.h>

// ---------------- problem constants ----------------
#define BATCH   16
#define CH      256
#define NTOK    4096      // GRID*GRID
#define GRIDW   64
#define HEADS   8
#define HD      32
#define NQ      8
#define WS      8
#define NWIN    64        // windows per batch
#define KVLEN   72        // 64 + NQ
#define HP2     256       // pooled positions per batch
#define SCALE   0.17677669529663687f  // 1/sqrt(32)

// ---------------- scratch (device globals, no allocs) ----------------
__device__ float g_xn   [(long)BATCH*NTOK*CH];
__device__ float g_pooled[(long)BATCH*HP2*CH];
__device__ float g_kpool [(long)BATCH*HP2*CH];
__device__ float g_vpool [(long)BATCH*HP2*CH];
__device__ float g_qin   [BATCH*NQ*CH];
__device__ float g_gk    [BATCH*NQ*CH];
__device__ float g_gv    [BATCH*NQ*CH];
__device__ float g_qkv  [(long)BATCH*NTOK*3*CH];
__device__ float g_attout[(long)BATCH*NTOK*CH];
__device__ float g_xnew [(long)BATCH*NTOK*CH];
__device__ float g_xm   [(long)BATCH*NTOK*CH];
__device__ float g_h    [(long)BATCH*NTOK*4*CH];

// ---------------- helpers ----------------
__device__ __forceinline__ unsigned f2tf32(float f) {
    unsigned u;
    asm("cvt.rna.tf32.f32 %0, %1;" : "=r"(u) : "f"(f));
    return u;
}

__device__ __forceinline__ void mma_tf32(float* c, const unsigned* a, const unsigned* b) {
    asm volatile(
        "mma.sync.aligned.m16n8k8.row.col.f32.tf32.tf32.f32 "
        "{%0,%1,%2,%3}, {%4,%5,%6,%7}, {%8,%9}, {%0,%1,%2,%3};"
        : "+f"(c[0]), "+f"(c[1]), "+f"(c[2]), "+f"(c[3])
        : "r"(a[0]), "r"(a[1]), "r"(a[2]), "r"(a[3]), "r"(b[0]), "r"(b[1]));
}

// ---------------- layernorm: one block per row of 256 ----------------
__global__ void layernorm_kernel(const float* __restrict__ x,
                                 const float* __restrict__ g,
                                 const float* __restrict__ b,
                                 float* __restrict__ out) {
    long row = blockIdx.x;
    int t = threadIdx.x;
    float v = x[row*CH + t];
    __shared__ float red[8];
    __shared__ float stat[2];
    int lane = t & 31, warp = t >> 5;
    float s = v;
    #pragma unroll
    for (int o = 16; o; o >>= 1) s += __shfl_xor_sync(~0u, s, o);
    if (lane == 0) red[warp] = s;
    __syncthreads();
    if (t == 0) {
        float z = 0.f;
        #pragma unroll
        for (int i = 0; i < 8; i++) z += red[i];
        stat[0] = z * (1.f/CH);
    }
    __syncthreads();
    float m = stat[0];
    float d = v - m;
    s = d*d;
    #pragma unroll
    for (int o = 16; o; o >>= 1) s += __shfl_xor_sync(~0u, s, o);
    if (lane == 0) red[warp] = s;
    __syncthreads();
    if (t == 0) {
        float z = 0.f;
        #pragma unroll
        for (int i = 0; i < 8; i++) z += red[i];
        stat[1] = rsqrtf(z * (1.f/CH) + 1e-5f);
    }
    __syncthreads();
    out[row*CH + t] = d * stat[1] * g[t] + b[t];
}

// ---------------- 4x4 avg pool ----------------
__global__ void pool_kernel(const float* __restrict__ xn, float* __restrict__ pooled) {
    int bidx = blockIdx.x;
    int b = bidx >> 8, hw = bidx & 255;
    int py = hw >> 4, px = hw & 15;
    int c = threadIdx.x;
    float s = 0.f;
    #pragma unroll
    for (int dy = 0; dy < 4; dy++)
        #pragma unroll
        for (int dx = 0; dx < 4; dx++) {
            int n = (py*4 + dy)*GRIDW + px*4 + dx;
            s += xn[((long)b*NTOK + n)*CH + c];
        }
    pooled[(long)bidx*CH + c] = s * (1.f/16.f);
}

// ---------------- tf32 tensor-core GEMM ---------------------------------
// out[M,O] = A[M,K] @ W[O,K]^T + bias, epilogues as before.
// BM=128, BN=64, BK=32, 256 threads (8 warps: 4 m x 2 n), warp tile 32x32.
// EPI: 0 bias; 1 BN(e0=m,e1=v,e2=g,e3=b); 2 GELU; 3 residual add (e0[M,O])
template<int EPI>
__global__ void __launch_bounds__(256, 2)
mma_gemm(const float* __restrict__ A, const float* __restrict__ W,
         const float* __restrict__ bias, float* __restrict__ out,
         int M, int K, int O,
         const float* __restrict__ e0, const float* __restrict__ e1,
         const float* __restrict__ e2, const float* __restrict__ e3) {
    __shared__ unsigned As[32][136];   // [k][m], pad -> conflict-free frag loads
    __shared__ unsigned Bs[32][72];    // [k][n]

    int tid  = threadIdx.x;
    int warp = tid >> 5, lane = tid & 31;
    int wm = warp >> 1, wn = warp & 1;
    int m_warp = wm * 32, n_warp = wn * 32;
    int g = lane >> 2, tg = lane & 3;

    int m0 = blockIdx.y * 128;
    int o0 = blockIdx.x * 64;

    float acc[2][4][4] = {};

    // prefetch registers
    float4 pa[4], pb[2];
    const float4* Ag = (const float4*)A;
    const float4* Wg = (const float4*)W;
    int Kq = K >> 2;   // K in float4 units

    // load chunk 0
    #pragma unroll
    for (int i = 0; i < 4; i++) {
        int idx = tid + 256*i;
        int r = idx >> 3, c4 = idx & 7;
        pa[i] = Ag[(long)(m0 + r)*Kq + c4];
    }
    #pragma unroll
    for (int i = 0; i < 2; i++) {
        int idx = tid + 256*i;
        int r = idx >> 3, c4 = idx & 7;
        pb[i] = Wg[(long)(o0 + r)*Kq + c4];
    }

    for (int kc = 0; kc < K; kc += 32) {
        // STS current chunk (with tf32 conversion)
        #pragma unroll
        for (int i = 0; i < 4; i++) {
            int idx = tid + 256*i;
            int r = idx >> 3, c4 = idx & 7;
            As[c4*4+0][r] = f2tf32(pa[i].x);
            As[c4*4+1][r] = f2tf32(pa[i].y);
            As[c4*4+2][r] = f2tf32(pa[i].z);
            As[c4*4+3][r] = f2tf32(pa[i].w);
        }
        #pragma unroll
        for (int i = 0; i < 2; i++) {
            int idx = tid + 256*i;
            int r = idx >> 3, c4 = idx & 7;
            Bs[c4*4+0][r] = f2tf32(pb[i].x);
            Bs[c4*4+1][r] = f2tf32(pb[i].y);
            Bs[c4*4+2][r] = f2tf32(pb[i].z);
            Bs[c4*4+3][r] = f2tf32(pb[i].w);
        }
        __syncthreads();

        // prefetch next chunk
        if (kc + 32 < K) {
            int kq = (kc + 32) >> 2;
            #pragma unroll
            for (int i = 0; i < 4; i++) {
                int idx = tid + 256*i;
                int r = idx >> 3, c4 = idx & 7;
                pa[i] = Ag[(long)(m0 + r)*Kq + kq + c4];
            }
            #pragma unroll
            for (int i = 0; i < 2; i++) {
                int idx = tid + 256*i;
                int r = idx >> 3, c4 = idx & 7;
                pb[i] = Wg[(long)(o0 + r)*Kq + kq + c4];
            }
        }

        // compute 4 k-tiles of 8
        #pragma unroll
        for (int kt = 0; kt < 4; kt++) {
            unsigned af[2][4], bf[4][2];
            #pragma unroll
            for (int mt = 0; mt < 2; mt++) {
                int mb = m_warp + mt*16 + g;
                af[mt][0] = As[kt*8 + tg    ][mb];
                af[mt][1] = As[kt*8 + tg    ][mb + 8];
                af[mt][2] = As[kt*8 + tg + 4][mb];
                af[mt][3] = As[kt*8 + tg + 4][mb + 8];
            }
            #pragma unroll
            for (int nt = 0; nt < 4; nt++) {
                int nb = n_warp + nt*8 + g;
                bf[nt][0] = Bs[kt*8 + tg    ][nb];
                bf[nt][1] = Bs[kt*8 + tg + 4][nb];
            }
            #pragma unroll
            for (int mt = 0; mt < 2; mt++)
                #pragma unroll
                for (int nt = 0; nt < 4; nt++)
                    mma_tf32(acc[mt][nt], af[mt], bf[nt]);
        }
        __syncthreads();
    }

    // epilogue
    #pragma unroll
    for (int mt = 0; mt < 2; mt++) {
        #pragma unroll
        for (int nt = 0; nt < 4; nt++) {
            #pragma unroll
            for (int c = 0; c < 4; c++) {
                int m = m0 + m_warp + mt*16 + g + (c >> 1)*8;
                int o = o0 + n_warp + nt*8 + tg*2 + (c & 1);
                float y = acc[mt][nt][c] + bias[o];
                if (EPI == 1) {
                    y = (y - e0[o]) * rsqrtf(e1[o] + 1e-5f) * e2[o] + e3[o];
                } else if (EPI == 2) {
                    y = 0.5f * y * (1.0f + erff(y * 0.70710678118654752f));
                } else if (EPI == 3) {
                    y += e0[(long)m*O + o];
                }
                out[(long)m*O + o] = y;
            }
        }
    }
}

// ---------------- global cross-attention pooling path -----------------
__global__ void global_attn_kernel(const float* __restrict__ kpool,
                                   const float* __restrict__ vpool,
                                   const float* __restrict__ qtok,
                                   float* __restrict__ qin) {
    int b = blockIdx.x >> 3, h = blockIdx.x & 7;
    __shared__ float qs[NQ][HD];
    __shared__ float lg[NQ][HP2];
    int tid = threadIdx.x;
    { int q = tid >> 5, d = tid & 31; qs[q][d] = qtok[q*CH + h*HD + d]; }
    __syncthreads();
    float kreg[HD];
    const float* kr = kpool + ((long)b*HP2 + tid)*CH + h*HD;
    #pragma unroll
    for (int d = 0; d < HD; d++) kreg[d] = kr[d];
    #pragma unroll
    for (int q = 0; q < NQ; q++) {
        float s = 0.f;
        #pragma unroll
        for (int d = 0; d < HD; d++) s = fmaf(qs[q][d], kreg[d], s);
        lg[q][tid] = s * SCALE;
    }
    __syncthreads();
    int w = tid >> 5, lane = tid & 31;
    {
        float m = -1e30f;
        for (int j = lane; j < HP2; j += 32) m = fmaxf(m, lg[w][j]);
        #pragma unroll
        for (int o = 16; o; o >>= 1) m = fmaxf(m, __shfl_xor_sync(~0u, m, o));
        float s = 0.f;
        for (int j = lane; j < HP2; j += 32) { float e = __expf(lg[w][j] - m); lg[w][j] = e; s += e; }
        #pragma unroll
        for (int o = 16; o; o >>= 1) s += __shfl_xor_sync(~0u, s, o);
        float inv = 1.f / s;
        for (int j = lane; j < HP2; j += 32) lg[w][j] *= inv;
    }
    __syncthreads();
    int q = tid >> 5, d = tid & 31;
    float acc = 0.f;
    const float* vb = vpool + (long)b*HP2*CH + h*HD + d;
    for (int kk = 0; kk < HP2; kk++) acc = fmaf(lg[q][kk], vb[(long)kk*CH], acc);
    qin[(b*NQ + q)*CH + h*HD + d] = acc + qtok[q*CH + h*HD + d];
}

// ---------------- window attention ------------------------------------
__global__ void window_attn_kernel(const float* __restrict__ qkv,
                                   const float* __restrict__ gk,
                                   const float* __restrict__ gv,
                                   const float* __restrict__ rpb,
                                   float* __restrict__ attn_out,
                                   float* __restrict__ attout) {
    int h   = blockIdx.x & 7;
    int win = blockIdx.x >> 3;
    int wx = win & 7, wy = (win >> 3) & 7, b = win >> 6;
    int n_base = (wy*WS)*GRIDW + wx*WS;

    __shared__ float qs[64][33];
    __shared__ float ks[KVLEN][33];
    __shared__ float vs[KVLEN][33];
    __shared__ float lg[64][KVLEN];
    int tid = threadIdx.x;

    for (int idx = tid; idx < 64*HD; idx += 256) {
        int i = idx >> 5, d = idx & 31;
        int n = n_base + (i >> 3)*GRIDW + (i & 7);
        qs[i][d] = qkv[((long)b*NTOK + n)*(3*CH) + h*HD + d] * SCALE;
    }
    for (int idx = tid; idx < KVLEN*HD; idx += 256) {
        int j = idx >> 5, d = idx & 31;
        if (j < 64) {
            int n = n_base + (j >> 3)*GRIDW + (j & 7);
            long base = ((long)b*NTOK + n)*(3*CH) + h*HD + d;
            ks[j][d] = qkv[base + CH];
            vs[j][d] = qkv[base + 2*CH];
        } else {
            int nq = j - 64;
            ks[j][d] = gk[(b*NQ + nq)*CH + h*HD + d];
            vs[j][d] = gv[(b*NQ + nq)*CH + h*HD + d];
        }
    }
    __syncthreads();

    for (int idx = tid; idx < 64*KVLEN; idx += 256) {
        int i = idx / KVLEN, j = idx - i*KVLEN;
        float s = 0.f;
        #pragma unroll
        for (int d = 0; d < HD; d++) s = fmaf(qs[i][d], ks[j][d], s);
        if (j < 64) {
            int diy = (i >> 3) - (j >> 3) + 7;
            int dix = (i & 7) - (j & 7) + 7;
            s += rpb[(diy*15 + dix)*HEADS + h];
        }
        lg[i][j] = s;
    }
    __syncthreads();

    int wp = tid >> 5, lane = tid & 31;
    for (int it = 0; it < 8; it++) {
        int i = it*8 + wp;
        float m = -1e30f;
        for (int j = lane; j < KVLEN; j += 32) m = fmaxf(m, lg[i][j]);
        #pragma unroll
        for (int o = 16; o; o >>= 1) m = fmaxf(m, __shfl_xor_sync(~0u, m, o));
        float s = 0.f;
        for (int j = lane; j < KVLEN; j += 32) { float e = __expf(lg[i][j] - m); lg[i][j] = e; s += e; }
        #pragma unroll
        for (int o = 16; o; o >>= 1) s += __shfl_xor_sync(~0u, s, o);
        float inv = 1.f / s;
        for (int j = lane; j < KVLEN; j += 32) lg[i][j] *= inv;
    }
    __syncthreads();

    long abase = ((long)(win*HEADS + h))*64*KVLEN;
    for (int idx = tid; idx < 64*KVLEN; idx += 256) {
        int i = idx / KVLEN, j = idx - i*KVLEN;
        attn_out[abase + idx] = lg[i][j];
    }

    for (int it = 0; it < 8; it++) {
        int i = it*8 + wp;
        int d = lane;
        float acc = 0.f;
        #pragma unroll
        for (int j = 0; j < KVLEN; j++) acc = fmaf(lg[i][j], vs[j][d], acc);
        int n = n_base + (i >> 3)*GRIDW + (i & 7);
        attout[((long)b*NTOK + n)*CH + h*HD + d] = acc;
    }
}

// ---------------- host launch ------------------------------------------
extern "C" void kernel_launch(void* const* d_in, const int* in_sizes, int n_in,
                              void* d_out, int out_size) {
    const float* x       = (const float*)d_in[0];
    const float* qtok    = (const float*)d_in[1];
    const float* kproj_w = (const float*)d_in[2];
    const float* kproj_b = (const float*)d_in[3];
    const float* kbn_g   = (const float*)d_in[4];
    const float* kbn_b   = (const float*)d_in[5];
    const float* kbn_m   = (const float*)d_in[6];
    const float* kbn_v   = (const float*)d_in[7];
    const float* vproj_w = (const float*)d_in[8];
    const float* vproj_b = (const float*)d_in[9];
    const float* vbn_g   = (const float*)d_in[10];
    const float* vbn_b   = (const float*)d_in[11];
    const float* vbn_m   = (const float*)d_in[12];
    const float* vbn_v   = (const float*)d_in[13];
    const float* ck_w    = (const float*)d_in[14];
    const float* ck_b    = (const float*)d_in[15];
    const float* cv_w    = (const float*)d_in[16];
    const float* cv_b    = (const float*)d_in[17];
    const float* rpb     = (const float*)d_in[18];
    const float* qkv_w   = (const float*)d_in[19];
    const float* qkv_b   = (const float*)d_in[20];
    const float* proj_w  = (const float*)d_in[21];
    const float* proj_b  = (const float*)d_in[22];
    const float* n1_g    = (const float*)d_in[23];
    const float* n1_b    = (const float*)d_in[24];
    const float* n2_g    = (const float*)d_in[25];
    const float* n2_b    = (const float*)d_in[26];
    const float* fc1_w   = (const float*)d_in[27];
    const float* fc1_b   = (const float*)d_in[28];
    const float* fc2_w   = (const float*)d_in[29];
    const float* fc2_b   = (const float*)d_in[30];

    float* out_x    = (float*)d_out;
    float* out_attn = out_x + (long)BATCH*NTOK*CH;

    float *xn, *pooled, *kpool, *vpool, *qin, *gk, *gv, *qkv, *attout, *xnew, *xm, *hbuf;
    cudaGetSymbolAddress((void**)&xn,     g_xn);
    cudaGetSymbolAddress((void**)&pooled, g_pooled);
    cudaGetSymbolAddress((void**)&kpool,  g_kpool);
    cudaGetSymbolAddress((void**)&vpool,  g_vpool);
    cudaGetSymbolAddress((void**)&qin,    g_qin);
    cudaGetSymbolAddress((void**)&gk,     g_gk);
    cudaGetSymbolAddress((void**)&gv,     g_gv);
    cudaGetSymbolAddress((void**)&qkv,    g_qkv);
    cudaGetSymbolAddress((void**)&attout, g_attout);
    cudaGetSymbolAddress((void**)&xnew,   g_xnew);
    cudaGetSymbolAddress((void**)&xm,     g_xm);
    cudaGetSymbolAddress((void**)&hbuf,   g_h);

    const int M = BATCH*NTOK;   // 65536

    // 1. LN1
    layernorm_kernel<<<M, 256>>>(x, n1_g, n1_b, xn);
    // 2. 4x4 avg pool
    pool_kernel<<<BATCH*HP2, 256>>>(xn, pooled);
    // 3/4. k,v projection + BN   (M=4096, K=256, O=256)
    mma_gemm<1><<<dim3(4, 32), 256>>>(pooled, kproj_w, kproj_b, kpool,
                                      BATCH*HP2, CH, CH, kbn_m, kbn_v, kbn_g, kbn_b);
    mma_gemm<1><<<dim3(4, 32), 256>>>(pooled, vproj_w, vproj_b, vpool,
                                      BATCH*HP2, CH, CH, vbn_m, vbn_v, vbn_g, vbn_b);
    // 5. global cross-attention -> qin = qout + q
    global_attn_kernel<<<BATCH*HEADS, 256>>>(kpool, vpool, qtok, qin);
    // 6/7. ck, cv  (M=128)
    mma_gemm<0><<<dim3(4, 1), 256>>>(qin, ck_w, ck_b, gk, BATCH*NQ, CH, CH, 0, 0, 0, 0);
    mma_gemm<0><<<dim3(4, 1), 256>>>(qin, cv_w, cv_b, gv, BATCH*NQ, CH, CH, 0, 0, 0, 0);
    // 8. qkv projection (token order)
    mma_gemm<0><<<dim3(12, 512), 256>>>(xn, qkv_w, qkv_b, qkv, M, CH, 3*CH, 0, 0, 0, 0);
    // 9. window attention
    window_attn_kernel<<<BATCH*NWIN*HEADS, 256>>>(qkv, gk, gv, rpb, out_attn, attout);
    // 10. proj + residual
    mma_gemm<3><<<dim3(4, 512), 256>>>(attout, proj_w, proj_b, xnew, M, CH, CH, x, 0, 0, 0);
    // 11. LN2
    layernorm_kernel<<<M, 256>>>(xnew, n2_g, n2_b, xm);
    // 12. fc1 + exact GELU
    mma_gemm<2><<<dim3(16, 512), 256>>>(xm, fc1_w, fc1_b, hbuf, M, CH, 4*CH, 0, 0, 0, 0);
    // 13. fc2 + residual -> final x
    mma_gemm<3><<<dim3(4, 512), 256>>>(hbuf, fc2_w, fc2_b, out_x, M, 4*CH, CH, xnew, 0, 0, 0);
}

// round 3
// speedup vs baseline: 2.2531x; 1.6029x over previous
#include <cuda_runtime.h>
#include <math.h>

// ---------------- problem constants ----------------
#define BATCH   16
#define CH      256
#define NTOK    4096
#define GRIDW   64
#define HEADS   8
#define HD      32
#define NQ      8
#define WS      8
#define NWIN    64
#define KVLEN   72
#define HP2     256
#define SCALE   0.17677669529663687f

// ---------------- scratch ----------------
__device__ float g_xn   [(long)BATCH*NTOK*CH];
__device__ float g_pooled[(long)BATCH*HP2*CH];
__device__ float g_kpool [(long)BATCH*HP2*CH];
__device__ float g_vpool [(long)BATCH*HP2*CH];
__device__ float g_qin   [BATCH*NQ*CH];
__device__ float g_gk    [BATCH*NQ*CH];
__device__ float g_gv    [BATCH*NQ*CH];
__device__ float g_qkv  [(long)BATCH*NTOK*3*CH];
__device__ float g_attout[(long)BATCH*NTOK*CH];
__device__ float g_xnew [(long)BATCH*NTOK*CH];
__device__ float g_xm   [(long)BATCH*NTOK*CH];
__device__ float g_h    [(long)BATCH*NTOK*4*CH];

// ---------------- helpers ----------------
__device__ __forceinline__ void mma_tf32(float* c, const unsigned* a, const unsigned* b) {
    asm volatile(
        "mma.sync.aligned.m16n8k8.row.col.f32.tf32.tf32.f32 "
        "{%0,%1,%2,%3}, {%4,%5,%6,%7}, {%8,%9}, {%0,%1,%2,%3};"
        : "+f"(c[0]), "+f"(c[1]), "+f"(c[2]), "+f"(c[3])
        : "r"(a[0]), "r"(a[1]), "r"(a[2]), "r"(a[3]), "r"(b[0]), "r"(b[1]));
}

__device__ __forceinline__ void cp16(void* dst, const void* src) {
    unsigned d = (unsigned)__cvta_generic_to_shared(dst);
    asm volatile("cp.async.cg.shared.global [%0], [%1], 16;" :: "r"(d), "l"(src));
}
__device__ __forceinline__ void cp_commit() {
    asm volatile("cp.async.commit_group;");
}
__device__ __forceinline__ void cp_wait1() {
    asm volatile("cp.async.wait_group 1;");
}

// ---------------- layernorm ----------------
__global__ void layernorm_kernel(const float* __restrict__ x,
                                 const float* __restrict__ g,
                                 const float* __restrict__ b,
                                 float* __restrict__ out) {
    long row = blockIdx.x;
    int t = threadIdx.x;
    float v = x[row*CH + t];
    __shared__ float red[8];
    __shared__ float stat[2];
    int lane = t & 31, warp = t >> 5;
    float s = v;
    #pragma unroll
    for (int o = 16; o; o >>= 1) s += __shfl_xor_sync(~0u, s, o);
    if (lane == 0) red[warp] = s;
    __syncthreads();
    if (t == 0) {
        float z = 0.f;
        #pragma unroll
        for (int i = 0; i < 8; i++) z += red[i];
        stat[0] = z * (1.f/CH);
    }
    __syncthreads();
    float m = stat[0];
    float d = v - m;
    s = d*d;
    #pragma unroll
    for (int o = 16; o; o >>= 1) s += __shfl_xor_sync(~0u, s, o);
    if (lane == 0) red[warp] = s;
    __syncthreads();
    if (t == 0) {
        float z = 0.f;
        #pragma unroll
        for (int i = 0; i < 8; i++) z += red[i];
        stat[1] = rsqrtf(z * (1.f/CH) + 1e-5f);
    }
    __syncthreads();
    out[row*CH + t] = d * stat[1] * g[t] + b[t];
}

// ---------------- 4x4 avg pool ----------------
__global__ void pool_kernel(const float* __restrict__ xn, float* __restrict__ pooled) {
    int bidx = blockIdx.x;
    int b = bidx >> 8, hw = bidx & 255;
    int py = hw >> 4, px = hw & 15;
    int c = threadIdx.x;
    float s = 0.f;
    #pragma unroll
    for (int dy = 0; dy < 4; dy++)
        #pragma unroll
        for (int dx = 0; dx < 4; dx++) {
            int n = (py*4 + dy)*GRIDW + px*4 + dx;
            s += xn[((long)b*NTOK + n)*CH + c];
        }
    pooled[(long)bidx*CH + c] = s * (1.f/16.f);
}

// ---------------- tf32 double-buffered GEMM -----------------------------
// out[M,O] = A[M,K] @ W[O,K]^T + bias.  BM=BN=128, BK=32, 256 thr, 8 warps
// (2m x 4n), warp tile 64x32.  Raw fp32 bits fed to tf32 mma (truncation).
// EPI: 0 bias; 1 BN(e0=m,e1=v,e2=g,e3=b); 2 GELU; 3 residual add (e0[M,O])
#define PADK 36           // 32 + 4 pad (floats), 144B row stride
#define BUFSZ (128*PADK)  // floats per matrix per stage

template<int EPI>
__global__ void __launch_bounds__(256)
mma_gemm(const float* __restrict__ A, const float* __restrict__ W,
         const float* __restrict__ bias, float* __restrict__ out,
         int M, int K, int O,
         const float* __restrict__ e0, const float* __restrict__ e1,
         const float* __restrict__ e2, const float* __restrict__ e3) {
    extern __shared__ float smem[];
    float* As = smem;               // [2][128][PADK]
    float* Bs = smem + 2*BUFSZ;     // [2][128][PADK]

    int tid  = threadIdx.x;
    int warp = tid >> 5, lane = tid & 31;
    int wm = warp >> 2, wn = warp & 3;          // 2 x 4
    int m_warp = wm * 64, n_warp = wn * 32;
    int g = lane >> 2, tg = lane & 3;

    int m0 = blockIdx.y * 128;
    int o0 = blockIdx.x * 128;

    // loader indices: 1024 16B-granules per matrix per stage (128 rows x 8)
    int lr = tid >> 3;        // row   (tid/8), +32 per iter
    int lc = (tid & 7) * 4;   // float col within 32-float chunk

    float acc[4][4][4] = {};

    // prologue: stage 0
    {
        const float* Ag = A + (long)(m0 + lr)*K + lc;
        const float* Wg = W + (long)(o0 + lr)*K + lc;
        float* Ad = As + lr*PADK + lc;
        float* Bd = Bs + lr*PADK + lc;
        #pragma unroll
        for (int i = 0; i < 4; i++) {
            cp16(Ad + i*32*PADK, Ag + (long)i*32*K);
            cp16(Bd + i*32*PADK, Wg + (long)i*32*K);
        }
        cp_commit();
    }

    int buf = 0;
    for (int kc = 0; kc < K; kc += 32) {
        // issue next stage
        if (kc + 32 < K) {
            int nb = buf ^ 1;
            const float* Ag = A + (long)(m0 + lr)*K + kc + 32 + lc;
            const float* Wg = W + (long)(o0 + lr)*K + kc + 32 + lc;
            float* Ad = As + nb*BUFSZ + lr*PADK + lc;
            float* Bd = Bs + nb*BUFSZ + lr*PADK + lc;
            #pragma unroll
            for (int i = 0; i < 4; i++) {
                cp16(Ad + i*32*PADK, Ag + (long)i*32*K);
                cp16(Bd + i*32*PADK, Wg + (long)i*32*K);
            }
        }
        cp_commit();
        cp_wait1();
        __syncthreads();

        const float* As_b = As + buf*BUFSZ;
        const float* Bs_b = Bs + buf*BUFSZ;
        #pragma unroll
        for (int kt = 0; kt < 4; kt++) {
            int k0 = kt*8;
            unsigned af[4][4], bf[4][2];
            #pragma unroll
            for (int mt = 0; mt < 4; mt++) {
                int mb = m_warp + mt*16 + g;
                af[mt][0] = __float_as_uint(As_b[mb*PADK + k0 + tg]);
                af[mt][1] = __float_as_uint(As_b[(mb+8)*PADK + k0 + tg]);
                af[mt][2] = __float_as_uint(As_b[mb*PADK + k0 + tg + 4]);
                af[mt][3] = __float_as_uint(As_b[(mb+8)*PADK + k0 + tg + 4]);
            }
            #pragma unroll
            for (int nt = 0; nt < 4; nt++) {
                int nb2 = n_warp + nt*8 + g;
                bf[nt][0] = __float_as_uint(Bs_b[nb2*PADK + k0 + tg]);
                bf[nt][1] = __float_as_uint(Bs_b[nb2*PADK + k0 + tg + 4]);
            }
            #pragma unroll
            for (int mt = 0; mt < 4; mt++)
                #pragma unroll
                for (int nt = 0; nt < 4; nt++)
                    mma_tf32(acc[mt][nt], af[mt], bf[nt]);
        }
        __syncthreads();
        buf ^= 1;
    }

    // epilogue
    #pragma unroll
    for (int mt = 0; mt < 4; mt++) {
        #pragma unroll
        for (int nt = 0; nt < 4; nt++) {
            #pragma unroll
            for (int c = 0; c < 4; c++) {
                int m = m0 + m_warp + mt*16 + g + (c >> 1)*8;
                int o = o0 + n_warp + nt*8 + tg*2 + (c & 1);
                float y = acc[mt][nt][c] + bias[o];
                if (EPI == 1) {
                    y = (y - e0[o]) * rsqrtf(e1[o] + 1e-5f) * e2[o] + e3[o];
                } else if (EPI == 2) {
                    y = 0.5f * y * (1.0f + erff(y * 0.70710678118654752f));
                } else if (EPI == 3) {
                    y += e0[(long)m*O + o];
                }
                out[(long)m*O + o] = y;
            }
        }
    }
}

// ---------------- global cross-attention pooling path -----------------
__global__ void global_attn_kernel(const float* __restrict__ kpool,
                                   const float* __restrict__ vpool,
                                   const float* __restrict__ qtok,
                                   float* __restrict__ qin) {
    int b = blockIdx.x >> 3, h = blockIdx.x & 7;
    __shared__ float qs[NQ][HD];
    __shared__ float lg[NQ][HP2];
    int tid = threadIdx.x;
    { int q = tid >> 5, d = tid & 31; qs[q][d] = qtok[q*CH + h*HD + d]; }
    __syncthreads();
    float kreg[HD];
    const float* kr = kpool + ((long)b*HP2 + tid)*CH + h*HD;
    #pragma unroll
    for (int d = 0; d < HD; d++) kreg[d] = kr[d];
    #pragma unroll
    for (int q = 0; q < NQ; q++) {
        float s = 0.f;
        #pragma unroll
        for (int d = 0; d < HD; d++) s = fmaf(qs[q][d], kreg[d], s);
        lg[q][tid] = s * SCALE;
    }
    __syncthreads();
    int w = tid >> 5, lane = tid & 31;
    {
        float m = -1e30f;
        for (int j = lane; j < HP2; j += 32) m = fmaxf(m, lg[w][j]);
        #pragma unroll
        for (int o = 16; o; o >>= 1) m = fmaxf(m, __shfl_xor_sync(~0u, m, o));
        float s = 0.f;
        for (int j = lane; j < HP2; j += 32) { float e = __expf(lg[w][j] - m); lg[w][j] = e; s += e; }
        #pragma unroll
        for (int o = 16; o; o >>= 1) s += __shfl_xor_sync(~0u, s, o);
        float inv = 1.f / s;
        for (int j = lane; j < HP2; j += 32) lg[w][j] *= inv;
    }
    __syncthreads();
    int q = tid >> 5, d = tid & 31;
    float acc = 0.f;
    const float* vb = vpool + (long)b*HP2*CH + h*HD + d;
    for (int kk = 0; kk < HP2; kk++) acc = fmaf(lg[q][kk], vb[(long)kk*CH], acc);
    qin[(b*NQ + q)*CH + h*HD + d] = acc + qtok[q*CH + h*HD + d];
}

// ---------------- window attention ------------------------------------
__global__ void window_attn_kernel(const float* __restrict__ qkv,
                                   const float* __restrict__ gk,
                                   const float* __restrict__ gv,
                                   const float* __restrict__ rpb,
                                   float* __restrict__ attn_out,
                                   float* __restrict__ attout) {
    int h   = blockIdx.x & 7;
    int win = blockIdx.x >> 3;
    int wx = win & 7, wy = (win >> 3) & 7, b = win >> 6;
    int n_base = (wy*WS)*GRIDW + wx*WS;

    __shared__ float qs[64][33];
    __shared__ float ks[KVLEN][33];
    __shared__ float vs[KVLEN][33];
    __shared__ float lg[64][KVLEN];
    int tid = threadIdx.x;

    for (int idx = tid; idx < 64*HD; idx += 256) {
        int i = idx >> 5, d = idx & 31;
        int n = n_base + (i >> 3)*GRIDW + (i & 7);
        qs[i][d] = qkv[((long)b*NTOK + n)*(3*CH) + h*HD + d] * SCALE;
    }
    for (int idx = tid; idx < KVLEN*HD; idx += 256) {
        int j = idx >> 5, d = idx & 31;
        if (j < 64) {
            int n = n_base + (j >> 3)*GRIDW + (j & 7);
            long base = ((long)b*NTOK + n)*(3*CH) + h*HD + d;
            ks[j][d] = qkv[base + CH];
            vs[j][d] = qkv[base + 2*CH];
        } else {
            int nq = j - 64;
            ks[j][d] = gk[(b*NQ + nq)*CH + h*HD + d];
            vs[j][d] = gv[(b*NQ + nq)*CH + h*HD + d];
        }
    }
    __syncthreads();

    for (int idx = tid; idx < 64*KVLEN; idx += 256) {
        int i = idx / KVLEN, j = idx - i*KVLEN;
        float s = 0.f;
        #pragma unroll
        for (int d = 0; d < HD; d++) s = fmaf(qs[i][d], ks[j][d], s);
        if (j < 64) {
            int diy = (i >> 3) - (j >> 3) + 7;
            int dix = (i & 7) - (j & 7) + 7;
            s += rpb[(diy*15 + dix)*HEADS + h];
        }
        lg[i][j] = s;
    }
    __syncthreads();

    int wp = tid >> 5, lane = tid & 31;
    for (int it = 0; it < 8; it++) {
        int i = it*8 + wp;
        float m = -1e30f;
        for (int j = lane; j < KVLEN; j += 32) m = fmaxf(m, lg[i][j]);
        #pragma unroll
        for (int o = 16; o; o >>= 1) m = fmaxf(m, __shfl_xor_sync(~0u, m, o));
        float s = 0.f;
        for (int j = lane; j < KVLEN; j += 32) { float e = __expf(lg[i][j] - m); lg[i][j] = e; s += e; }
        #pragma unroll
        for (int o = 16; o; o >>= 1) s += __shfl_xor_sync(~0u, s, o);
        float inv = 1.f / s;
        for (int j = lane; j < KVLEN; j += 32) lg[i][j] *= inv;
    }
    __syncthreads();

    long abase = ((long)(win*HEADS + h))*64*KVLEN;
    for (int idx = tid; idx < 64*KVLEN; idx += 256) {
        int i = idx / KVLEN, j = idx - i*KVLEN;
        attn_out[abase + idx] = lg[i][j];
    }

    for (int it = 0; it < 8; it++) {
        int i = it*8 + wp;
        int d = lane;
        float acc = 0.f;
        #pragma unroll
        for (int j = 0; j < KVLEN; j++) acc = fmaf(lg[i][j], vs[j][d], acc);
        int n = n_base + (i >> 3)*GRIDW + (i & 7);
        attout[((long)b*NTOK + n)*CH + h*HD + d] = acc;
    }
}

// ---------------- host launch ------------------------------------------
#define GEMM_SMEM (4*BUFSZ*4)   // bytes: 2 stages x (A+B) x 128 x PADK

extern "C" void kernel_launch(void* const* d_in, const int* in_sizes, int n_in,
                              void* d_out, int out_size) {
    const float* x       = (const float*)d_in[0];
    const float* qtok    = (const float*)d_in[1];
    const float* kproj_w = (const float*)d_in[2];
    const float* kproj_b = (const float*)d_in[3];
    const float* kbn_g   = (const float*)d_in[4];
    const float* kbn_b   = (const float*)d_in[5];
    const float* kbn_m   = (const float*)d_in[6];
    const float* kbn_v   = (const float*)d_in[7];
    const float* vproj_w = (const float*)d_in[8];
    const float* vproj_b = (const float*)d_in[9];
    const float* vbn_g   = (const float*)d_in[10];
    const float* vbn_b   = (const float*)d_in[11];
    const float* vbn_m   = (const float*)d_in[12];
    const float* vbn_v   = (const float*)d_in[13];
    const float* ck_w    = (const float*)d_in[14];
    const float* ck_b    = (const float*)d_in[15];
    const float* cv_w    = (const float*)d_in[16];
    const float* cv_b    = (const float*)d_in[17];
    const float* rpb     = (const float*)d_in[18];
    const float* qkv_w   = (const float*)d_in[19];
    const float* qkv_b   = (const float*)d_in[20];
    const float* proj_w  = (const float*)d_in[21];
    const float* proj_b  = (const float*)d_in[22];
    const float* n1_g    = (const float*)d_in[23];
    const float* n1_b    = (const float*)d_in[24];
    const float* n2_g    = (const float*)d_in[25];
    const float* n2_b    = (const float*)d_in[26];
    const float* fc1_w   = (const float*)d_in[27];
    const float* fc1_b   = (const float*)d_in[28];
    const float* fc2_w   = (const float*)d_in[29];
    const float* fc2_b   = (const float*)d_in[30];

    float* out_x    = (float*)d_out;
    float* out_attn = out_x + (long)BATCH*NTOK*CH;

    float *xn, *pooled, *kpool, *vpool, *qin, *gk, *gv, *qkv, *attout, *xnew, *xm, *hbuf;
    cudaGetSymbolAddress((void**)&xn,     g_xn);
    cudaGetSymbolAddress((void**)&pooled, g_pooled);
    cudaGetSymbolAddress((void**)&kpool,  g_kpool);
    cudaGetSymbolAddress((void**)&vpool,  g_vpool);
    cudaGetSymbolAddress((void**)&qin,    g_qin);
    cudaGetSymbolAddress((void**)&gk,     g_gk);
    cudaGetSymbolAddress((void**)&gv,     g_gv);
    cudaGetSymbolAddress((void**)&qkv,    g_qkv);
    cudaGetSymbolAddress((void**)&attout, g_attout);
    cudaGetSymbolAddress((void**)&xnew,   g_xnew);
    cudaGetSymbolAddress((void**)&xm,     g_xm);
    cudaGetSymbolAddress((void**)&hbuf,   g_h);

    static int smem_set = 0;
    if (!smem_set) {
        cudaFuncSetAttribute(mma_gemm<0>, cudaFuncAttributeMaxDynamicSharedMemorySize, GEMM_SMEM);
        cudaFuncSetAttribute(mma_gemm<1>, cudaFuncAttributeMaxDynamicSharedMemorySize, GEMM_SMEM);
        cudaFuncSetAttribute(mma_gemm<2>, cudaFuncAttributeMaxDynamicSharedMemorySize, GEMM_SMEM);
        cudaFuncSetAttribute(mma_gemm<3>, cudaFuncAttributeMaxDynamicSharedMemorySize, GEMM_SMEM);
        smem_set = 1;
    }

    const int M = BATCH*NTOK;   // 65536

    layernorm_kernel<<<M, 256>>>(x, n1_g, n1_b, xn);
    pool_kernel<<<BATCH*HP2, 256>>>(xn, pooled);
    mma_gemm<1><<<dim3(2, 32), 256, GEMM_SMEM>>>(pooled, kproj_w, kproj_b, kpool,
                                                 BATCH*HP2, CH, CH, kbn_m, kbn_v, kbn_g, kbn_b);
    mma_gemm<1><<<dim3(2, 32), 256, GEMM_SMEM>>>(pooled, vproj_w, vproj_b, vpool,
                                                 BATCH*HP2, CH, CH, vbn_m, vbn_v, vbn_g, vbn_b);
    global_attn_kernel<<<BATCH*HEADS, 256>>>(kpool, vpool, qtok, qin);
    mma_gemm<0><<<dim3(2, 1), 256, GEMM_SMEM>>>(qin, ck_w, ck_b, gk, BATCH*NQ, CH, CH, 0, 0, 0, 0);
    mma_gemm<0><<<dim3(2, 1), 256, GEMM_SMEM>>>(qin, cv_w, cv_b, gv, BATCH*NQ, CH, CH, 0, 0, 0, 0);
    mma_gemm<0><<<dim3(6, 512), 256, GEMM_SMEM>>>(xn, qkv_w, qkv_b, qkv, M, CH, 3*CH, 0, 0, 0, 0);
    window_attn_kernel<<<BATCH*NWIN*HEADS, 256>>>(qkv, gk, gv, rpb, out_attn, attout);
    mma_gemm<3><<<dim3(2, 512), 256, GEMM_SMEM>>>(attout, proj_w, proj_b, xnew, M, CH, CH, x, 0, 0, 0);
    layernorm_kernel<<<M, 256>>>(xnew, n2_g, n2_b, xm);
    mma_gemm<2><<<dim3(8, 512), 256, GEMM_SMEM>>>(xm, fc1_w, fc1_b, hbuf, M, CH, 4*CH, 0, 0, 0, 0);
    mma_gemm<3><<<dim3(2, 512), 256, GEMM_SMEM>>>(hbuf, fc2_w, fc2_b, out_x, M, 4*CH, CH, xnew, 0, 0, 0);
}

// round 4
// speedup vs baseline: 2.2694x; 1.0072x over previous
#include <cuda_runtime.h>
#include <math.h>

// ---------------- problem constants ----------------
#define BATCH   16
#define CH      256
#define NTOK    4096
#define GRIDW   64
#define HEADS   8
#define HD      32
#define NQ      8
#define WS      8
#define NWIN    64
#define KVLEN   72
#define HP2     256
#define SCALE   0.17677669529663687f

// ---------------- scratch ----------------
__device__ float g_xn   [(long)BATCH*NTOK*CH];
__device__ float g_pooled[(long)BATCH*HP2*CH];
__device__ float g_kpool [(long)BATCH*HP2*CH];
__device__ float g_vpool [(long)BATCH*HP2*CH];
__device__ float g_qin   [BATCH*NQ*CH];
__device__ float g_gk    [BATCH*NQ*CH];
__device__ float g_gv    [BATCH*NQ*CH];
__device__ float g_qkv  [(long)BATCH*NTOK*3*CH];
__device__ float g_attout[(long)BATCH*NTOK*CH];
__device__ float g_xnew [(long)BATCH*NTOK*CH];
__device__ float g_xm   [(long)BATCH*NTOK*CH];
__device__ float g_h    [(long)BATCH*NTOK*4*CH];

// ---------------- helpers ----------------
__device__ __forceinline__ void mma_tf32(float* c, const unsigned* a, const unsigned* b) {
    asm volatile(
        "mma.sync.aligned.m16n8k8.row.col.f32.tf32.tf32.f32 "
        "{%0,%1,%2,%3}, {%4,%5,%6,%7}, {%8,%9}, {%0,%1,%2,%3};"
        : "+f"(c[0]), "+f"(c[1]), "+f"(c[2]), "+f"(c[3])
        : "r"(a[0]), "r"(a[1]), "r"(a[2]), "r"(a[3]), "r"(b[0]), "r"(b[1]));
}

__device__ __forceinline__ void cp16(void* dst, const void* src) {
    unsigned d = (unsigned)__cvta_generic_to_shared(dst);
    asm volatile("cp.async.cg.shared.global [%0], [%1], 16;" :: "r"(d), "l"(src));
}
__device__ __forceinline__ void cp_commit() {
    asm volatile("cp.async.commit_group;");
}
__device__ __forceinline__ void cp_wait1() {
    asm volatile("cp.async.wait_group 1;");
}

// ---------------- layernorm ----------------
__global__ void layernorm_kernel(const float* __restrict__ x,
                                 const float* __restrict__ g,
                                 const float* __restrict__ b,
                                 float* __restrict__ out) {
    long row = blockIdx.x;
    int t = threadIdx.x;
    float v = x[row*CH + t];
    __shared__ float red[8];
    __shared__ float stat[2];
    int lane = t & 31, warp = t >> 5;
    float s = v;
    #pragma unroll
    for (int o = 16; o; o >>= 1) s += __shfl_xor_sync(~0u, s, o);
    if (lane == 0) red[warp] = s;
    __syncthreads();
    if (t == 0) {
        float z = 0.f;
        #pragma unroll
        for (int i = 0; i < 8; i++) z += red[i];
        stat[0] = z * (1.f/CH);
    }
    __syncthreads();
    float m = stat[0];
    float d = v - m;
    s = d*d;
    #pragma unroll
    for (int o = 16; o; o >>= 1) s += __shfl_xor_sync(~0u, s, o);
    if (lane == 0) red[warp] = s;
    __syncthreads();
    if (t == 0) {
        float z = 0.f;
        #pragma unroll
        for (int i = 0; i < 8; i++) z += red[i];
        stat[1] = rsqrtf(z * (1.f/CH) + 1e-5f);
    }
    __syncthreads();
    out[row*CH + t] = d * stat[1] * g[t] + b[t];
}

// ---------------- 4x4 avg pool ----------------
__global__ void pool_kernel(const float* __restrict__ xn, float* __restrict__ pooled) {
    int bidx = blockIdx.x;
    int b = bidx >> 8, hw = bidx & 255;
    int py = hw >> 4, px = hw & 15;
    int c = threadIdx.x;
    float s = 0.f;
    #pragma unroll
    for (int dy = 0; dy < 4; dy++)
        #pragma unroll
        for (int dx = 0; dx < 4; dx++) {
            int n = (py*4 + dy)*GRIDW + px*4 + dx;
            s += xn[((long)b*NTOK + n)*CH + c];
        }
    pooled[(long)bidx*CH + c] = s * (1.f/16.f);
}

// ---------------- tf32 double-buffered GEMM -----------------------------
// out[M,O] = A[M,K] @ W[O,K]^T + bias.  BM=BN=128, BK=32, 256 thr, 8 warps
// (2m x 4n), warp tile 64x32.  Raw fp32 bits fed to tf32 mma (truncation).
// gridDim.z selects parameter set (merged independent GEMMs sharing A).
// EPI: 0 bias; 1 BN(e0=m,e1=v,e2=g,e3=b); 2 GELU; 3 residual add (e0[M,O])
#define PADK 36
#define BUFSZ (128*PADK)

struct GP {
    const float* W; const float* bias; float* out;
    const float* e0; const float* e1; const float* e2; const float* e3;
};

template<int EPI>
__global__ void __launch_bounds__(256, 2)
mma_gemm(const float* __restrict__ A, int M, int K, int O, GP p0, GP p1) {
    extern __shared__ float smem[];
    float* As = smem;
    float* Bs = smem + 2*BUFSZ;

    const GP* P = blockIdx.z ? &p1 : &p0;
    const float* __restrict__ W = P->W;

    int tid  = threadIdx.x;
    int warp = tid >> 5, lane = tid & 31;
    int wm = warp >> 2, wn = warp & 3;
    int m_warp = wm * 64, n_warp = wn * 32;
    int g = lane >> 2, tg = lane & 3;

    int m0 = blockIdx.y * 128;
    int o0 = blockIdx.x * 128;

    int lr = tid >> 3;
    int lc = (tid & 7) * 4;

    float acc[4][4][4] = {};

    {
        const float* Ag = A + (long)(m0 + lr)*K + lc;
        const float* Wg = W + (long)(o0 + lr)*K + lc;
        float* Ad = As + lr*PADK + lc;
        float* Bd = Bs + lr*PADK + lc;
        #pragma unroll
        for (int i = 0; i < 4; i++) {
            cp16(Ad + i*32*PADK, Ag + (long)i*32*K);
            cp16(Bd + i*32*PADK, Wg + (long)i*32*K);
        }
        cp_commit();
    }

    int buf = 0;
    for (int kc = 0; kc < K; kc += 32) {
        if (kc + 32 < K) {
            int nb = buf ^ 1;
            const float* Ag = A + (long)(m0 + lr)*K + kc + 32 + lc;
            const float* Wg = W + (long)(o0 + lr)*K + kc + 32 + lc;
            float* Ad = As + nb*BUFSZ + lr*PADK + lc;
            float* Bd = Bs + nb*BUFSZ + lr*PADK + lc;
            #pragma unroll
            for (int i = 0; i < 4; i++) {
                cp16(Ad + i*32*PADK, Ag + (long)i*32*K);
                cp16(Bd + i*32*PADK, Wg + (long)i*32*K);
            }
        }
        cp_commit();
        cp_wait1();
        __syncthreads();

        const float* As_b = As + buf*BUFSZ;
        const float* Bs_b = Bs + buf*BUFSZ;
        #pragma unroll
        for (int kt = 0; kt < 4; kt++) {
            int k0 = kt*8;
            unsigned af[4][4], bf[4][2];
            #pragma unroll
            for (int mt = 0; mt < 4; mt++) {
                int mb = m_warp + mt*16 + g;
                af[mt][0] = __float_as_uint(As_b[mb*PADK + k0 + tg]);
                af[mt][1] = __float_as_uint(As_b[(mb+8)*PADK + k0 + tg]);
                af[mt][2] = __float_as_uint(As_b[mb*PADK + k0 + tg + 4]);
                af[mt][3] = __float_as_uint(As_b[(mb+8)*PADK + k0 + tg + 4]);
            }
            #pragma unroll
            for (int nt = 0; nt < 4; nt++) {
                int nb2 = n_warp + nt*8 + g;
                bf[nt][0] = __float_as_uint(Bs_b[nb2*PADK + k0 + tg]);
                bf[nt][1] = __float_as_uint(Bs_b[nb2*PADK + k0 + tg + 4]);
            }
            #pragma unroll
            for (int mt = 0; mt < 4; mt++)
                #pragma unroll
                for (int nt = 0; nt < 4; nt++)
                    mma_tf32(acc[mt][nt], af[mt], bf[nt]);
        }
        __syncthreads();
        buf ^= 1;
    }

    const float* __restrict__ bias = P->bias;
    float* __restrict__ out = P->out;
    const float* e0 = P->e0;
    const float* e1 = P->e1;
    const float* e2 = P->e2;
    const float* e3 = P->e3;

    #pragma unroll
    for (int mt = 0; mt < 4; mt++) {
        #pragma unroll
        for (int nt = 0; nt < 4; nt++) {
            #pragma unroll
            for (int c = 0; c < 4; c++) {
                int m = m0 + m_warp + mt*16 + g + (c >> 1)*8;
                int o = o0 + n_warp + nt*8 + tg*2 + (c & 1);
                float y = acc[mt][nt][c] + bias[o];
                if (EPI == 1) {
                    y = (y - e0[o]) * rsqrtf(e1[o] + 1e-5f) * e2[o] + e3[o];
                } else if (EPI == 2) {
                    y = 0.5f * y * (1.0f + erff(y * 0.70710678118654752f));
                } else if (EPI == 3) {
                    y += e0[(long)m*O + o];
                }
                out[(long)m*O + o] = y;
            }
        }
    }
}

// ---------------- global cross-attention pooling path -----------------
__global__ void global_attn_kernel(const float* __restrict__ kpool,
                                   const float* __restrict__ vpool,
                                   const float* __restrict__ qtok,
                                   float* __restrict__ qin) {
    int b = blockIdx.x >> 3, h = blockIdx.x & 7;
    __shared__ float qs[NQ][HD];
    __shared__ float lg[NQ][HP2];
    int tid = threadIdx.x;
    { int q = tid >> 5, d = tid & 31; qs[q][d] = qtok[q*CH + h*HD + d]; }
    __syncthreads();
    float kreg[HD];
    const float* kr = kpool + ((long)b*HP2 + tid)*CH + h*HD;
    #pragma unroll
    for (int d = 0; d < HD; d++) kreg[d] = kr[d];
    #pragma unroll
    for (int q = 0; q < NQ; q++) {
        float s = 0.f;
        #pragma unroll
        for (int d = 0; d < HD; d++) s = fmaf(qs[q][d], kreg[d], s);
        lg[q][tid] = s * SCALE;
    }
    __syncthreads();
    int w = tid >> 5, lane = tid & 31;
    {
        float m = -1e30f;
        for (int j = lane; j < HP2; j += 32) m = fmaxf(m, lg[w][j]);
        #pragma unroll
        for (int o = 16; o; o >>= 1) m = fmaxf(m, __shfl_xor_sync(~0u, m, o));
        float s = 0.f;
        for (int j = lane; j < HP2; j += 32) { float e = __expf(lg[w][j] - m); lg[w][j] = e; s += e; }
        #pragma unroll
        for (int o = 16; o; o >>= 1) s += __shfl_xor_sync(~0u, s, o);
        float inv = 1.f / s;
        for (int j = lane; j < HP2; j += 32) lg[w][j] *= inv;
    }
    __syncthreads();
    int q = tid >> 5, d = tid & 31;
    float acc = 0.f;
    const float* vb = vpool + (long)b*HP2*CH + h*HD + d;
    for (int kk = 0; kk < HP2; kk++) acc = fmaf(lg[q][kk], vb[(long)kk*CH], acc);
    qin[(b*NQ + q)*CH + h*HD + d] = acc + qtok[q*CH + h*HD + d];
}

// ---------------- window attention ------------------------------------
__global__ void window_attn_kernel(const float* __restrict__ qkv,
                                   const float* __restrict__ gk,
                                   const float* __restrict__ gv,
                                   const float* __restrict__ rpb,
                                   float* __restrict__ attn_out,
                                   float* __restrict__ attout) {
    int h   = blockIdx.x & 7;
    int win = blockIdx.x >> 3;
    int wx = win & 7, wy = (win >> 3) & 7, b = win >> 6;
    int n_base = (wy*WS)*GRIDW + wx*WS;

    __shared__ float qs[64][33];
    __shared__ float ks[KVLEN][33];
    __shared__ float vs[KVLEN][33];
    __shared__ float lg[64][KVLEN];
    int tid = threadIdx.x;

    for (int idx = tid; idx < 64*HD; idx += 256) {
        int i = idx >> 5, d = idx & 31;
        int n = n_base + (i >> 3)*GRIDW + (i & 7);
        qs[i][d] = qkv[((long)b*NTOK + n)*(3*CH) + h*HD + d] * SCALE;
    }
    for (int idx = tid; idx < KVLEN*HD; idx += 256) {
        int j = idx >> 5, d = idx & 31;
        if (j < 64) {
            int n = n_base + (j >> 3)*GRIDW + (j & 7);
            long base = ((long)b*NTOK + n)*(3*CH) + h*HD + d;
            ks[j][d] = qkv[base + CH];
            vs[j][d] = qkv[base + 2*CH];
        } else {
            int nq = j - 64;
            ks[j][d] = gk[(b*NQ + nq)*CH + h*HD + d];
            vs[j][d] = gv[(b*NQ + nq)*CH + h*HD + d];
        }
    }
    __syncthreads();

    for (int idx = tid; idx < 64*KVLEN; idx += 256) {
        int i = idx / KVLEN, j = idx - i*KVLEN;
        float s = 0.f;
        #pragma unroll
        for (int d = 0; d < HD; d++) s = fmaf(qs[i][d], ks[j][d], s);
        if (j < 64) {
            int diy = (i >> 3) - (j >> 3) + 7;
            int dix = (i & 7) - (j & 7) + 7;
            s += rpb[(diy*15 + dix)*HEADS + h];
        }
        lg[i][j] = s;
    }
    __syncthreads();

    int wp = tid >> 5, lane = tid & 31;
    for (int it = 0; it < 8; it++) {
        int i = it*8 + wp;
        float m = -1e30f;
        for (int j = lane; j < KVLEN; j += 32) m = fmaxf(m, lg[i][j]);
        #pragma unroll
        for (int o = 16; o; o >>= 1) m = fmaxf(m, __shfl_xor_sync(~0u, m, o));
        float s = 0.f;
        for (int j = lane; j < KVLEN; j += 32) { float e = __expf(lg[i][j] - m); lg[i][j] = e; s += e; }
        #pragma unroll
        for (int o = 16; o; o >>= 1) s += __shfl_xor_sync(~0u, s, o);
        float inv = 1.f / s;
        for (int j = lane; j < KVLEN; j += 32) lg[i][j] *= inv;
    }
    __syncthreads();

    long abase = ((long)(win*HEADS + h))*64*KVLEN;
    for (int idx = tid; idx < 64*KVLEN; idx += 256) {
        int i = idx / KVLEN, j = idx - i*KVLEN;
        attn_out[abase + idx] = lg[i][j];
    }

    for (int it = 0; it < 8; it++) {
        int i = it*8 + wp;
        int d = lane;
        float acc = 0.f;
        #pragma unroll
        for (int j = 0; j < KVLEN; j++) acc = fmaf(lg[i][j], vs[j][d], acc);
        int n = n_base + (i >> 3)*GRIDW + (i & 7);
        attout[((long)b*NTOK + n)*CH + h*HD + d] = acc;
    }
}

// ---------------- host launch ------------------------------------------
#define GEMM_SMEM (4*BUFSZ*4)

extern "C" void kernel_launch(void* const* d_in, const int* in_sizes, int n_in,
                              void* d_out, int out_size) {
    const float* x       = (const float*)d_in[0];
    const float* qtok    = (const float*)d_in[1];
    const float* kproj_w = (const float*)d_in[2];
    const float* kproj_b = (const float*)d_in[3];
    const float* kbn_g   = (const float*)d_in[4];
    const float* kbn_b   = (const float*)d_in[5];
    const float* kbn_m   = (const float*)d_in[6];
    const float* kbn_v   = (const float*)d_in[7];
    const float* vproj_w = (const float*)d_in[8];
    const float* vproj_b = (const float*)d_in[9];
    const float* vbn_g   = (const float*)d_in[10];
    const float* vbn_b   = (const float*)d_in[11];
    const float* vbn_m   = (const float*)d_in[12];
    const float* vbn_v   = (const float*)d_in[13];
    const float* ck_w    = (const float*)d_in[14];
    const float* ck_b    = (const float*)d_in[15];
    const float* cv_w    = (const float*)d_in[16];
    const float* cv_b    = (const float*)d_in[17];
    const float* rpb     = (const float*)d_in[18];
    const float* qkv_w   = (const float*)d_in[19];
    const float* qkv_b   = (const float*)d_in[20];
    const float* proj_w  = (const float*)d_in[21];
    const float* proj_b  = (const float*)d_in[22];
    const float* n1_g    = (const float*)d_in[23];
    const float* n1_b    = (const float*)d_in[24];
    const float* n2_g    = (const float*)d_in[25];
    const float* n2_b    = (const float*)d_in[26];
    const float* fc1_w   = (const float*)d_in[27];
    const float* fc1_b   = (const float*)d_in[28];
    const float* fc2_w   = (const float*)d_in[29];
    const float* fc2_b   = (const float*)d_in[30];

    float* out_x    = (float*)d_out;
    float* out_attn = out_x + (long)BATCH*NTOK*CH;

    float *xn, *pooled, *kpool, *vpool, *qin, *gk, *gv, *qkv, *attout, *xnew, *xm, *hbuf;
    cudaGetSymbolAddress((void**)&xn,     g_xn);
    cudaGetSymbolAddress((void**)&pooled, g_pooled);
    cudaGetSymbolAddress((void**)&kpool,  g_kpool);
    cudaGetSymbolAddress((void**)&vpool,  g_vpool);
    cudaGetSymbolAddress((void**)&qin,    g_qin);
    cudaGetSymbolAddress((void**)&gk,     g_gk);
    cudaGetSymbolAddress((void**)&gv,     g_gv);
    cudaGetSymbolAddress((void**)&qkv,    g_qkv);
    cudaGetSymbolAddress((void**)&attout, g_attout);
    cudaGetSymbolAddress((void**)&xnew,   g_xnew);
    cudaGetSymbolAddress((void**)&xm,     g_xm);
    cudaGetSymbolAddress((void**)&hbuf,   g_h);

    static int smem_set = 0;
    if (!smem_set) {
        cudaFuncSetAttribute(mma_gemm<0>, cudaFuncAttributeMaxDynamicSharedMemorySize, GEMM_SMEM);
        cudaFuncSetAttribute(mma_gemm<1>, cudaFuncAttributeMaxDynamicSharedMemorySize, GEMM_SMEM);
        cudaFuncSetAttribute(mma_gemm<2>, cudaFuncAttributeMaxDynamicSharedMemorySize, GEMM_SMEM);
        cudaFuncSetAttribute(mma_gemm<3>, cudaFuncAttributeMaxDynamicSharedMemorySize, GEMM_SMEM);
        smem_set = 1;
    }

    const int M = BATCH*NTOK;   // 65536

    layernorm_kernel<<<M, 256>>>(x, n1_g, n1_b, xn);
    pool_kernel<<<BATCH*HP2, 256>>>(xn, pooled);

    GP kp = {kproj_w, kproj_b, kpool, kbn_m, kbn_v, kbn_g, kbn_b};
    GP vp = {vproj_w, vproj_b, vpool, vbn_m, vbn_v, vbn_g, vbn_b};
    mma_gemm<1><<<dim3(2, 32, 2), 256, GEMM_SMEM>>>(pooled, BATCH*HP2, CH, CH, kp, vp);

    global_attn_kernel<<<BATCH*HEADS, 256>>>(kpool, vpool, qtok, qin);

    GP ckp = {ck_w, ck_b, gk, 0, 0, 0, 0};
    GP cvp = {cv_w, cv_b, gv, 0, 0, 0, 0};
    mma_gemm<0><<<dim3(2, 1, 2), 256, GEMM_SMEM>>>(qin, BATCH*NQ, CH, CH, ckp, cvp);

    GP qkvp = {qkv_w, qkv_b, qkv, 0, 0, 0, 0};
    mma_gemm<0><<<dim3(6, 512, 1), 256, GEMM_SMEM>>>(xn, M, CH, 3*CH, qkvp, qkvp);

    window_attn_kernel<<<BATCH*NWIN*HEADS, 256>>>(qkv, gk, gv, rpb, out_attn, attout);

    GP projp = {proj_w, proj_b, xnew, x, 0, 0, 0};
    mma_gemm<3><<<dim3(2, 512, 1), 256, GEMM_SMEM>>>(attout, M, CH, CH, projp, projp);

    layernorm_kernel<<<M, 256>>>(xnew, n2_g, n2_b, xm);

    GP fc1p = {fc1_w, fc1_b, hbuf, 0, 0, 0, 0};
    mma_gemm<2><<<dim3(8, 512, 1), 256, GEMM_SMEM>>>(xm, M, CH, 4*CH, fc1p, fc1p);

    GP fc2p = {fc2_w, fc2_b, out_x, xnew, 0, 0, 0};
    mma_gemm<3><<<dim3(2, 512, 1), 256, GEMM_SMEM>>>(hbuf, M, 4*CH, CH, fc2p, fc2p);
}

// round 8
// speedup vs baseline: 2.9818x; 1.3139x over previous
#include <cuda_runtime.h>
#include <math.h>

// ---------------- problem constants ----------------
#define BATCH   16
#define CH      256
#define NTOK    4096
#define GRIDW   64
#define HEADS   8
#define HD      32
#define NQ      8
#define WS      8
#define NWIN    64
#define KVLEN   72
#define HP2     256
#define SCALE   0.17677669529663687f

// ---------------- scratch ----------------
__device__ float g_xn   [(long)BATCH*NTOK*CH];
__device__ float g_pooled[(long)BATCH*HP2*CH];
__device__ float g_kpool [(long)BATCH*HP2*CH];
__device__ float g_vpool [(long)BATCH*HP2*CH];
__device__ float g_qin   [BATCH*NQ*CH];
__device__ float g_gk    [BATCH*NQ*CH];
__device__ float g_gv    [BATCH*NQ*CH];
__device__ float g_qkv  [(long)BATCH*NTOK*3*CH];
__device__ float g_attout[(long)BATCH*NTOK*CH];
__device__ float g_xnew [(long)BATCH*NTOK*CH];
__device__ float g_xm   [(long)BATCH*NTOK*CH];
__device__ float g_h    [(long)BATCH*NTOK*4*CH];

// ---------------- helpers ----------------
__device__ __forceinline__ void mma_tf32(float* c, const unsigned* a, const unsigned* b) {
    asm volatile(
        "mma.sync.aligned.m16n8k8.row.col.f32.tf32.tf32.f32 "
        "{%0,%1,%2,%3}, {%4,%5,%6,%7}, {%8,%9}, {%0,%1,%2,%3};"
        : "+f"(c[0]), "+f"(c[1]), "+f"(c[2]), "+f"(c[3])
        : "r"(a[0]), "r"(a[1]), "r"(a[2]), "r"(a[3]), "r"(b[0]), "r"(b[1]));
}

__device__ __forceinline__ void cp16(void* dst, const void* src) {
    unsigned d = (unsigned)__cvta_generic_to_shared(dst);
    asm volatile("cp.async.cg.shared.global [%0], [%1], 16;" :: "r"(d), "l"(src));
}
__device__ __forceinline__ void cp_commit() {
    asm volatile("cp.async.commit_group;");
}
__device__ __forceinline__ void cp_wait1() {
    asm volatile("cp.async.wait_group 1;");
}

// ---------------- layernorm ----------------
__global__ void layernorm_kernel(const float* __restrict__ x,
                                 const float* __restrict__ g,
                                 const float* __restrict__ b,
                                 float* __restrict__ out) {
    long row = blockIdx.x;
    int t = threadIdx.x;
    float v = x[row*CH + t];
    __shared__ float red[8];
    __shared__ float stat[2];
    int lane = t & 31, warp = t >> 5;
    float s = v;
    #pragma unroll
    for (int o = 16; o; o >>= 1) s += __shfl_xor_sync(~0u, s, o);
    if (lane == 0) red[warp] = s;
    __syncthreads();
    if (t == 0) {
        float z = 0.f;
        #pragma unroll
        for (int i = 0; i < 8; i++) z += red[i];
        stat[0] = z * (1.f/CH);
    }
    __syncthreads();
    float m = stat[0];
    float d = v - m;
    s = d*d;
    #pragma unroll
    for (int o = 16; o; o >>= 1) s += __shfl_xor_sync(~0u, s, o);
    if (lane == 0) red[warp] = s;
    __syncthreads();
    if (t == 0) {
        float z = 0.f;
        #pragma unroll
        for (int i = 0; i < 8; i++) z += red[i];
        stat[1] = rsqrtf(z * (1.f/CH) + 1e-5f);
    }
    __syncthreads();
    out[row*CH + t] = d * stat[1] * g[t] + b[t];
}

// ---------------- 4x4 avg pool ----------------
__global__ void pool_kernel(const float* __restrict__ xn, float* __restrict__ pooled) {
    int bidx = blockIdx.x;
    int b = bidx >> 8, hw = bidx & 255;
    int py = hw >> 4, px = hw & 15;
    int c = threadIdx.x;
    float s = 0.f;
    #pragma unroll
    for (int dy = 0; dy < 4; dy++)
        #pragma unroll
        for (int dx = 0; dx < 4; dx++) {
            int n = (py*4 + dy)*GRIDW + px*4 + dx;
            s += xn[((long)b*NTOK + n)*CH + c];
        }
    pooled[(long)bidx*CH + c] = s * (1.f/16.f);
}

// ---------------- tf32 double-buffered GEMM (mma.sync) ------------------
#define PADK 36
#define BUFSZ (128*PADK)

struct GP {
    const float* W; const float* bias; float* out;
    const float* e0; const float* e1; const float* e2; const float* e3;
};

template<int EPI>
__global__ void __launch_bounds__(256, 2)
mma_gemm(const float* __restrict__ A, int M, int K, int O, GP p0, GP p1) {
    extern __shared__ float smem[];
    float* As = smem;
    float* Bs = smem + 2*BUFSZ;

    const GP* P = blockIdx.z ? &p1 : &p0;
    const float* __restrict__ W = P->W;

    int tid  = threadIdx.x;
    int warp = tid >> 5, lane = tid & 31;
    int wm = warp >> 2, wn = warp & 3;
    int m_warp = wm * 64, n_warp = wn * 32;
    int g = lane >> 2, tg = lane & 3;

    int m0 = blockIdx.y * 128;
    int o0 = blockIdx.x * 128;

    int lr = tid >> 3;
    int lc = (tid & 7) * 4;

    float acc[4][4][4] = {};

    {
        const float* Ag = A + (long)(m0 + lr)*K + lc;
        const float* Wg = W + (long)(o0 + lr)*K + lc;
        float* Ad = As + lr*PADK + lc;
        float* Bd = Bs + lr*PADK + lc;
        #pragma unroll
        for (int i = 0; i < 4; i++) {
            cp16(Ad + i*32*PADK, Ag + (long)i*32*K);
            cp16(Bd + i*32*PADK, Wg + (long)i*32*K);
        }
        cp_commit();
    }

    int buf = 0;
    for (int kc = 0; kc < K; kc += 32) {
        if (kc + 32 < K) {
            int nb = buf ^ 1;
            const float* Ag = A + (long)(m0 + lr)*K + kc + 32 + lc;
            const float* Wg = W + (long)(o0 + lr)*K + kc + 32 + lc;
            float* Ad = As + nb*BUFSZ + lr*PADK + lc;
            float* Bd = Bs + nb*BUFSZ + lr*PADK + lc;
            #pragma unroll
            for (int i = 0; i < 4; i++) {
                cp16(Ad + i*32*PADK, Ag + (long)i*32*K);
                cp16(Bd + i*32*PADK, Wg + (long)i*32*K);
            }
        }
        cp_commit();
        cp_wait1();
        __syncthreads();

        const float* As_b = As + buf*BUFSZ;
        const float* Bs_b = Bs + buf*BUFSZ;
        #pragma unroll
        for (int kt = 0; kt < 4; kt++) {
            int k0 = kt*8;
            unsigned af[4][4], bf[4][2];
            #pragma unroll
            for (int mt = 0; mt < 4; mt++) {
                int mb = m_warp + mt*16 + g;
                af[mt][0] = __float_as_uint(As_b[mb*PADK + k0 + tg]);
                af[mt][1] = __float_as_uint(As_b[(mb+8)*PADK + k0 + tg]);
                af[mt][2] = __float_as_uint(As_b[mb*PADK + k0 + tg + 4]);
                af[mt][3] = __float_as_uint(As_b[(mb+8)*PADK + k0 + tg + 4]);
            }
            #pragma unroll
            for (int nt = 0; nt < 4; nt++) {
                int nb2 = n_warp + nt*8 + g;
                bf[nt][0] = __float_as_uint(Bs_b[nb2*PADK + k0 + tg]);
                bf[nt][1] = __float_as_uint(Bs_b[nb2*PADK + k0 + tg + 4]);
            }
            #pragma unroll
            for (int mt = 0; mt < 4; mt++)
                #pragma unroll
                for (int nt = 0; nt < 4; nt++)
                    mma_tf32(acc[mt][nt], af[mt], bf[nt]);
        }
        __syncthreads();
        buf ^= 1;
    }

    const float* __restrict__ bias = P->bias;
    float* __restrict__ out = P->out;
    const float* e0 = P->e0;
    const float* e1 = P->e1;
    const float* e2 = P->e2;
    const float* e3 = P->e3;

    #pragma unroll
    for (int mt = 0; mt < 4; mt++) {
        #pragma unroll
        for (int nt = 0; nt < 4; nt++) {
            #pragma unroll
            for (int c = 0; c < 4; c++) {
                int m = m0 + m_warp + mt*16 + g + (c >> 1)*8;
                int o = o0 + n_warp + nt*8 + tg*2 + (c & 1);
                float y = acc[mt][nt][c] + bias[o];
                if (EPI == 1) {
                    y = (y - e0[o]) * rsqrtf(e1[o] + 1e-5f) * e2[o] + e3[o];
                } else if (EPI == 2) {
                    y = 0.5f * y * (1.0f + erff(y * 0.70710678118654752f));
                } else if (EPI == 3) {
                    y += e0[(long)m*O + o];
                }
                out[(long)m*O + o] = y;
            }
        }
    }
}

// ---------------- global cross-attention pooling path -----------------
__global__ void global_attn_kernel(const float* __restrict__ kpool,
                                   const float* __restrict__ vpool,
                                   const float* __restrict__ qtok,
                                   float* __restrict__ qin) {
    int b = blockIdx.x >> 3, h = blockIdx.x & 7;
    __shared__ float qs[NQ][HD];
    __shared__ float lg[NQ][HP2];
    __shared__ float vsm[HP2][HD];
    int tid = threadIdx.x;
    { int q = tid >> 5, d = tid & 31; qs[q][d] = qtok[q*CH + h*HD + d]; }
    // stage V tile (coalesced)
    for (int idx = tid; idx < HP2*HD; idx += 256) {
        int r = idx >> 5, d = idx & 31;
        vsm[r][d] = vpool[((long)b*HP2 + r)*CH + h*HD + d];
    }
    __syncthreads();
    float kreg[HD];
    const float* kr = kpool + ((long)b*HP2 + tid)*CH + h*HD;
    #pragma unroll
    for (int d = 0; d < HD; d++) kreg[d] = kr[d];
    #pragma unroll
    for (int q = 0; q < NQ; q++) {
        float s = 0.f;
        #pragma unroll
        for (int d = 0; d < HD; d++) s = fmaf(qs[q][d], kreg[d], s);
        lg[q][tid] = s * SCALE;
    }
    __syncthreads();
    int w = tid >> 5, lane = tid & 31;
    {
        float m = -1e30f;
        for (int j = lane; j < HP2; j += 32) m = fmaxf(m, lg[w][j]);
        #pragma unroll
        for (int o = 16; o; o >>= 1) m = fmaxf(m, __shfl_xor_sync(~0u, m, o));
        float s = 0.f;
        for (int j = lane; j < HP2; j += 32) { float e = __expf(lg[w][j] - m); lg[w][j] = e; s += e; }
        #pragma unroll
        for (int o = 16; o; o >>= 1) s += __shfl_xor_sync(~0u, s, o);
        float inv = 1.f / s;
        for (int j = lane; j < HP2; j += 32) lg[w][j] *= inv;
    }
    __syncthreads();
    int q = tid >> 5, d = tid & 31;
    float acc = 0.f;
    for (int kk = 0; kk < HP2; kk++) acc = fmaf(lg[q][kk], vsm[kk][d], acc);
    qin[(b*NQ + q)*CH + h*HD + d] = acc + qtok[q*CH + h*HD + d];
}

// ---------------- window attention (tensor-core) -----------------------
// per (win, head): S = Q K^T via tf32 mma (K padded 72->80 with zeros),
// fp32 softmax, AV via tf32 mma. Fragment mapping identical to mma_gemm.
__global__ void __launch_bounds__(256)
window_attn_kernel(const float* __restrict__ qkv,
                   const float* __restrict__ gk,
                   const float* __restrict__ gv,
                   const float* __restrict__ rpb,
                   float* __restrict__ attn_out,
                   float* __restrict__ attout) {
    int h   = blockIdx.x & 7;
    int win = blockIdx.x >> 3;
    int wx = win & 7, wy = (win >> 3) & 7, b = win >> 6;
    int n_base = (wy*WS)*GRIDW + wx*WS;

    __shared__ float qs[64][36];
    __shared__ float ks[80][36];
    __shared__ float vt[32][84];
    __shared__ float lg[64][84];

    int tid = threadIdx.x;
    int warp = tid >> 5, lane = tid & 31;
    int g = lane >> 2, tg = lane & 3;

    // ---- load Q (scaled), K (72 + 8 zero pad), V transposed ----
    for (int idx = tid; idx < 64*32; idx += 256) {
        int i = idx >> 5, d = idx & 31;
        int n = n_base + (i >> 3)*GRIDW + (i & 7);
        qs[i][d] = qkv[((long)b*NTOK + n)*(3*CH) + h*HD + d] * SCALE;
    }
    for (int idx = tid; idx < 80*32; idx += 256) {
        int j = idx >> 5, d = idx & 31;
        float kv = 0.f, vv = 0.f;
        if (j < 64) {
            int n = n_base + (j >> 3)*GRIDW + (j & 7);
            long base = ((long)b*NTOK + n)*(3*CH) + h*HD + d;
            kv = qkv[base + CH];
            vv = qkv[base + 2*CH];
        } else if (j < 72) {
            int nq = j - 64;
            kv = gk[(b*NQ + nq)*CH + h*HD + d];
            vv = gv[(b*NQ + nq)*CH + h*HD + d];
        }
        ks[j][d] = kv;
        vt[d][j] = vv;
    }
    __syncthreads();

    // ---- S = Q K^T : warp = (m-tile 16) x (n-half 40) ----
    {
        int mw = (warp >> 1)*16, np = (warp & 1)*40;
        float acc[5][4] = {};
        #pragma unroll
        for (int kt = 0; kt < 4; kt++) {
            int k0 = kt*8;
            unsigned a[4];
            a[0] = __float_as_uint(qs[mw+g][k0+tg]);
            a[1] = __float_as_uint(qs[mw+g+8][k0+tg]);
            a[2] = __float_as_uint(qs[mw+g][k0+tg+4]);
            a[3] = __float_as_uint(qs[mw+g+8][k0+tg+4]);
            #pragma unroll
            for (int nt = 0; nt < 5; nt++) {
                int nb = np + nt*8 + g;
                unsigned bb[2];
                bb[0] = __float_as_uint(ks[nb][k0+tg]);
                bb[1] = __float_as_uint(ks[nb][k0+tg+4]);
                mma_tf32(acc[nt], a, bb);
            }
        }
        #pragma unroll
        for (int nt = 0; nt < 5; nt++) {
            #pragma unroll
            for (int c = 0; c < 4; c++) {
                int i = mw + g + (c >> 1)*8;
                int j = np + nt*8 + tg*2 + (c & 1);
                float s = acc[nt][c];
                if (j < 64) {
                    int diy = (i >> 3) - (j >> 3) + 7;
                    int dix = (i & 7) - (j & 7) + 7;
                    s += rpb[(diy*15 + dix)*HEADS + h];
                }
                lg[i][j] = s;
            }
        }
    }
    __syncthreads();

    // ---- softmax over j<72 (cols 72..79 remain 0) ----
    for (int it = 0; it < 8; it++) {
        int i = it*8 + warp;
        float m = -1e30f;
        for (int j = lane; j < KVLEN; j += 32) m = fmaxf(m, lg[i][j]);
        #pragma unroll
        for (int o = 16; o; o >>= 1) m = fmaxf(m, __shfl_xor_sync(~0u, m, o));
        float s = 0.f;
        for (int j = lane; j < KVLEN; j += 32) { float e = __expf(lg[i][j] - m); lg[i][j] = e; s += e; }
        #pragma unroll
        for (int o = 16; o; o >>= 1) s += __shfl_xor_sync(~0u, s, o);
        float inv = 1.f / s;
        for (int j = lane; j < KVLEN; j += 32) lg[i][j] *= inv;
    }
    __syncthreads();

    // ---- emit attention probabilities ----
    long abase = ((long)(win*HEADS + h))*64*KVLEN;
    for (int idx = tid; idx < 64*KVLEN; idx += 256) {
        int i = idx / KVLEN, j = idx - i*KVLEN;
        attn_out[abase + idx] = lg[i][j];
    }

    // ---- AV : warp = (m-tile 16) x (d-half 16) ----
    {
        int mw = (warp >> 1)*16, nv = (warp & 1)*16;
        float acc[2][4] = {};
        #pragma unroll
        for (int kt = 0; kt < 10; kt++) {
            int k0 = kt*8;
            unsigned a[4];
            a[0] = __float_as_uint(lg[mw+g][k0+tg]);
            a[1] = __float_as_uint(lg[mw+g+8][k0+tg]);
            a[2] = __float_as_uint(lg[mw+g][k0+tg+4]);
            a[3] = __float_as_uint(lg[mw+g+8][k0+tg+4]);
            #pragma unroll
            for (int nt = 0; nt < 2; nt++) {
                int nb = nv + nt*8 + g;
                unsigned bb[2];
                bb[0] = __float_as_uint(vt[nb][k0+tg]);
                bb[1] = __float_as_uint(vt[nb][k0+tg+4]);
                mma_tf32(acc[nt], a, bb);
            }
        }
        #pragma unroll
        for (int nt = 0; nt < 2; nt++) {
            #pragma unroll
            for (int c = 0; c < 4; c++) {
                int i = mw + g + (c >> 1)*8;
                int d = nv + nt*8 + tg*2 + (c & 1);
                int n = n_base + (i >> 3)*GRIDW + (i & 7);
                attout[((long)b*NTOK + n)*CH + h*HD + d] = acc[nt][c];
            }
        }
    }
}

// ---------------- host launch ------------------------------------------
#define GEMM_SMEM (4*BUFSZ*4)

extern "C" void kernel_launch(void* const* d_in, const int* in_sizes, int n_in,
                              void* d_out, int out_size) {
    const float* x       = (const float*)d_in[0];
    const float* qtok    = (const float*)d_in[1];
    const float* kproj_w = (const float*)d_in[2];
    const float* kproj_b = (const float*)d_in[3];
    const float* kbn_g   = (const float*)d_in[4];
    const float* kbn_b   = (const float*)d_in[5];
    const float* kbn_m   = (const float*)d_in[6];
    const float* kbn_v   = (const float*)d_in[7];
    const float* vproj_w = (const float*)d_in[8];
    const float* vproj_b = (const float*)d_in[9];
    const float* vbn_g   = (const float*)d_in[10];
    const float* vbn_b   = (const float*)d_in[11];
    const float* vbn_m   = (const float*)d_in[12];
    const float* vbn_v   = (const float*)d_in[13];
    const float* ck_w    = (const float*)d_in[14];
    const float* ck_b    = (const float*)d_in[15];
    const float* cv_w    = (const float*)d_in[16];
    const float* cv_b    = (const float*)d_in[17];
    const float* rpb     = (const float*)d_in[18];
    const float* qkv_w   = (const float*)d_in[19];
    const float* qkv_b   = (const float*)d_in[20];
    const float* proj_w  = (const float*)d_in[21];
    const float* proj_b  = (const float*)d_in[22];
    const float* n1_g    = (const float*)d_in[23];
    const float* n1_b    = (const float*)d_in[24];
    const float* n2_g    = (const float*)d_in[25];
    const float* n2_b    = (const float*)d_in[26];
    const float* fc1_w   = (const float*)d_in[27];
    const float* fc1_b   = (const float*)d_in[28];
    const float* fc2_w   = (const float*)d_in[29];
    const float* fc2_b   = (const float*)d_in[30];

    float* out_x    = (float*)d_out;
    float* out_attn = out_x + (long)BATCH*NTOK*CH;

    float *xn, *pooled, *kpool, *vpool, *qin, *gk, *gv, *qkv, *attout, *xnew, *xm, *hbuf;
    cudaGetSymbolAddress((void**)&xn,     g_xn);
    cudaGetSymbolAddress((void**)&pooled, g_pooled);
    cudaGetSymbolAddress((void**)&kpool,  g_kpool);
    cudaGetSymbolAddress((void**)&vpool,  g_vpool);
    cudaGetSymbolAddress((void**)&qin,    g_qin);
    cudaGetSymbolAddress((void**)&gk,     g_gk);
    cudaGetSymbolAddress((void**)&gv,     g_gv);
    cudaGetSymbolAddress((void**)&qkv,    g_qkv);
    cudaGetSymbolAddress((void**)&attout, g_attout);
    cudaGetSymbolAddress((void**)&xnew,   g_xnew);
    cudaGetSymbolAddress((void**)&xm,     g_xm);
    cudaGetSymbolAddress((void**)&hbuf,   g_h);

    static int smem_set = 0;
    if (!smem_set) {
        cudaFuncSetAttribute(mma_gemm<0>, cudaFuncAttributeMaxDynamicSharedMemorySize, GEMM_SMEM);
        cudaFuncSetAttribute(mma_gemm<1>, cudaFuncAttributeMaxDynamicSharedMemorySize, GEMM_SMEM);
        cudaFuncSetAttribute(mma_gemm<2>, cudaFuncAttributeMaxDynamicSharedMemorySize, GEMM_SMEM);
        cudaFuncSetAttribute(mma_gemm<3>, cudaFuncAttributeMaxDynamicSharedMemorySize, GEMM_SMEM);
        smem_set = 1;
    }

    const int M = BATCH*NTOK;   // 65536

    layernorm_kernel<<<M, 256>>>(x, n1_g, n1_b, xn);
    pool_kernel<<<BATCH*HP2, 256>>>(xn, pooled);

    GP kp = {kproj_w, kproj_b, kpool, kbn_m, kbn_v, kbn_g, kbn_b};
    GP vp = {vproj_w, vproj_b, vpool, vbn_m, vbn_v, vbn_g, vbn_b};
    mma_gemm<1><<<dim3(2, 32, 2), 256, GEMM_SMEM>>>(pooled, BATCH*HP2, CH, CH, kp, vp);

    global_attn_kernel<<<BATCH*HEADS, 256>>>(kpool, vpool, qtok, qin);

    GP ckp = {ck_w, ck_b, gk, 0, 0, 0, 0};
    GP cvp = {cv_w, cv_b, gv, 0, 0, 0, 0};
    mma_gemm<0><<<dim3(2, 1, 2), 256, GEMM_SMEM>>>(qin, BATCH*NQ, CH, CH, ckp, cvp);

    GP qkvp = {qkv_w, qkv_b, qkv, 0, 0, 0, 0};
    mma_gemm<0><<<dim3(6, 512, 1), 256, GEMM_SMEM>>>(xn, M, CH, 3*CH, qkvp, qkvp);

    window_attn_kernel<<<BATCH*NWIN*HEADS, 256>>>(qkv, gk, gv, rpb, out_attn, attout);

    GP projp = {proj_w, proj_b, xnew, x, 0, 0, 0};
    mma_gemm<3><<<dim3(2, 512, 1), 256, GEMM_SMEM>>>(attout, M, CH, CH, projp, projp);

    layernorm_kernel<<<M, 256>>>(xnew, n2_g, n2_b, xm);

    GP fc1p = {fc1_w, fc1_b, hbuf, 0, 0, 0, 0};
    mma_gemm<2><<<dim3(8, 512, 1), 256, GEMM_SMEM>>>(xm, M, CH, 4*CH, fc1p, fc1p);

    GP fc2p = {fc2_w, fc2_b, out_x, xnew, 0, 0, 0};
    mma_gemm<3><<<dim3(2, 512, 1), 256, GEMM_SMEM>>>(hbuf, M, 4*CH, CH, fc2p, fc2p);
}

// round 9
// speedup vs baseline: 3.8798x; 1.3012x over previous
#include <cuda_runtime.h>
#include <cuda_fp16.h>
#include <math.h>

// ---------------- problem constants ----------------
#define BATCH   16
#define CH      256
#define NTOK    4096
#define GRIDW   64
#define HEADS   8
#define HD      32
#define NQ      8
#define WS      8
#define NWIN    64
#define KVLEN   72
#define HP2     256
#define SCALE   0.17677669529663687f

// ---------------- scratch ----------------
__device__ float g_xn   [(long)BATCH*NTOK*CH];
__device__ float g_pooled[(long)BATCH*HP2*CH];
__device__ float g_kpool [(long)BATCH*HP2*CH];
__device__ float g_vpool [(long)BATCH*HP2*CH];
__device__ float g_qin   [BATCH*NQ*CH];
__device__ float g_gk    [BATCH*NQ*CH];
__device__ float g_gv    [BATCH*NQ*CH];
__device__ float g_qkv  [(long)BATCH*NTOK*3*CH];
__device__ float g_attout[(long)BATCH*NTOK*CH];
__device__ float g_xnew [(long)BATCH*NTOK*CH];
__device__ float g_xm   [(long)BATCH*NTOK*CH];
__device__ float g_h    [(long)BATCH*NTOK*4*CH];

// fp16 weight copies (converted once per call)
__device__ __half g_wqkv[768*256];
__device__ __half g_wfc1[1024*256];
__device__ __half g_wfc2[256*1024];
__device__ __half g_wproj[256*256];
__device__ __half g_wkp [256*256];
__device__ __half g_wvp [256*256];
__device__ __half g_wck [256*256];
__device__ __half g_wcv [256*256];

// ---------------- helpers ----------------
__device__ __forceinline__ void mma_f16(float* c, const unsigned* a, const unsigned* b) {
    asm volatile(
        "mma.sync.aligned.m16n8k16.row.col.f32.f16.f16.f32 "
        "{%0,%1,%2,%3}, {%4,%5,%6,%7}, {%8,%9}, {%0,%1,%2,%3};"
        : "+f"(c[0]), "+f"(c[1]), "+f"(c[2]), "+f"(c[3])
        : "r"(a[0]), "r"(a[1]), "r"(a[2]), "r"(a[3]), "r"(b[0]), "r"(b[1]));
}

__device__ __forceinline__ void mma_tf32(float* c, const unsigned* a, const unsigned* b) {
    asm volatile(
        "mma.sync.aligned.m16n8k8.row.col.f32.tf32.tf32.f32 "
        "{%0,%1,%2,%3}, {%4,%5,%6,%7}, {%8,%9}, {%0,%1,%2,%3};"
        : "+f"(c[0]), "+f"(c[1]), "+f"(c[2]), "+f"(c[3])
        : "r"(a[0]), "r"(a[1]), "r"(a[2]), "r"(a[3]), "r"(b[0]), "r"(b[1]));
}

__device__ __forceinline__ void cp16(void* dst, const void* src) {
    unsigned d = (unsigned)__cvta_generic_to_shared(dst);
    asm volatile("cp.async.cg.shared.global [%0], [%1], 16;" :: "r"(d), "l"(src));
}
__device__ __forceinline__ void cp_commit() {
    asm volatile("cp.async.commit_group;");
}
__device__ __forceinline__ void cp_wait1() {
    asm volatile("cp.async.wait_group 1;");
}

// ---------------- weight fp32 -> fp16 conversion ----------------
__global__ void wconv_kernel(const float* __restrict__ s, __half* __restrict__ d, int n4) {
    int i = blockIdx.x*256 + threadIdx.x;
    if (i < n4) {
        float4 v = ((const float4*)s)[i];
        __half2 a = __floats2half2_rn(v.x, v.y);
        __half2 b = __floats2half2_rn(v.z, v.w);
        uint2 u;
        u.x = *(unsigned*)&a;
        u.y = *(unsigned*)&b;
        ((uint2*)d)[i] = u;
    }
}

// ---------------- layernorm: warp per row, shfl-only ----------------
__global__ void layernorm_kernel(const float* __restrict__ x,
                                 const float* __restrict__ g,
                                 const float* __restrict__ b,
                                 float* __restrict__ out) {
    long row = (long)blockIdx.x*8 + (threadIdx.x >> 5);
    int lane = threadIdx.x & 31;
    const float4* xr = (const float4*)(x + row*CH);
    float4 v0 = xr[lane], v1 = xr[lane + 32];
    float s = v0.x+v0.y+v0.z+v0.w + v1.x+v1.y+v1.z+v1.w;
    #pragma unroll
    for (int o = 16; o; o >>= 1) s += __shfl_xor_sync(~0u, s, o);
    float m = s * (1.f/CH);
    float d0x=v0.x-m, d0y=v0.y-m, d0z=v0.z-m, d0w=v0.w-m;
    float d1x=v1.x-m, d1y=v1.y-m, d1z=v1.z-m, d1w=v1.w-m;
    float q = d0x*d0x+d0y*d0y+d0z*d0z+d0w*d0w + d1x*d1x+d1y*d1y+d1z*d1z+d1w*d1w;
    #pragma unroll
    for (int o = 16; o; o >>= 1) q += __shfl_xor_sync(~0u, q, o);
    float r = rsqrtf(q * (1.f/CH) + 1e-5f);
    const float4* gr = (const float4*)g;
    const float4* br = (const float4*)b;
    float4 g0 = gr[lane], g1 = gr[lane+32], b0 = br[lane], b1 = br[lane+32];
    float4 o0, o1;
    o0.x = d0x*r*g0.x + b0.x; o0.y = d0y*r*g0.y + b0.y;
    o0.z = d0z*r*g0.z + b0.z; o0.w = d0w*r*g0.w + b0.w;
    o1.x = d1x*r*g1.x + b1.x; o1.y = d1y*r*g1.y + b1.y;
    o1.z = d1z*r*g1.z + b1.z; o1.w = d1w*r*g1.w + b1.w;
    float4* orow = (float4*)(out + row*CH);
    orow[lane] = o0; orow[lane+32] = o1;
}

// ---------------- 4x4 avg pool ----------------
__global__ void pool_kernel(const float* __restrict__ xn, float* __restrict__ pooled) {
    int bidx = blockIdx.x;
    int b = bidx >> 8, hw = bidx & 255;
    int py = hw >> 4, px = hw & 15;
    int c = threadIdx.x;
    float s = 0.f;
    #pragma unroll
    for (int dy = 0; dy < 4; dy++)
        #pragma unroll
        for (int dx = 0; dx < 4; dx++) {
            int n = (py*4 + dy)*GRIDW + px*4 + dx;
            s += xn[((long)b*NTOK + n)*CH + c];
        }
    pooled[(long)bidx*CH + c] = s * (1.f/16.f);
}

// ---------------- fp16 double-buffered GEMM (mma.sync m16n8k16) --------
// out[M,O] = A[M,K]fp32 @ Wh[O,K]fp16^T + bias. BM=BN=128, BK=32.
// A: LDG fp32 -> cvt -> STS half (register prefetch). B: cp.async halves.
// 256 thr, 8 warps (2m x 4n), warp tile 64x32.
// EPI: 0 bias; 1 BN(e0=m,e1=v,e2=g,e3=b); 2 GELU; 3 residual add (e0[M,O])
#define PADH 40                  // halves per smem row (32 + 8 pad), 80B
#define TSTG (128*PADH)          // halves per matrix per stage

struct GP {
    const __half* W; const float* bias; float* out;
    const float* e0; const float* e1; const float* e2; const float* e3;
};

template<int EPI>
__global__ void __launch_bounds__(256, 2)
mma_gemm(const float* __restrict__ A, int M, int K, int O, GP p0, GP p1) {
    extern __shared__ __half hsm[];
    __half* Ah = hsm;              // [2][128][PADH]
    __half* Bh = hsm + 2*TSTG;     // [2][128][PADH]

    const GP* P = blockIdx.z ? &p1 : &p0;
    const __half* __restrict__ W = P->W;

    int tid  = threadIdx.x;
    int warp = tid >> 5, lane = tid & 31;
    int wm = warp >> 2, wn = warp & 3;
    int m_warp = wm * 64, n_warp = wn * 32;
    int g = lane >> 2, tg = lane & 3;

    int m0 = blockIdx.y * 128;
    int o0 = blockIdx.x * 128;

    // A loader mapping: idx = tid + i*256; row = idx>>3, c4 = idx&7 (float4)
    int lr = tid >> 3;
    int lc4 = tid & 7;
    // B loader mapping: gi = tid + i*256; row = gi>>2, g16 = gi&3 (16B granule)
    int br_ = tid >> 2;
    int bg = tid & 3;

    float acc[4][4][4] = {};
    float4 pa[4];

    // prologue: LDG A chunk0, cp.async B chunk0
    #pragma unroll
    for (int i = 0; i < 4; i++)
        pa[i] = *(const float4*)(A + (long)(m0 + lr + i*32)*K + lc4*4);
    #pragma unroll
    for (int i = 0; i < 2; i++) {
        int row = br_ + i*64;
        cp16((char*)(Bh + row*PADH) + bg*16, W + (long)(o0 + row)*K + bg*8);
    }
    cp_commit();

    int NC = K >> 5;
    for (int c = 0; c < NC; c++) {
        int s = c & 1;
        // STS A chunk c (convert fp32 -> fp16)
        {
            __half* Ad = Ah + s*TSTG;
            #pragma unroll
            for (int i = 0; i < 4; i++) {
                __half2 h01 = __floats2half2_rn(pa[i].x, pa[i].y);
                __half2 h23 = __floats2half2_rn(pa[i].z, pa[i].w);
                uint2 u;
                u.x = *(unsigned*)&h01;
                u.y = *(unsigned*)&h23;
                *(uint2*)(Ad + (lr + i*32)*PADH + lc4*4) = u;
            }
        }
        // issue B chunk c+1
        if (c + 1 < NC) {
            __half* Bd = Bh + (s^1)*TSTG;
            #pragma unroll
            for (int i = 0; i < 2; i++) {
                int row = br_ + i*64;
                cp16((char*)(Bd + row*PADH) + bg*16,
                     W + (long)(o0 + row)*K + (c+1)*32 + bg*8);
            }
        }
        cp_commit();
        cp_wait1();
        __syncthreads();

        // prefetch A chunk c+1
        if (c + 1 < NC) {
            #pragma unroll
            for (int i = 0; i < 4; i++)
                pa[i] = *(const float4*)(A + (long)(m0 + lr + i*32)*K + (c+1)*32 + lc4*4);
        }

        const __half* Ab = Ah + s*TSTG;
        const __half* Bb = Bh + s*TSTG;
        #pragma unroll
        for (int kt = 0; kt < 2; kt++) {
            int k0 = kt*16;
            unsigned af[4][4], bf[4][2];
            #pragma unroll
            for (int mt = 0; mt < 4; mt++) {
                int mb = m_warp + mt*16 + g;
                af[mt][0] = *(const unsigned*)(Ab + mb*PADH + k0 + tg*2);
                af[mt][1] = *(const unsigned*)(Ab + (mb+8)*PADH + k0 + tg*2);
                af[mt][2] = *(const unsigned*)(Ab + mb*PADH + k0 + tg*2 + 8);
                af[mt][3] = *(const unsigned*)(Ab + (mb+8)*PADH + k0 + tg*2 + 8);
            }
            #pragma unroll
            for (int nt = 0; nt < 4; nt++) {
                int nb = n_warp + nt*8 + g;
                bf[nt][0] = *(const unsigned*)(Bb + nb*PADH + k0 + tg*2);
                bf[nt][1] = *(const unsigned*)(Bb + nb*PADH + k0 + tg*2 + 8);
            }
            #pragma unroll
            for (int mt = 0; mt < 4; mt++)
                #pragma unroll
                for (int nt = 0; nt < 4; nt++)
                    mma_f16(acc[mt][nt], af[mt], bf[nt]);
        }
        __syncthreads();
    }

    const float* __restrict__ bias = P->bias;
    float* __restrict__ out = P->out;
    const float* e0 = P->e0;
    const float* e1 = P->e1;
    const float* e2 = P->e2;
    const float* e3 = P->e3;

    #pragma unroll
    for (int mt = 0; mt < 4; mt++) {
        #pragma unroll
        for (int nt = 0; nt < 4; nt++) {
            #pragma unroll
            for (int c = 0; c < 4; c++) {
                int m = m0 + m_warp + mt*16 + g + (c >> 1)*8;
                int o = o0 + n_warp + nt*8 + tg*2 + (c & 1);
                float y = acc[mt][nt][c] + bias[o];
                if (EPI == 1) {
                    y = (y - e0[o]) * rsqrtf(e1[o] + 1e-5f) * e2[o] + e3[o];
                } else if (EPI == 2) {
                    y = 0.5f * y * (1.0f + erff(y * 0.70710678118654752f));
                } else if (EPI == 3) {
                    y += e0[(long)m*O + o];
                }
                out[(long)m*O + o] = y;
            }
        }
    }
}

// ---------------- global cross-attention pooling path -----------------
__global__ void global_attn_kernel(const float* __restrict__ kpool,
                                   const float* __restrict__ vpool,
                                   const float* __restrict__ qtok,
                                   float* __restrict__ qin) {
    int b = blockIdx.x >> 3, h = blockIdx.x & 7;
    __shared__ float qs[NQ][HD];
    __shared__ float lg[NQ][HP2];
    __shared__ float vsm[HP2][HD];
    int tid = threadIdx.x;
    { int q = tid >> 5, d = tid & 31; qs[q][d] = qtok[q*CH + h*HD + d]; }
    for (int idx = tid; idx < HP2*HD; idx += 256) {
        int r = idx >> 5, d = idx & 31;
        vsm[r][d] = vpool[((long)b*HP2 + r)*CH + h*HD + d];
    }
    __syncthreads();
    float kreg[HD];
    const float* kr = kpool + ((long)b*HP2 + tid)*CH + h*HD;
    #pragma unroll
    for (int d = 0; d < HD; d++) kreg[d] = kr[d];
    #pragma unroll
    for (int q = 0; q < NQ; q++) {
        float s = 0.f;
        #pragma unroll
        for (int d = 0; d < HD; d++) s = fmaf(qs[q][d], kreg[d], s);
        lg[q][tid] = s * SCALE;
    }
    __syncthreads();
    int w = tid >> 5, lane = tid & 31;
    {
        float m = -1e30f;
        for (int j = lane; j < HP2; j += 32) m = fmaxf(m, lg[w][j]);
        #pragma unroll
        for (int o = 16; o; o >>= 1) m = fmaxf(m, __shfl_xor_sync(~0u, m, o));
        float s = 0.f;
        for (int j = lane; j < HP2; j += 32) { float e = __expf(lg[w][j] - m); lg[w][j] = e; s += e; }
        #pragma unroll
        for (int o = 16; o; o >>= 1) s += __shfl_xor_sync(~0u, s, o);
        float inv = 1.f / s;
        for (int j = lane; j < HP2; j += 32) lg[w][j] *= inv;
    }
    __syncthreads();
    int q = tid >> 5, d = tid & 31;
    float acc = 0.f;
    for (int kk = 0; kk < HP2; kk++) acc = fmaf(lg[q][kk], vsm[kk][d], acc);
    qin[(b*NQ + q)*CH + h*HD + d] = acc + qtok[q*CH + h*HD + d];
}

// ---------------- window attention (tensor-core, tf32) -----------------
__global__ void __launch_bounds__(256)
window_attn_kernel(const float* __restrict__ qkv,
                   const float* __restrict__ gk,
                   const float* __restrict__ gv,
                   const float* __restrict__ rpb,
                   float* __restrict__ attn_out,
                   float* __restrict__ attout) {
    int h   = blockIdx.x & 7;
    int win = blockIdx.x >> 3;
    int wx = win & 7, wy = (win >> 3) & 7, b = win >> 6;
    int n_base = (wy*WS)*GRIDW + wx*WS;

    __shared__ float qs[64][36];
    __shared__ float ks[80][36];
    __shared__ float vt[32][84];
    __shared__ float lg[64][84];

    int tid = threadIdx.x;
    int warp = tid >> 5, lane = tid & 31;
    int g = lane >> 2, tg = lane & 3;

    for (int idx = tid; idx < 64*32; idx += 256) {
        int i = idx >> 5, d = idx & 31;
        int n = n_base + (i >> 3)*GRIDW + (i & 7);
        qs[i][d] = qkv[((long)b*NTOK + n)*(3*CH) + h*HD + d] * SCALE;
    }
    for (int idx = tid; idx < 80*32; idx += 256) {
        int j = idx >> 5, d = idx & 31;
        float kv = 0.f, vv = 0.f;
        if (j < 64) {
            int n = n_base + (j >> 3)*GRIDW + (j & 7);
            long base = ((long)b*NTOK + n)*(3*CH) + h*HD + d;
            kv = qkv[base + CH];
            vv = qkv[base + 2*CH];
        } else if (j < 72) {
            int nq = j - 64;
            kv = gk[(b*NQ + nq)*CH + h*HD + d];
            vv = gv[(b*NQ + nq)*CH + h*HD + d];
        }
        ks[j][d] = kv;
        vt[d][j] = vv;
    }
    __syncthreads();

    {
        int mw = (warp >> 1)*16, np = (warp & 1)*40;
        float acc[5][4] = {};
        #pragma unroll
        for (int kt = 0; kt < 4; kt++) {
            int k0 = kt*8;
            unsigned a[4];
            a[0] = __float_as_uint(qs[mw+g][k0+tg]);
            a[1] = __float_as_uint(qs[mw+g+8][k0+tg]);
            a[2] = __float_as_uint(qs[mw+g][k0+tg+4]);
            a[3] = __float_as_uint(qs[mw+g+8][k0+tg+4]);
            #pragma unroll
            for (int nt = 0; nt < 5; nt++) {
                int nb = np + nt*8 + g;
                unsigned bb[2];
                bb[0] = __float_as_uint(ks[nb][k0+tg]);
                bb[1] = __float_as_uint(ks[nb][k0+tg+4]);
                mma_tf32(acc[nt], a, bb);
            }
        }
        #pragma unroll
        for (int nt = 0; nt < 5; nt++) {
            #pragma unroll
            for (int c = 0; c < 4; c++) {
                int i = mw + g + (c >> 1)*8;
                int j = np + nt*8 + tg*2 + (c & 1);
                float s = acc[nt][c];
                if (j < 64) {
                    int diy = (i >> 3) - (j >> 3) + 7;
                    int dix = (i & 7) - (j & 7) + 7;
                    s += rpb[(diy*15 + dix)*HEADS + h];
                }
                lg[i][j] = s;
            }
        }
    }
    __syncthreads();

    for (int it = 0; it < 8; it++) {
        int i = it*8 + warp;
        float m = -1e30f;
        for (int j = lane; j < KVLEN; j += 32) m = fmaxf(m, lg[i][j]);
        #pragma unroll
        for (int o = 16; o; o >>= 1) m = fmaxf(m, __shfl_xor_sync(~0u, m, o));
        float s = 0.f;
        for (int j = lane; j < KVLEN; j += 32) { float e = __expf(lg[i][j] - m); lg[i][j] = e; s += e; }
        #pragma unroll
        for (int o = 16; o; o >>= 1) s += __shfl_xor_sync(~0u, s, o);
        float inv = 1.f / s;
        for (int j = lane; j < KVLEN; j += 32) lg[i][j] *= inv;
    }
    __syncthreads();

    long abase = ((long)(win*HEADS + h))*64*KVLEN;
    for (int idx = tid; idx < 64*KVLEN; idx += 256) {
        int i = idx / KVLEN, j = idx - i*KVLEN;
        attn_out[abase + idx] = lg[i][j];
    }

    {
        int mw = (warp >> 1)*16, nv = (warp & 1)*16;
        float acc[2][4] = {};
        #pragma unroll
        for (int kt = 0; kt < 10; kt++) {
            int k0 = kt*8;
            unsigned a[4];
            a[0] = __float_as_uint(lg[mw+g][k0+tg]);
            a[1] = __float_as_uint(lg[mw+g+8][k0+tg]);
            a[2] = __float_as_uint(lg[mw+g][k0+tg+4]);
            a[3] = __float_as_uint(lg[mw+g+8][k0+tg+4]);
            #pragma unroll
            for (int nt = 0; nt < 2; nt++) {
                int nb = nv + nt*8 + g;
                unsigned bb[2];
                bb[0] = __float_as_uint(vt[nb][k0+tg]);
                bb[1] = __float_as_uint(vt[nb][k0+tg+4]);
                mma_tf32(acc[nt], a, bb);
            }
        }
        #pragma unroll
        for (int nt = 0; nt < 2; nt++) {
            #pragma unroll
            for (int c = 0; c < 4; c++) {
                int i = mw + g + (c >> 1)*8;
                int d = nv + nt*8 + tg*2 + (c & 1);
                int n = n_base + (i >> 3)*GRIDW + (i & 7);
                attout[((long)b*NTOK + n)*CH + h*HD + d] = acc[nt][c];
            }
        }
    }
}

// ---------------- host launch ------------------------------------------
#define GEMM_SMEM (4*TSTG*2)   // bytes: 2 stages x (A+B) x 128 x PADH halves

extern "C" void kernel_launch(void* const* d_in, const int* in_sizes, int n_in,
                              void* d_out, int out_size) {
    const float* x       = (const float*)d_in[0];
    const float* qtok    = (const float*)d_in[1];
    const float* kproj_w = (const float*)d_in[2];
    const float* kproj_b = (const float*)d_in[3];
    const float* kbn_g   = (const float*)d_in[4];
    const float* kbn_b   = (const float*)d_in[5];
    const float* kbn_m   = (const float*)d_in[6];
    const float* kbn_v   = (const float*)d_in[7];
    const float* vproj_w = (const float*)d_in[8];
    const float* vproj_b = (const float*)d_in[9];
    const float* vbn_g   = (const float*)d_in[10];
    const float* vbn_b   = (const float*)d_in[11];
    const float* vbn_m   = (const float*)d_in[12];
    const float* vbn_v   = (const float*)d_in[13];
    const float* ck_w    = (const float*)d_in[14];
    const float* ck_b    = (const float*)d_in[15];
    const float* cv_w    = (const float*)d_in[16];
    const float* cv_b    = (const float*)d_in[17];
    const float* rpb     = (const float*)d_in[18];
    const float* qkv_w   = (const float*)d_in[19];
    const float* qkv_b   = (const float*)d_in[20];
    const float* proj_w  = (const float*)d_in[21];
    const float* proj_b  = (const float*)d_in[22];
    const float* n1_g    = (const float*)d_in[23];
    const float* n1_b    = (const float*)d_in[24];
    const float* n2_g    = (const float*)d_in[25];
    const float* n2_b    = (const float*)d_in[26];
    const float* fc1_w   = (const float*)d_in[27];
    const float* fc1_b   = (const float*)d_in[28];
    const float* fc2_w   = (const float*)d_in[29];
    const float* fc2_b   = (const float*)d_in[30];

    float* out_x    = (float*)d_out;
    float* out_attn = out_x + (long)BATCH*NTOK*CH;

    float *xn, *pooled, *kpool, *vpool, *qin, *gk, *gv, *qkv, *attout, *xnew, *xm, *hbuf;
    cudaGetSymbolAddress((void**)&xn,     g_xn);
    cudaGetSymbolAddress((void**)&pooled, g_pooled);
    cudaGetSymbolAddress((void**)&kpool,  g_kpool);
    cudaGetSymbolAddress((void**)&vpool,  g_vpool);
    cudaGetSymbolAddress((void**)&qin,    g_qin);
    cudaGetSymbolAddress((void**)&gk,     g_gk);
    cudaGetSymbolAddress((void**)&gv,     g_gv);
    cudaGetSymbolAddress((void**)&qkv,    g_qkv);
    cudaGetSymbolAddress((void**)&attout, g_attout);
    cudaGetSymbolAddress((void**)&xnew,   g_xnew);
    cudaGetSymbolAddress((void**)&xm,     g_xm);
    cudaGetSymbolAddress((void**)&hbuf,   g_h);

    __half *wqkv, *wfc1, *wfc2, *wproj, *wkp, *wvp, *wck, *wcv;
    cudaGetSymbolAddress((void**)&wqkv, g_wqkv);
    cudaGetSymbolAddress((void**)&wfc1, g_wfc1);
    cudaGetSymbolAddress((void**)&wfc2, g_wfc2);
    cudaGetSymbolAddress((void**)&wproj, g_wproj);
    cudaGetSymbolAddress((void**)&wkp,  g_wkp);
    cudaGetSymbolAddress((void**)&wvp,  g_wvp);
    cudaGetSymbolAddress((void**)&wck,  g_wck);
    cudaGetSymbolAddress((void**)&wcv,  g_wcv);

    static int smem_set = 0;
    if (!smem_set) {
        cudaFuncSetAttribute(mma_gemm<0>, cudaFuncAttributeMaxDynamicSharedMemorySize, GEMM_SMEM);
        cudaFuncSetAttribute(mma_gemm<1>, cudaFuncAttributeMaxDynamicSharedMemorySize, GEMM_SMEM);
        cudaFuncSetAttribute(mma_gemm<2>, cudaFuncAttributeMaxDynamicSharedMemorySize, GEMM_SMEM);
        cudaFuncSetAttribute(mma_gemm<3>, cudaFuncAttributeMaxDynamicSharedMemorySize, GEMM_SMEM);
        smem_set = 1;
    }

    const int M = BATCH*NTOK;   // 65536

    // weight conversions (independent of activations)
    wconv_kernel<<<192, 256>>>(qkv_w, wqkv, 49152);
    wconv_kernel<<<256, 256>>>(fc1_w, wfc1, 65536);
    wconv_kernel<<<256, 256>>>(fc2_w, wfc2, 65536);
    wconv_kernel<<<64, 256>>>(proj_w, wproj, 16384);
    wconv_kernel<<<64, 256>>>(kproj_w, wkp, 16384);
    wconv_kernel<<<64, 256>>>(vproj_w, wvp, 16384);
    wconv_kernel<<<64, 256>>>(ck_w, wck, 16384);
    wconv_kernel<<<64, 256>>>(cv_w, wcv, 16384);

    layernorm_kernel<<<M/8, 256>>>(x, n1_g, n1_b, xn);
    pool_kernel<<<BATCH*HP2, 256>>>(xn, pooled);

    GP kp = {wkp, kproj_b, kpool, kbn_m, kbn_v, kbn_g, kbn_b};
    GP vp = {wvp, vproj_b, vpool, vbn_m, vbn_v, vbn_g, vbn_b};
    mma_gemm<1><<<dim3(2, 32, 2), 256, GEMM_SMEM>>>(pooled, BATCH*HP2, CH, CH, kp, vp);

    global_attn_kernel<<<BATCH*HEADS, 256>>>(kpool, vpool, qtok, qin);

    GP ckp = {wck, ck_b, gk, 0, 0, 0, 0};
    GP cvp = {wcv, cv_b, gv, 0, 0, 0, 0};
    mma_gemm<0><<<dim3(2, 1, 2), 256, GEMM_SMEM>>>(qin, BATCH*NQ, CH, CH, ckp, cvp);

    GP qkvp = {wqkv, qkv_b, qkv, 0, 0, 0, 0};
    mma_gemm<0><<<dim3(6, 512, 1), 256, GEMM_SMEM>>>(xn, M, CH, 3*CH, qkvp, qkvp);

    window_attn_kernel<<<BATCH*NWIN*HEADS, 256>>>(qkv, gk, gv, rpb, out_attn, attout);

    GP projp = {wproj, proj_b, xnew, x, 0, 0, 0};
    mma_gemm<3><<<dim3(2, 512, 1), 256, GEMM_SMEM>>>(attout, M, CH, CH, projp, projp);

    layernorm_kernel<<<M/8, 256>>>(xnew, n2_g, n2_b, xm);

    GP fc1p = {wfc1, fc1_b, hbuf, 0, 0, 0, 0};
    mma_gemm<2><<<dim3(8, 512, 1), 256, GEMM_SMEM>>>(xm, M, CH, 4*CH, fc1p, fc1p);

    GP fc2p = {wfc2, fc2_b, out_x, xnew, 0, 0, 0};
    mma_gemm<3><<<dim3(2, 512, 1), 256, GEMM_SMEM>>>(hbuf, M, 4*CH, CH, fc2p, fc2p);
}

// round 10
// speedup vs baseline: 4.3161x; 1.1125x over previous
#include <cuda_runtime.h>
#include <cuda_fp16.h>
#include <math.h>

// ---------------- problem constants ----------------
#define BATCH   16
#define CH      256
#define NTOK    4096
#define GRIDW   64
#define HEADS   8
#define HD      32
#define NQ      8
#define WS      8
#define NWIN    64
#define KVLEN   72
#define HP2     256
#define SCALE   0.17677669529663687f

// ---------------- scratch ----------------
__device__ float  g_xn   [(long)BATCH*NTOK*CH];
__device__ __half g_xnh  [(long)BATCH*NTOK*CH];
__device__ float  g_pooled[(long)BATCH*HP2*CH];
__device__ float  g_kpool [(long)BATCH*HP2*CH];
__device__ float  g_vpool [(long)BATCH*HP2*CH];
__device__ float  g_qin   [BATCH*NQ*CH];
__device__ float  g_gk    [BATCH*NQ*CH];
__device__ float  g_gv    [BATCH*NQ*CH];
__device__ float  g_qkv  [(long)BATCH*NTOK*3*CH];
__device__ __half g_attouth[(long)BATCH*NTOK*CH];
__device__ float  g_xnew [(long)BATCH*NTOK*CH];
__device__ __half g_xmh  [(long)BATCH*NTOK*CH];
__device__ __half g_hh   [(long)BATCH*NTOK*4*CH];

// fp16 weight copies
__device__ __half g_wqkv[768*256];
__device__ __half g_wfc1[1024*256];
__device__ __half g_wfc2[256*1024];
__device__ __half g_wproj[256*256];
__device__ __half g_wkp [256*256];
__device__ __half g_wvp [256*256];
__device__ __half g_wck [256*256];
__device__ __half g_wcv [256*256];

// ---------------- helpers ----------------
__device__ __forceinline__ void mma_f16(float* c, const unsigned* a, const unsigned* b) {
    asm volatile(
        "mma.sync.aligned.m16n8k16.row.col.f32.f16.f16.f32 "
        "{%0,%1,%2,%3}, {%4,%5,%6,%7}, {%8,%9}, {%0,%1,%2,%3};"
        : "+f"(c[0]), "+f"(c[1]), "+f"(c[2]), "+f"(c[3])
        : "r"(a[0]), "r"(a[1]), "r"(a[2]), "r"(a[3]), "r"(b[0]), "r"(b[1]));
}

__device__ __forceinline__ void mma_tf32(float* c, const unsigned* a, const unsigned* b) {
    asm volatile(
        "mma.sync.aligned.m16n8k8.row.col.f32.tf32.tf32.f32 "
        "{%0,%1,%2,%3}, {%4,%5,%6,%7}, {%8,%9}, {%0,%1,%2,%3};"
        : "+f"(c[0]), "+f"(c[1]), "+f"(c[2]), "+f"(c[3])
        : "r"(a[0]), "r"(a[1]), "r"(a[2]), "r"(a[3]), "r"(b[0]), "r"(b[1]));
}

__device__ __forceinline__ void cp16(void* dst, const void* src) {
    unsigned d = (unsigned)__cvta_generic_to_shared(dst);
    asm volatile("cp.async.cg.shared.global [%0], [%1], 16;" :: "r"(d), "l"(src));
}
__device__ __forceinline__ void cp_commit() {
    asm volatile("cp.async.commit_group;");
}
__device__ __forceinline__ void cp_wait1() {
    asm volatile("cp.async.wait_group 1;");
}

// ---------------- merged weight fp32 -> fp16 conversion ----------------
struct WC { const float* s[8]; __half* d[8]; int n4[8]; };

__global__ void wconv_all(WC wc) {
    int seg = blockIdx.y;
    int i = blockIdx.x*256 + threadIdx.x;
    if (i < wc.n4[seg]) {
        float4 v = ((const float4*)wc.s[seg])[i];
        __half2 a = __floats2half2_rn(v.x, v.y);
        __half2 b = __floats2half2_rn(v.z, v.w);
        uint2 u;
        u.x = *(unsigned*)&a;
        u.y = *(unsigned*)&b;
        ((uint2*)wc.d[seg])[i] = u;
    }
}

// ---------------- layernorm: warp per row, shfl-only -------------------
// MODE 0: fp32 only, 1: half only, 2: both
template<int MODE>
__global__ void layernorm_kernel(const float* __restrict__ x,
                                 const float* __restrict__ g,
                                 const float* __restrict__ b,
                                 float* __restrict__ out,
                                 __half* __restrict__ outh) {
    long row = (long)blockIdx.x*8 + (threadIdx.x >> 5);
    int lane = threadIdx.x & 31;
    const float4* xr = (const float4*)(x + row*CH);
    float4 v0 = xr[lane], v1 = xr[lane + 32];
    float s = v0.x+v0.y+v0.z+v0.w + v1.x+v1.y+v1.z+v1.w;
    #pragma unroll
    for (int o = 16; o; o >>= 1) s += __shfl_xor_sync(~0u, s, o);
    float m = s * (1.f/CH);
    float d0x=v0.x-m, d0y=v0.y-m, d0z=v0.z-m, d0w=v0.w-m;
    float d1x=v1.x-m, d1y=v1.y-m, d1z=v1.z-m, d1w=v1.w-m;
    float q = d0x*d0x+d0y*d0y+d0z*d0z+d0w*d0w + d1x*d1x+d1y*d1y+d1z*d1z+d1w*d1w;
    #pragma unroll
    for (int o = 16; o; o >>= 1) q += __shfl_xor_sync(~0u, q, o);
    float r = rsqrtf(q * (1.f/CH) + 1e-5f);
    const float4* gr = (const float4*)g;
    const float4* br = (const float4*)b;
    float4 g0 = gr[lane], g1 = gr[lane+32], b0 = br[lane], b1 = br[lane+32];
    float4 o0, o1;
    o0.x = d0x*r*g0.x + b0.x; o0.y = d0y*r*g0.y + b0.y;
    o0.z = d0z*r*g0.z + b0.z; o0.w = d0w*r*g0.w + b0.w;
    o1.x = d1x*r*g1.x + b1.x; o1.y = d1y*r*g1.y + b1.y;
    o1.z = d1z*r*g1.z + b1.z; o1.w = d1w*r*g1.w + b1.w;
    if (MODE != 1) {
        float4* orow = (float4*)(out + row*CH);
        orow[lane] = o0; orow[lane+32] = o1;
    }
    if (MODE != 0) {
        __half2 h0 = __floats2half2_rn(o0.x, o0.y);
        __half2 h1 = __floats2half2_rn(o0.z, o0.w);
        __half2 h2 = __floats2half2_rn(o1.x, o1.y);
        __half2 h3 = __floats2half2_rn(o1.z, o1.w);
        uint2 u0, u1;
        u0.x = *(unsigned*)&h0; u0.y = *(unsigned*)&h1;
        u1.x = *(unsigned*)&h2; u1.y = *(unsigned*)&h3;
        uint2* hrow = (uint2*)(outh + row*CH);
        hrow[lane] = u0; hrow[lane+32] = u1;
    }
}

// ---------------- 4x4 avg pool ----------------
__global__ void pool_kernel(const float* __restrict__ xn, float* __restrict__ pooled) {
    int bidx = blockIdx.x;
    int b = bidx >> 8, hw = bidx & 255;
    int py = hw >> 4, px = hw & 15;
    int c = threadIdx.x;
    float s = 0.f;
    #pragma unroll
    for (int dy = 0; dy < 4; dy++)
        #pragma unroll
        for (int dx = 0; dx < 4; dx++) {
            int n = (py*4 + dy)*GRIDW + px*4 + dx;
            s += xn[((long)b*NTOK + n)*CH + c];
        }
    pooled[(long)bidx*CH + c] = s * (1.f/16.f);
}

// ---------------- fp16 double-buffered GEMM (mma.sync m16n8k16) --------
// out[M,O] = A[M,K] @ Wh[O,K]^T + bias. BM=BN=128, BK=32. 256 thr.
// AH=1: A fp16 in gmem (pure cp.async). AH=0: A fp32 LDG->cvt->STS.
// OH=1: store fp16 to outh. EPI: 0 bias; 1 BN; 2 GELU; 3 residual(e0).
#define PADH 40
#define TSTG (128*PADH)

struct GP {
    const __half* W; const float* bias; float* out; __half* outh;
    const float* e0; const float* e1; const float* e2; const float* e3;
};

template<int EPI, int AH, int OH>
__global__ void __launch_bounds__(256, 2)
mma_gemm(const void* Av, int M, int K, int O, GP p0, GP p1) {
    extern __shared__ __half hsm[];
    __half* Ah = hsm;              // [2][128][PADH]
    __half* Bh = hsm + 2*TSTG;     // [2][128][PADH]

    const GP* P = blockIdx.z ? &p1 : &p0;
    const __half* __restrict__ W = P->W;

    int tid  = threadIdx.x;
    int warp = tid >> 5, lane = tid & 31;
    int wm = warp >> 2, wn = warp & 3;
    int m_warp = wm * 64, n_warp = wn * 32;
    int g = lane >> 2, tg = lane & 3;

    int m0 = blockIdx.y * 128;
    int o0 = blockIdx.x * 128;

    int br_ = tid >> 2;      // 0..63
    int bg = tid & 3;        // 16B granule

    float acc[4][4][4] = {};
    int NC = K >> 5;

    if (AH) {
        const __half* Agh = (const __half*)Av;
        // prologue stage 0
        #pragma unroll
        for (int i = 0; i < 2; i++) {
            int row = br_ + i*64;
            cp16(Ah + row*PADH + bg*8, Agh + (long)(m0 + row)*K + bg*8);
            cp16(Bh + row*PADH + bg*8, W + (long)(o0 + row)*K + bg*8);
        }
        cp_commit();
        for (int c = 0; c < NC; c++) {
            int s = c & 1;
            if (c + 1 < NC) {
                int ns = s ^ 1;
                #pragma unroll
                for (int i = 0; i < 2; i++) {
                    int row = br_ + i*64;
                    cp16(Ah + ns*TSTG + row*PADH + bg*8,
                         Agh + (long)(m0 + row)*K + (c+1)*32 + bg*8);
                    cp16(Bh + ns*TSTG + row*PADH + bg*8,
                         W + (long)(o0 + row)*K + (c+1)*32 + bg*8);
                }
            }
            cp_commit();
            cp_wait1();
            __syncthreads();
            const __half* Ab = Ah + s*TSTG;
            const __half* Bb = Bh + s*TSTG;
            #pragma unroll
            for (int kt = 0; kt < 2; kt++) {
                int k0 = kt*16;
                unsigned af[4][4], bf[4][2];
                #pragma unroll
                for (int mt = 0; mt < 4; mt++) {
                    int mb = m_warp + mt*16 + g;
                    af[mt][0] = *(const unsigned*)(Ab + mb*PADH + k0 + tg*2);
                    af[mt][1] = *(const unsigned*)(Ab + (mb+8)*PADH + k0 + tg*2);
                    af[mt][2] = *(const unsigned*)(Ab + mb*PADH + k0 + tg*2 + 8);
                    af[mt][3] = *(const unsigned*)(Ab + (mb+8)*PADH + k0 + tg*2 + 8);
                }
                #pragma unroll
                for (int nt = 0; nt < 4; nt++) {
                    int nb = n_warp + nt*8 + g;
                    bf[nt][0] = *(const unsigned*)(Bb + nb*PADH + k0 + tg*2);
                    bf[nt][1] = *(const unsigned*)(Bb + nb*PADH + k0 + tg*2 + 8);
                }
                #pragma unroll
                for (int mt = 0; mt < 4; mt++)
                    #pragma unroll
                    for (int nt = 0; nt < 4; nt++)
                        mma_f16(acc[mt][nt], af[mt], bf[nt]);
            }
            __syncthreads();
        }
    } else {
        const float* A = (const float*)Av;
        int lr = tid >> 3;
        int lc4 = tid & 7;
        float4 pa[4];
        #pragma unroll
        for (int i = 0; i < 4; i++)
            pa[i] = *(const float4*)(A + (long)(m0 + lr + i*32)*K + lc4*4);
        #pragma unroll
        for (int i = 0; i < 2; i++) {
            int row = br_ + i*64;
            cp16((char*)(Bh + row*PADH) + bg*16, W + (long)(o0 + row)*K + bg*8);
        }
        cp_commit();

        for (int c = 0; c < NC; c++) {
            int s = c & 1;
            {
                __half* Ad = Ah + s*TSTG;
                #pragma unroll
                for (int i = 0; i < 4; i++) {
                    __half2 h01 = __floats2half2_rn(pa[i].x, pa[i].y);
                    __half2 h23 = __floats2half2_rn(pa[i].z, pa[i].w);
                    uint2 u;
                    u.x = *(unsigned*)&h01;
                    u.y = *(unsigned*)&h23;
                    *(uint2*)(Ad + (lr + i*32)*PADH + lc4*4) = u;
                }
            }
            if (c + 1 < NC) {
                __half* Bd = Bh + (s^1)*TSTG;
                #pragma unroll
                for (int i = 0; i < 2; i++) {
                    int row = br_ + i*64;
                    cp16((char*)(Bd + row*PADH) + bg*16,
                         W + (long)(o0 + row)*K + (c+1)*32 + bg*8);
                }
            }
            cp_commit();
            cp_wait1();
            __syncthreads();
            if (c + 1 < NC) {
                #pragma unroll
                for (int i = 0; i < 4; i++)
                    pa[i] = *(const float4*)(A + (long)(m0 + lr + i*32)*K + (c+1)*32 + lc4*4);
            }
            const __half* Ab = Ah + s*TSTG;
            const __half* Bb = Bh + s*TSTG;
            #pragma unroll
            for (int kt = 0; kt < 2; kt++) {
                int k0 = kt*16;
                unsigned af[4][4], bf[4][2];
                #pragma unroll
                for (int mt = 0; mt < 4; mt++) {
                    int mb = m_warp + mt*16 + g;
                    af[mt][0] = *(const unsigned*)(Ab + mb*PADH + k0 + tg*2);
                    af[mt][1] = *(const unsigned*)(Ab + (mb+8)*PADH + k0 + tg*2);
                    af[mt][2] = *(const unsigned*)(Ab + mb*PADH + k0 + tg*2 + 8);
                    af[mt][3] = *(const unsigned*)(Ab + (mb+8)*PADH + k0 + tg*2 + 8);
                }
                #pragma unroll
                for (int nt = 0; nt < 4; nt++) {
                    int nb = n_warp + nt*8 + g;
                    bf[nt][0] = *(const unsigned*)(Bb + nb*PADH + k0 + tg*2);
                    bf[nt][1] = *(const unsigned*)(Bb + nb*PADH + k0 + tg*2 + 8);
                }
                #pragma unroll
                for (int mt = 0; mt < 4; mt++)
                    #pragma unroll
                    for (int nt = 0; nt < 4; nt++)
                        mma_f16(acc[mt][nt], af[mt], bf[nt]);
            }
            __syncthreads();
        }
    }

    const float* __restrict__ bias = P->bias;
    float* __restrict__ out = P->out;
    __half* __restrict__ outh = P->outh;
    const float* e0 = P->e0;
    const float* e1 = P->e1;
    const float* e2 = P->e2;
    const float* e3 = P->e3;

    #pragma unroll
    for (int mt = 0; mt < 4; mt++) {
        #pragma unroll
        for (int nt = 0; nt < 4; nt++) {
            #pragma unroll
            for (int c2 = 0; c2 < 2; c2++) {
                int m = m0 + m_warp + mt*16 + g + c2*8;
                int o = o0 + n_warp + nt*8 + tg*2;
                float y0 = acc[mt][nt][c2*2+0] + bias[o];
                float y1 = acc[mt][nt][c2*2+1] + bias[o+1];
                if (EPI == 1) {
                    y0 = (y0 - e0[o])   * rsqrtf(e1[o]   + 1e-5f) * e2[o]   + e3[o];
                    y1 = (y1 - e0[o+1]) * rsqrtf(e1[o+1] + 1e-5f) * e2[o+1] + e3[o+1];
                } else if (EPI == 2) {
                    y0 = 0.5f*y0*(1.f + erff(y0*0.70710678118654752f));
                    y1 = 0.5f*y1*(1.f + erff(y1*0.70710678118654752f));
                } else if (EPI == 3) {
                    float2 rv = *(const float2*)(e0 + (long)m*O + o);
                    y0 += rv.x; y1 += rv.y;
                }
                if (OH) {
                    __half2 hv = __floats2half2_rn(y0, y1);
                    *(__half2*)(outh + (long)m*O + o) = hv;
                } else {
                    float2 v; v.x = y0; v.y = y1;
                    *(float2*)(out + (long)m*O + o) = v;
                }
            }
        }
    }
}

// ---------------- global cross-attention pooling path -----------------
__global__ void global_attn_kernel(const float* __restrict__ kpool,
                                   const float* __restrict__ vpool,
                                   const float* __restrict__ qtok,
                                   float* __restrict__ qin) {
    int b = blockIdx.x >> 3, h = blockIdx.x & 7;
    __shared__ float qs[NQ][HD];
    __shared__ float lg[NQ][HP2];
    __shared__ float vsm[HP2][HD];
    int tid = threadIdx.x;
    { int q = tid >> 5, d = tid & 31; qs[q][d] = qtok[q*CH + h*HD + d]; }
    for (int idx = tid; idx < HP2*HD; idx += 256) {
        int r = idx >> 5, d = idx & 31;
        vsm[r][d] = vpool[((long)b*HP2 + r)*CH + h*HD + d];
    }
    __syncthreads();
    float kreg[HD];
    const float* kr = kpool + ((long)b*HP2 + tid)*CH + h*HD;
    #pragma unroll
    for (int d = 0; d < HD; d++) kreg[d] = kr[d];
    #pragma unroll
    for (int q = 0; q < NQ; q++) {
        float s = 0.f;
        #pragma unroll
        for (int d = 0; d < HD; d++) s = fmaf(qs[q][d], kreg[d], s);
        lg[q][tid] = s * SCALE;
    }
    __syncthreads();
    int w = tid >> 5, lane = tid & 31;
    {
        float m = -1e30f;
        for (int j = lane; j < HP2; j += 32) m = fmaxf(m, lg[w][j]);
        #pragma unroll
        for (int o = 16; o; o >>= 1) m = fmaxf(m, __shfl_xor_sync(~0u, m, o));
        float s = 0.f;
        for (int j = lane; j < HP2; j += 32) { float e = __expf(lg[w][j] - m); lg[w][j] = e; s += e; }
        #pragma unroll
        for (int o = 16; o; o >>= 1) s += __shfl_xor_sync(~0u, s, o);
        float inv = 1.f / s;
        for (int j = lane; j < HP2; j += 32) lg[w][j] *= inv;
    }
    __syncthreads();
    int q = tid >> 5, d = tid & 31;
    float acc = 0.f;
    for (int kk = 0; kk < HP2; kk++) acc = fmaf(lg[q][kk], vsm[kk][d], acc);
    qin[(b*NQ + q)*CH + h*HD + d] = acc + qtok[q*CH + h*HD + d];
}

// ---------------- window attention (tensor-core, tf32) -----------------
__global__ void __launch_bounds__(256)
window_attn_kernel(const float* __restrict__ qkv,
                   const float* __restrict__ gk,
                   const float* __restrict__ gv,
                   const float* __restrict__ rpb,
                   float* __restrict__ attn_out,
                   __half* __restrict__ attouth) {
    int h   = blockIdx.x & 7;
    int win = blockIdx.x >> 3;
    int wx = win & 7, wy = (win >> 3) & 7, b = win >> 6;
    int n_base = (wy*WS)*GRIDW + wx*WS;

    __shared__ float qs[64][36];
    __shared__ float ks[80][36];
    __shared__ float vt[32][84];
    __shared__ float lg[64][84];

    int tid = threadIdx.x;
    int warp = tid >> 5, lane = tid & 31;
    int g = lane >> 2, tg = lane & 3;

    for (int idx = tid; idx < 64*32; idx += 256) {
        int i = idx >> 5, d = idx & 31;
        int n = n_base + (i >> 3)*GRIDW + (i & 7);
        qs[i][d] = qkv[((long)b*NTOK + n)*(3*CH) + h*HD + d] * SCALE;
    }
    for (int idx = tid; idx < 80*32; idx += 256) {
        int j = idx >> 5, d = idx & 31;
        float kv = 0.f, vv = 0.f;
        if (j < 64) {
            int n = n_base + (j >> 3)*GRIDW + (j & 7);
            long base = ((long)b*NTOK + n)*(3*CH) + h*HD + d;
            kv = qkv[base + CH];
            vv = qkv[base + 2*CH];
        } else if (j < 72) {
            int nq = j - 64;
            kv = gk[(b*NQ + nq)*CH + h*HD + d];
            vv = gv[(b*NQ + nq)*CH + h*HD + d];
        }
        ks[j][d] = kv;
        vt[d][j] = vv;
    }
    __syncthreads();

    {
        int mw = (warp >> 1)*16, np = (warp & 1)*40;
        float acc[5][4] = {};
        #pragma unroll
        for (int kt = 0; kt < 4; kt++) {
            int k0 = kt*8;
            unsigned a[4];
            a[0] = __float_as_uint(qs[mw+g][k0+tg]);
            a[1] = __float_as_uint(qs[mw+g+8][k0+tg]);
            a[2] = __float_as_uint(qs[mw+g][k0+tg+4]);
            a[3] = __float_as_uint(qs[mw+g+8][k0+tg+4]);
            #pragma unroll
            for (int nt = 0; nt < 5; nt++) {
                int nb = np + nt*8 + g;
                unsigned bb[2];
                bb[0] = __float_as_uint(ks[nb][k0+tg]);
                bb[1] = __float_as_uint(ks[nb][k0+tg+4]);
                mma_tf32(acc[nt], a, bb);
            }
        }
        #pragma unroll
        for (int nt = 0; nt < 5; nt++) {
            #pragma unroll
            for (int c = 0; c < 4; c++) {
                int i = mw + g + (c >> 1)*8;
                int j = np + nt*8 + tg*2 + (c & 1);
                float s = acc[nt][c];
                if (j < 64) {
                    int diy = (i >> 3) - (j >> 3) + 7;
                    int dix = (i & 7) - (j & 7) + 7;
                    s += rpb[(diy*15 + dix)*HEADS + h];
                }
                lg[i][j] = s;
            }
        }
    }
    __syncthreads();

    for (int it = 0; it < 8; it++) {
        int i = it*8 + warp;
        float m = -1e30f;
        for (int j = lane; j < KVLEN; j += 32) m = fmaxf(m, lg[i][j]);
        #pragma unroll
        for (int o = 16; o; o >>= 1) m = fmaxf(m, __shfl_xor_sync(~0u, m, o));
        float s = 0.f;
        for (int j = lane; j < KVLEN; j += 32) { float e = __expf(lg[i][j] - m); lg[i][j] = e; s += e; }
        #pragma unroll
        for (int o = 16; o; o >>= 1) s += __shfl_xor_sync(~0u, s, o);
        float inv = 1.f / s;
        for (int j = lane; j < KVLEN; j += 32) lg[i][j] *= inv;
    }
    __syncthreads();

    long abase = ((long)(win*HEADS + h))*64*KVLEN;
    for (int idx = tid; idx < 64*KVLEN; idx += 256) {
        int i = idx / KVLEN, j = idx - i*KVLEN;
        attn_out[abase + idx] = lg[i][j];
    }

    {
        int mw = (warp >> 1)*16, nv = (warp & 1)*16;
        float acc[2][4] = {};
        #pragma unroll
        for (int kt = 0; kt < 10; kt++) {
            int k0 = kt*8;
            unsigned a[4];
            a[0] = __float_as_uint(lg[mw+g][k0+tg]);
            a[1] = __float_as_uint(lg[mw+g+8][k0+tg]);
            a[2] = __float_as_uint(lg[mw+g][k0+tg+4]);
            a[3] = __float_as_uint(lg[mw+g+8][k0+tg+4]);
            #pragma unroll
            for (int nt = 0; nt < 2; nt++) {
                int nb = nv + nt*8 + g;
                unsigned bb[2];
                bb[0] = __float_as_uint(vt[nb][k0+tg]);
                bb[1] = __float_as_uint(vt[nb][k0+tg+4]);
                mma_tf32(acc[nt], a, bb);
            }
        }
        #pragma unroll
        for (int nt = 0; nt < 2; nt++) {
            #pragma unroll
            for (int c = 0; c < 4; c++) {
                int i = mw + g + (c >> 1)*8;
                int d = nv + nt*8 + tg*2 + (c & 1);
                int n = n_base + (i >> 3)*GRIDW + (i & 7);
                attouth[((long)b*NTOK + n)*CH + h*HD + d] = __float2half(acc[nt][c]);
            }
        }
    }
}

// ---------------- host launch ------------------------------------------
#define GEMM_SMEM (4*TSTG*2)

extern "C" void kernel_launch(void* const* d_in, const int* in_sizes, int n_in,
                              void* d_out, int out_size) {
    const float* x       = (const float*)d_in[0];
    const float* qtok    = (const float*)d_in[1];
    const float* kproj_w = (const float*)d_in[2];
    const float* kproj_b = (const float*)d_in[3];
    const float* kbn_g   = (const float*)d_in[4];
    const float* kbn_b   = (const float*)d_in[5];
    const float* kbn_m   = (const float*)d_in[6];
    const float* kbn_v   = (const float*)d_in[7];
    const float* vproj_w = (const float*)d_in[8];
    const float* vproj_b = (const float*)d_in[9];
    const float* vbn_g   = (const float*)d_in[10];
    const float* vbn_b   = (const float*)d_in[11];
    const float* vbn_m   = (const float*)d_in[12];
    const float* vbn_v   = (const float*)d_in[13];
    const float* ck_w    = (const float*)d_in[14];
    const float* ck_b    = (const float*)d_in[15];
    const float* cv_w    = (const float*)d_in[16];
    const float* cv_b    = (const float*)d_in[17];
    const float* rpb     = (const float*)d_in[18];
    const float* qkv_w   = (const float*)d_in[19];
    const float* qkv_b   = (const float*)d_in[20];
    const float* proj_w  = (const float*)d_in[21];
    const float* proj_b  = (const float*)d_in[22];
    const float* n1_g    = (const float*)d_in[23];
    const float* n1_b    = (const float*)d_in[24];
    const float* n2_g    = (const float*)d_in[25];
    const float* n2_b    = (const float*)d_in[26];
    const float* fc1_w   = (const float*)d_in[27];
    const float* fc1_b   = (const float*)d_in[28];
    const float* fc2_w   = (const float*)d_in[29];
    const float* fc2_b   = (const float*)d_in[30];

    float* out_x    = (float*)d_out;
    float* out_attn = out_x + (long)BATCH*NTOK*CH;

    float *xn, *pooled, *kpool, *vpool, *qin, *gk, *gv, *qkv, *xnew;
    __half *xnh, *xmh, *attouth, *hh;
    cudaGetSymbolAddress((void**)&xn,      g_xn);
    cudaGetSymbolAddress((void**)&xnh,     g_xnh);
    cudaGetSymbolAddress((void**)&pooled,  g_pooled);
    cudaGetSymbolAddress((void**)&kpool,   g_kpool);
    cudaGetSymbolAddress((void**)&vpool,   g_vpool);
    cudaGetSymbolAddress((void**)&qin,     g_qin);
    cudaGetSymbolAddress((void**)&gk,      g_gk);
    cudaGetSymbolAddress((void**)&gv,      g_gv);
    cudaGetSymbolAddress((void**)&qkv,     g_qkv);
    cudaGetSymbolAddress((void**)&attouth, g_attouth);
    cudaGetSymbolAddress((void**)&xnew,    g_xnew);
    cudaGetSymbolAddress((void**)&xmh,     g_xmh);
    cudaGetSymbolAddress((void**)&hh,      g_hh);

    __half *wqkv, *wfc1, *wfc2, *wproj, *wkp, *wvp, *wck, *wcv;
    cudaGetSymbolAddress((void**)&wqkv,  g_wqkv);
    cudaGetSymbolAddress((void**)&wfc1,  g_wfc1);
    cudaGetSymbolAddress((void**)&wfc2,  g_wfc2);
    cudaGetSymbolAddress((void**)&wproj, g_wproj);
    cudaGetSymbolAddress((void**)&wkp,   g_wkp);
    cudaGetSymbolAddress((void**)&wvp,   g_wvp);
    cudaGetSymbolAddress((void**)&wck,   g_wck);
    cudaGetSymbolAddress((void**)&wcv,   g_wcv);

    static int smem_set = 0;
    if (!smem_set) {
        cudaFuncSetAttribute(mma_gemm<0,0,0>, cudaFuncAttributeMaxDynamicSharedMemorySize, GEMM_SMEM);
        cudaFuncSetAttribute(mma_gemm<1,0,0>, cudaFuncAttributeMaxDynamicSharedMemorySize, GEMM_SMEM);
        cudaFuncSetAttribute(mma_gemm<0,1,0>, cudaFuncAttributeMaxDynamicSharedMemorySize, GEMM_SMEM);
        cudaFuncSetAttribute(mma_gemm<2,1,1>, cudaFuncAttributeMaxDynamicSharedMemorySize, GEMM_SMEM);
        cudaFuncSetAttribute(mma_gemm<3,1,0>, cudaFuncAttributeMaxDynamicSharedMemorySize, GEMM_SMEM);
        smem_set = 1;
    }

    const int M = BATCH*NTOK;   // 65536

    // merged weight conversion (one launch)
    WC wc;
    wc.s[0]=qkv_w;  wc.d[0]=wqkv;  wc.n4[0]=49152;
    wc.s[1]=fc1_w;  wc.d[1]=wfc1;  wc.n4[1]=65536;
    wc.s[2]=fc2_w;  wc.d[2]=wfc2;  wc.n4[2]=65536;
    wc.s[3]=proj_w; wc.d[3]=wproj; wc.n4[3]=16384;
    wc.s[4]=kproj_w;wc.d[4]=wkp;   wc.n4[4]=16384;
    wc.s[5]=vproj_w;wc.d[5]=wvp;   wc.n4[5]=16384;
    wc.s[6]=ck_w;   wc.d[6]=wck;   wc.n4[6]=16384;
    wc.s[7]=cv_w;   wc.d[7]=wcv;   wc.n4[7]=16384;
    wconv_all<<<dim3(256, 8), 256>>>(wc);

    // LN1: fp32 (for pool) + fp16 (for qkv GEMM)
    layernorm_kernel<2><<<M/8, 256>>>(x, n1_g, n1_b, xn, xnh);
    pool_kernel<<<BATCH*HP2, 256>>>(xn, pooled);

    GP kp = {wkp, kproj_b, kpool, 0, kbn_m, kbn_v, kbn_g, kbn_b};
    GP vp = {wvp, vproj_b, vpool, 0, vbn_m, vbn_v, vbn_g, vbn_b};
    mma_gemm<1,0,0><<<dim3(2, 32, 2), 256, GEMM_SMEM>>>(pooled, BATCH*HP2, CH, CH, kp, vp);

    global_attn_kernel<<<BATCH*HEADS, 256>>>(kpool, vpool, qtok, qin);

    GP ckp = {wck, ck_b, gk, 0, 0, 0, 0, 0};
    GP cvp = {wcv, cv_b, gv, 0, 0, 0, 0, 0};
    mma_gemm<0,0,0><<<dim3(2, 1, 2), 256, GEMM_SMEM>>>(qin, BATCH*NQ, CH, CH, ckp, cvp);

    GP qkvp = {wqkv, qkv_b, qkv, 0, 0, 0, 0, 0};
    mma_gemm<0,1,0><<<dim3(6, 512, 1), 256, GEMM_SMEM>>>(xnh, M, CH, 3*CH, qkvp, qkvp);

    window_attn_kernel<<<BATCH*NWIN*HEADS, 256>>>(qkv, gk, gv, rpb, out_attn, attouth);

    GP projp = {wproj, proj_b, xnew, 0, x, 0, 0, 0};
    mma_gemm<3,1,0><<<dim3(2, 512, 1), 256, GEMM_SMEM>>>(attouth, M, CH, CH, projp, projp);

    // LN2: fp16 only (consumed by fc1)
    layernorm_kernel<1><<<M/8, 256>>>(xnew, n2_g, n2_b, 0, xmh);

    GP fc1p = {wfc1, fc1_b, 0, hh, 0, 0, 0, 0};
    mma_gemm<2,1,1><<<dim3(8, 512, 1), 256, GEMM_SMEM>>>(xmh, M, CH, 4*CH, fc1p, fc1p);

    GP fc2p = {wfc2, fc2_b, out_x, 0, xnew, 0, 0, 0};
    mma_gemm<3,1,0><<<dim3(2, 512, 1), 256, GEMM_SMEM>>>(hh, M, 4*CH, CH, fc2p, fc2p);
}

// round 11
// speedup vs baseline: 4.3965x; 1.0186x over previous
#include <cuda_runtime.h>
#include <cuda_fp16.h>
#include <math.h>

// ---------------- problem constants ----------------
#define BATCH   16
#define CH      256
#define NTOK    4096
#define GRIDW   64
#define HEADS   8
#define HD      32
#define NQ      8
#define WS      8
#define NWIN    64
#define KVLEN   72
#define HP2     256
#define SCALE   0.17677669529663687f

// ---------------- scratch ----------------
__device__ float  g_xn   [(long)BATCH*NTOK*CH];
__device__ __half g_xnh  [(long)BATCH*NTOK*CH];
__device__ float  g_pooled[(long)BATCH*HP2*CH];
__device__ float  g_kpool [(long)BATCH*HP2*CH];
__device__ float  g_vpool [(long)BATCH*HP2*CH];
__device__ float  g_qin   [BATCH*NQ*CH];
__device__ float  g_gk    [BATCH*NQ*CH];
__device__ float  g_gv    [BATCH*NQ*CH];
__device__ __half g_qkvh [(long)BATCH*NTOK*3*CH];
__device__ __half g_attouth[(long)BATCH*NTOK*CH];
__device__ float  g_xnew [(long)BATCH*NTOK*CH];
__device__ __half g_xmh  [(long)BATCH*NTOK*CH];
__device__ __half g_hh   [(long)BATCH*NTOK*4*CH];

// fp16 weight copies
__device__ __half g_wqkv[768*256];
__device__ __half g_wfc1[1024*256];
__device__ __half g_wfc2[256*1024];
__device__ __half g_wproj[256*256];
__device__ __half g_wkp [256*256];
__device__ __half g_wvp [256*256];
__device__ __half g_wck [256*256];
__device__ __half g_wcv [256*256];

// ---------------- helpers ----------------
__device__ __forceinline__ void mma_f16(float* c, const unsigned* a, const unsigned* b) {
    asm volatile(
        "mma.sync.aligned.m16n8k16.row.col.f32.f16.f16.f32 "
        "{%0,%1,%2,%3}, {%4,%5,%6,%7}, {%8,%9}, {%0,%1,%2,%3};"
        : "+f"(c[0]), "+f"(c[1]), "+f"(c[2]), "+f"(c[3])
        : "r"(a[0]), "r"(a[1]), "r"(a[2]), "r"(a[3]), "r"(b[0]), "r"(b[1]));
}

__device__ __forceinline__ void cp16(void* dst, const void* src) {
    unsigned d = (unsigned)__cvta_generic_to_shared(dst);
    asm volatile("cp.async.cg.shared.global [%0], [%1], 16;" :: "r"(d), "l"(src));
}
__device__ __forceinline__ void cp_commit() {
    asm volatile("cp.async.commit_group;");
}
__device__ __forceinline__ void cp_wait1() {
    asm volatile("cp.async.wait_group 1;");
}

// ---------------- merged weight fp32 -> fp16 conversion ----------------
struct WC { const float* s[8]; __half* d[8]; int n4[8]; };

__global__ void wconv_all(WC wc) {
    int seg = blockIdx.y;
    int i = blockIdx.x*256 + threadIdx.x;
    if (i < wc.n4[seg]) {
        float4 v = ((const float4*)wc.s[seg])[i];
        __half2 a = __floats2half2_rn(v.x, v.y);
        __half2 b = __floats2half2_rn(v.z, v.w);
        uint2 u;
        u.x = *(unsigned*)&a;
        u.y = *(unsigned*)&b;
        ((uint2*)wc.d[seg])[i] = u;
    }
}

// ---------------- layernorm: warp per row, shfl-only -------------------
// MODE 0: fp32 only, 1: half only, 2: both
template<int MODE>
__global__ void layernorm_kernel(const float* __restrict__ x,
                                 const float* __restrict__ g,
                                 const float* __restrict__ b,
                                 float* __restrict__ out,
                                 __half* __restrict__ outh) {
    long row = (long)blockIdx.x*8 + (threadIdx.x >> 5);
    int lane = threadIdx.x & 31;
    const float4* xr = (const float4*)(x + row*CH);
    float4 v0 = xr[lane], v1 = xr[lane + 32];
    float s = v0.x+v0.y+v0.z+v0.w + v1.x+v1.y+v1.z+v1.w;
    #pragma unroll
    for (int o = 16; o; o >>= 1) s += __shfl_xor_sync(~0u, s, o);
    float m = s * (1.f/CH);
    float d0x=v0.x-m, d0y=v0.y-m, d0z=v0.z-m, d0w=v0.w-m;
    float d1x=v1.x-m, d1y=v1.y-m, d1z=v1.z-m, d1w=v1.w-m;
    float q = d0x*d0x+d0y*d0y+d0z*d0z+d0w*d0w + d1x*d1x+d1y*d1y+d1z*d1z+d1w*d1w;
    #pragma unroll
    for (int o = 16; o; o >>= 1) q += __shfl_xor_sync(~0u, q, o);
    float r = rsqrtf(q * (1.f/CH) + 1e-5f);
    const float4* gr = (const float4*)g;
    const float4* br = (const float4*)b;
    float4 g0 = gr[lane], g1 = gr[lane+32], b0 = br[lane], b1 = br[lane+32];
    float4 o0, o1;
    o0.x = d0x*r*g0.x + b0.x; o0.y = d0y*r*g0.y + b0.y;
    o0.z = d0z*r*g0.z + b0.z; o0.w = d0w*r*g0.w + b0.w;
    o1.x = d1x*r*g1.x + b1.x; o1.y = d1y*r*g1.y + b1.y;
    o1.z = d1z*r*g1.z + b1.z; o1.w = d1w*r*g1.w + b1.w;
    if (MODE != 1) {
        float4* orow = (float4*)(out + row*CH);
        orow[lane] = o0; orow[lane+32] = o1;
    }
    if (MODE != 0) {
        __half2 h0 = __floats2half2_rn(o0.x, o0.y);
        __half2 h1 = __floats2half2_rn(o0.z, o0.w);
        __half2 h2 = __floats2half2_rn(o1.x, o1.y);
        __half2 h3 = __floats2half2_rn(o1.z, o1.w);
        uint2 u0, u1;
        u0.x = *(unsigned*)&h0; u0.y = *(unsigned*)&h1;
        u1.x = *(unsigned*)&h2; u1.y = *(unsigned*)&h3;
        uint2* hrow = (uint2*)(outh + row*CH);
        hrow[lane] = u0; hrow[lane+32] = u1;
    }
}

// ---------------- 4x4 avg pool ----------------
__global__ void pool_kernel(const float* __restrict__ xn, float* __restrict__ pooled) {
    int bidx = blockIdx.x;
    int b = bidx >> 8, hw = bidx & 255;
    int py = hw >> 4, px = hw & 15;
    int c = threadIdx.x;
    float s = 0.f;
    #pragma unroll
    for (int dy = 0; dy < 4; dy++)
        #pragma unroll
        for (int dx = 0; dx < 4; dx++) {
            int n = (py*4 + dy)*GRIDW + px*4 + dx;
            s += xn[((long)b*NTOK + n)*CH + c];
        }
    pooled[(long)bidx*CH + c] = s * (1.f/16.f);
}

// ---------------- fp16 double-buffered GEMM (mma.sync m16n8k16) --------
#define PADH 40
#define TSTG (128*PADH)

struct GP {
    const __half* W; const float* bias; float* out; __half* outh;
    const float* e0; const float* e1; const float* e2; const float* e3;
};

template<int EPI, int AH, int OH>
__global__ void __launch_bounds__(256, 2)
mma_gemm(const void* Av, int M, int K, int O, GP p0, GP p1) {
    extern __shared__ __half hsm[];
    __half* Ah = hsm;              // [2][128][PADH]
    __half* Bh = hsm + 2*TSTG;     // [2][128][PADH]

    const GP* P = blockIdx.z ? &p1 : &p0;
    const __half* __restrict__ W = P->W;

    int tid  = threadIdx.x;
    int warp = tid >> 5, lane = tid & 31;
    int wm = warp >> 2, wn = warp & 3;
    int m_warp = wm * 64, n_warp = wn * 32;
    int g = lane >> 2, tg = lane & 3;

    int m0 = blockIdx.y * 128;
    int o0 = blockIdx.x * 128;

    int br_ = tid >> 2;
    int bg = tid & 3;

    float acc[4][4][4] = {};
    int NC = K >> 5;

    if (AH) {
        const __half* Agh = (const __half*)Av;
        #pragma unroll
        for (int i = 0; i < 2; i++) {
            int row = br_ + i*64;
            cp16(Ah + row*PADH + bg*8, Agh + (long)(m0 + row)*K + bg*8);
            cp16(Bh + row*PADH + bg*8, W + (long)(o0 + row)*K + bg*8);
        }
        cp_commit();
        for (int c = 0; c < NC; c++) {
            int s = c & 1;
            if (c + 1 < NC) {
                int ns = s ^ 1;
                #pragma unroll
                for (int i = 0; i < 2; i++) {
                    int row = br_ + i*64;
                    cp16(Ah + ns*TSTG + row*PADH + bg*8,
                         Agh + (long)(m0 + row)*K + (c+1)*32 + bg*8);
                    cp16(Bh + ns*TSTG + row*PADH + bg*8,
                         W + (long)(o0 + row)*K + (c+1)*32 + bg*8);
                }
            }
            cp_commit();
            cp_wait1();
            __syncthreads();
            const __half* Ab = Ah + s*TSTG;
            const __half* Bb = Bh + s*TSTG;
            #pragma unroll
            for (int kt = 0; kt < 2; kt++) {
                int k0 = kt*16;
                unsigned af[4][4], bf[4][2];
                #pragma unroll
                for (int mt = 0; mt < 4; mt++) {
                    int mb = m_warp + mt*16 + g;
                    af[mt][0] = *(const unsigned*)(Ab + mb*PADH + k0 + tg*2);
                    af[mt][1] = *(const unsigned*)(Ab + (mb+8)*PADH + k0 + tg*2);
                    af[mt][2] = *(const unsigned*)(Ab + mb*PADH + k0 + tg*2 + 8);
                    af[mt][3] = *(const unsigned*)(Ab + (mb+8)*PADH + k0 + tg*2 + 8);
                }
                #pragma unroll
                for (int nt = 0; nt < 4; nt++) {
                    int nb = n_warp + nt*8 + g;
                    bf[nt][0] = *(const unsigned*)(Bb + nb*PADH + k0 + tg*2);
                    bf[nt][1] = *(const unsigned*)(Bb + nb*PADH + k0 + tg*2 + 8);
                }
                #pragma unroll
                for (int mt = 0; mt < 4; mt++)
                    #pragma unroll
                    for (int nt = 0; nt < 4; nt++)
                        mma_f16(acc[mt][nt], af[mt], bf[nt]);
            }
            __syncthreads();
        }
    } else {
        const float* A = (const float*)Av;
        int lr = tid >> 3;
        int lc4 = tid & 7;
        float4 pa[4];
        #pragma unroll
        for (int i = 0; i < 4; i++)
            pa[i] = *(const float4*)(A + (long)(m0 + lr + i*32)*K + lc4*4);
        #pragma unroll
        for (int i = 0; i < 2; i++) {
            int row = br_ + i*64;
            cp16((char*)(Bh + row*PADH) + bg*16, W + (long)(o0 + row)*K + bg*8);
        }
        cp_commit();

        for (int c = 0; c < NC; c++) {
            int s = c & 1;
            {
                __half* Ad = Ah + s*TSTG;
                #pragma unroll
                for (int i = 0; i < 4; i++) {
                    __half2 h01 = __floats2half2_rn(pa[i].x, pa[i].y);
                    __half2 h23 = __floats2half2_rn(pa[i].z, pa[i].w);
                    uint2 u;
                    u.x = *(unsigned*)&h01;
                    u.y = *(unsigned*)&h23;
                    *(uint2*)(Ad + (lr + i*32)*PADH + lc4*4) = u;
                }
            }
            if (c + 1 < NC) {
                __half* Bd = Bh + (s^1)*TSTG;
                #pragma unroll
                for (int i = 0; i < 2; i++) {
                    int row = br_ + i*64;
                    cp16((char*)(Bd + row*PADH) + bg*16,
                         W + (long)(o0 + row)*K + (c+1)*32 + bg*8);
                }
            }
            cp_commit();
            cp_wait1();
            __syncthreads();
            if (c + 1 < NC) {
                #pragma unroll
                for (int i = 0; i < 4; i++)
                    pa[i] = *(const float4*)(A + (long)(m0 + lr + i*32)*K + (c+1)*32 + lc4*4);
            }
            const __half* Ab = Ah + s*TSTG;
            const __half* Bb = Bh + s*TSTG;
            #pragma unroll
            for (int kt = 0; kt < 2; kt++) {
                int k0 = kt*16;
                unsigned af[4][4], bf[4][2];
                #pragma unroll
                for (int mt = 0; mt < 4; mt++) {
                    int mb = m_warp + mt*16 + g;
                    af[mt][0] = *(const unsigned*)(Ab + mb*PADH + k0 + tg*2);
                    af[mt][1] = *(const unsigned*)(Ab + (mb+8)*PADH + k0 + tg*2);
                    af[mt][2] = *(const unsigned*)(Ab + mb*PADH + k0 + tg*2 + 8);
                    af[mt][3] = *(const unsigned*)(Ab + (mb+8)*PADH + k0 + tg*2 + 8);
                }
                #pragma unroll
                for (int nt = 0; nt < 4; nt++) {
                    int nb = n_warp + nt*8 + g;
                    bf[nt][0] = *(const unsigned*)(Bb + nb*PADH + k0 + tg*2);
                    bf[nt][1] = *(const unsigned*)(Bb + nb*PADH + k0 + tg*2 + 8);
                }
                #pragma unroll
                for (int mt = 0; mt < 4; mt++)
                    #pragma unroll
                    for (int nt = 0; nt < 4; nt++)
                        mma_f16(acc[mt][nt], af[mt], bf[nt]);
            }
            __syncthreads();
        }
    }

    const float* __restrict__ bias = P->bias;
    float* __restrict__ out = P->out;
    __half* __restrict__ outh = P->outh;
    const float* e0 = P->e0;
    const float* e1 = P->e1;
    const float* e2 = P->e2;
    const float* e3 = P->e3;

    #pragma unroll
    for (int mt = 0; mt < 4; mt++) {
        #pragma unroll
        for (int nt = 0; nt < 4; nt++) {
            #pragma unroll
            for (int c2 = 0; c2 < 2; c2++) {
                int m = m0 + m_warp + mt*16 + g + c2*8;
                int o = o0 + n_warp + nt*8 + tg*2;
                float y0 = acc[mt][nt][c2*2+0] + bias[o];
                float y1 = acc[mt][nt][c2*2+1] + bias[o+1];
                if (EPI == 1) {
                    y0 = (y0 - e0[o])   * rsqrtf(e1[o]   + 1e-5f) * e2[o]   + e3[o];
                    y1 = (y1 - e0[o+1]) * rsqrtf(e1[o+1] + 1e-5f) * e2[o+1] + e3[o+1];
                } else if (EPI == 2) {
                    y0 = 0.5f*y0*(1.f + erff(y0*0.70710678118654752f));
                    y1 = 0.5f*y1*(1.f + erff(y1*0.70710678118654752f));
                } else if (EPI == 3) {
                    float2 rv = *(const float2*)(e0 + (long)m*O + o);
                    y0 += rv.x; y1 += rv.y;
                }
                if (OH) {
                    __half2 hv = __floats2half2_rn(y0, y1);
                    *(__half2*)(outh + (long)m*O + o) = hv;
                } else {
                    float2 v; v.x = y0; v.y = y1;
                    *(float2*)(out + (long)m*O + o) = v;
                }
            }
        }
    }
}

// ---------------- global cross-attention pooling path -----------------
__global__ void global_attn_kernel(const float* __restrict__ kpool,
                                   const float* __restrict__ vpool,
                                   const float* __restrict__ qtok,
                                   float* __restrict__ qin) {
    int b = blockIdx.x >> 3, h = blockIdx.x & 7;
    __shared__ float qs[NQ][HD];
    __shared__ float lg[NQ][HP2];
    __shared__ float vsm[HP2][HD];
    int tid = threadIdx.x;
    { int q = tid >> 5, d = tid & 31; qs[q][d] = qtok[q*CH + h*HD + d]; }
    for (int idx = tid; idx < HP2*HD; idx += 256) {
        int r = idx >> 5, d = idx & 31;
        vsm[r][d] = vpool[((long)b*HP2 + r)*CH + h*HD + d];
    }
    __syncthreads();
    float kreg[HD];
    const float* kr = kpool + ((long)b*HP2 + tid)*CH + h*HD;
    #pragma unroll
    for (int d = 0; d < HD; d++) kreg[d] = kr[d];
    #pragma unroll
    for (int q = 0; q < NQ; q++) {
        float s = 0.f;
        #pragma unroll
        for (int d = 0; d < HD; d++) s = fmaf(qs[q][d], kreg[d], s);
        lg[q][tid] = s * SCALE;
    }
    __syncthreads();
    int w = tid >> 5, lane = tid & 31;
    {
        float m = -1e30f;
        for (int j = lane; j < HP2; j += 32) m = fmaxf(m, lg[w][j]);
        #pragma unroll
        for (int o = 16; o; o >>= 1) m = fmaxf(m, __shfl_xor_sync(~0u, m, o));
        float s = 0.f;
        for (int j = lane; j < HP2; j += 32) { float e = __expf(lg[w][j] - m); lg[w][j] = e; s += e; }
        #pragma unroll
        for (int o = 16; o; o >>= 1) s += __shfl_xor_sync(~0u, s, o);
        float inv = 1.f / s;
        for (int j = lane; j < HP2; j += 32) lg[w][j] *= inv;
    }
    __syncthreads();
    int q = tid >> 5, d = tid & 31;
    float acc = 0.f;
    for (int kk = 0; kk < HP2; kk++) acc = fmaf(lg[q][kk], vsm[kk][d], acc);
    qin[(b*NQ + q)*CH + h*HD + d] = acc + qtok[q*CH + h*HD + d];
}

// ---------------- window attention (fp16 tensor-core) ------------------
// S = QK^T fp16 mma (KV padded 72->80 zeros), fp32 softmax+bias+attn out,
// AV fp16 mma with P half. Smem pads: 40/88 halves -> conflict-free frags.
#define PADQ 40
#define PADP 88

__global__ void __launch_bounds__(256)
window_attn_kernel(const __half* __restrict__ qkvh,
                   const float* __restrict__ gk,
                   const float* __restrict__ gv,
                   const float* __restrict__ rpb,
                   float* __restrict__ attn_out,
                   __half* __restrict__ attouth) {
    int h   = blockIdx.x & 7;
    int win = blockIdx.x >> 3;
    int wx = win & 7, wy = (win >> 3) & 7, b = win >> 6;
    int n_base = (wy*WS)*GRIDW + wx*WS;

    __shared__ __half qs[64][PADQ];
    __shared__ __half ks[80][PADQ];
    __shared__ __half vt[32][PADP];
    __shared__ __half ph[64][PADP];
    __shared__ float  lg[64][80];

    int tid = threadIdx.x;
    int warp = tid >> 5, lane = tid & 31;
    int g = lane >> 2, tg = lane & 3;

    // ---- load Q (scaled), K (72 + 8 zero pad), V transposed ----
    for (int idx = tid; idx < 64*32; idx += 256) {
        int i = idx >> 5, d = idx & 31;
        int n = n_base + (i >> 3)*GRIDW + (i & 7);
        float qv = __half2float(qkvh[((long)b*NTOK + n)*(3*CH) + h*HD + d]);
        qs[i][d] = __float2half(qv * SCALE);
    }
    for (int idx = tid; idx < 80*32; idx += 256) {
        int j = idx >> 5, d = idx & 31;
        float kv = 0.f, vv = 0.f;
        if (j < 64) {
            int n = n_base + (j >> 3)*GRIDW + (j & 7);
            long base = ((long)b*NTOK + n)*(3*CH) + h*HD + d;
            kv = __half2float(qkvh[base + CH]);
            vv = __half2float(qkvh[base + 2*CH]);
        } else if (j < 72) {
            int nq = j - 64;
            kv = gk[(b*NQ + nq)*CH + h*HD + d];
            vv = gv[(b*NQ + nq)*CH + h*HD + d];
        }
        ks[j][d] = __float2half(kv);
        vt[d][j] = __float2half(vv);
    }
    // zero P pad columns 72..79
    for (int idx = tid; idx < 64*8; idx += 256) {
        int i = idx >> 3, jj = idx & 7;
        ph[i][72 + jj] = __float2half(0.f);
    }
    __syncthreads();

    // ---- S = Q K^T : warp = 16 rows x 40 cols ----
    {
        int mw = (warp >> 1)*16, np = (warp & 1)*40;
        float acc[5][4] = {};
        #pragma unroll
        for (int kt = 0; kt < 2; kt++) {
            int k0 = kt*16;
            unsigned a[4];
            a[0] = *(const unsigned*)(&qs[mw+g][k0 + tg*2]);
            a[1] = *(const unsigned*)(&qs[mw+g+8][k0 + tg*2]);
            a[2] = *(const unsigned*)(&qs[mw+g][k0 + tg*2 + 8]);
            a[3] = *(const unsigned*)(&qs[mw+g+8][k0 + tg*2 + 8]);
            #pragma unroll
            for (int nt = 0; nt < 5; nt++) {
                int nb = np + nt*8 + g;
                unsigned bb[2];
                bb[0] = *(const unsigned*)(&ks[nb][k0 + tg*2]);
                bb[1] = *(const unsigned*)(&ks[nb][k0 + tg*2 + 8]);
                mma_f16(acc[nt], a, bb);
            }
        }
        #pragma unroll
        for (int nt = 0; nt < 5; nt++) {
            #pragma unroll
            for (int c = 0; c < 4; c++) {
                int i = mw + g + (c >> 1)*8;
                int j = np + nt*8 + tg*2 + (c & 1);
                float s = acc[nt][c];
                if (j < 64) {
                    int diy = (i >> 3) - (j >> 3) + 7;
                    int dix = (i & 7) - (j & 7) + 7;
                    s += rpb[(diy*15 + dix)*HEADS + h];
                }
                lg[i][j] = s;
            }
        }
    }
    __syncthreads();

    // ---- fp32 softmax over j<72 ----
    for (int it = 0; it < 8; it++) {
        int i = it*8 + warp;
        float m = -1e30f;
        for (int j = lane; j < KVLEN; j += 32) m = fmaxf(m, lg[i][j]);
        #pragma unroll
        for (int o = 16; o; o >>= 1) m = fmaxf(m, __shfl_xor_sync(~0u, m, o));
        float s = 0.f;
        for (int j = lane; j < KVLEN; j += 32) { float e = __expf(lg[i][j] - m); lg[i][j] = e; s += e; }
        #pragma unroll
        for (int o = 16; o; o >>= 1) s += __shfl_xor_sync(~0u, s, o);
        float inv = 1.f / s;
        for (int j = lane; j < KVLEN; j += 32) lg[i][j] *= inv;
    }
    __syncthreads();

    // ---- emit attention probabilities (fp32) + fill P half ----
    long abase = ((long)(win*HEADS + h))*64*KVLEN;
    for (int idx = tid; idx < 64*KVLEN; idx += 256) {
        int i = idx / KVLEN, j = idx - i*KVLEN;
        float p = lg[i][j];
        attn_out[abase + idx] = p;
        ph[i][j] = __float2half(p);
    }
    __syncthreads();

    // ---- AV fp16 : warp = 16 rows x 16 d ----
    {
        int mw = (warp >> 1)*16, nv = (warp & 1)*16;
        float acc[2][4] = {};
        #pragma unroll
        for (int kt = 0; kt < 5; kt++) {
            int k0 = kt*16;
            unsigned a[4];
            a[0] = *(const unsigned*)(&ph[mw+g][k0 + tg*2]);
            a[1] = *(const unsigned*)(&ph[mw+g+8][k0 + tg*2]);
            a[2] = *(const unsigned*)(&ph[mw+g][k0 + tg*2 + 8]);
            a[3] = *(const unsigned*)(&ph[mw+g+8][k0 + tg*2 + 8]);
            #pragma unroll
            for (int nt = 0; nt < 2; nt++) {
                int nb = nv + nt*8 + g;
                unsigned bb[2];
                bb[0] = *(const unsigned*)(&vt[nb][k0 + tg*2]);
                bb[1] = *(const unsigned*)(&vt[nb][k0 + tg*2 + 8]);
                mma_f16(acc[nt], a, bb);
            }
        }
        #pragma unroll
        for (int nt = 0; nt < 2; nt++) {
            #pragma unroll
            for (int c = 0; c < 4; c++) {
                int i = mw + g + (c >> 1)*8;
                int d = nv + nt*8 + tg*2 + (c & 1);
                int n = n_base + (i >> 3)*GRIDW + (i & 7);
                attouth[((long)b*NTOK + n)*CH + h*HD + d] = __float2half(acc[nt][c]);
            }
        }
    }
}

// ---------------- host launch ------------------------------------------
#define GEMM_SMEM (4*TSTG*2)

extern "C" void kernel_launch(void* const* d_in, const int* in_sizes, int n_in,
                              void* d_out, int out_size) {
    const float* x       = (const float*)d_in[0];
    const float* qtok    = (const float*)d_in[1];
    const float* kproj_w = (const float*)d_in[2];
    const float* kproj_b = (const float*)d_in[3];
    const float* kbn_g   = (const float*)d_in[4];
    const float* kbn_b   = (const float*)d_in[5];
    const float* kbn_m   = (const float*)d_in[6];
    const float* kbn_v   = (const float*)d_in[7];
    const float* vproj_w = (const float*)d_in[8];
    const float* vproj_b = (const float*)d_in[9];
    const float* vbn_g   = (const float*)d_in[10];
    const float* vbn_b   = (const float*)d_in[11];
    const float* vbn_m   = (const float*)d_in[12];
    const float* vbn_v   = (const float*)d_in[13];
    const float* ck_w    = (const float*)d_in[14];
    const float* ck_b    = (const float*)d_in[15];
    const float* cv_w    = (const float*)d_in[16];
    const float* cv_b    = (const float*)d_in[17];
    const float* rpb     = (const float*)d_in[18];
    const float* qkv_w   = (const float*)d_in[19];
    const float* qkv_b   = (const float*)d_in[20];
    const float* proj_w  = (const float*)d_in[21];
    const float* proj_b  = (const float*)d_in[22];
    const float* n1_g    = (const float*)d_in[23];
    const float* n1_b    = (const float*)d_in[24];
    const float* n2_g    = (const float*)d_in[25];
    const float* n2_b    = (const float*)d_in[26];
    const float* fc1_w   = (const float*)d_in[27];
    const float* fc1_b   = (const float*)d_in[28];
    const float* fc2_w   = (const float*)d_in[29];
    const float* fc2_b   = (const float*)d_in[30];

    float* out_x    = (float*)d_out;
    float* out_attn = out_x + (long)BATCH*NTOK*CH;

    float *xn, *pooled, *kpool, *vpool, *qin, *gk, *gv, *xnew;
    __half *xnh, *xmh, *attouth, *hh, *qkvh;
    cudaGetSymbolAddress((void**)&xn,      g_xn);
    cudaGetSymbolAddress((void**)&xnh,     g_xnh);
    cudaGetSymbolAddress((void**)&pooled,  g_pooled);
    cudaGetSymbolAddress((void**)&kpool,   g_kpool);
    cudaGetSymbolAddress((void**)&vpool,   g_vpool);
    cudaGetSymbolAddress((void**)&qin,     g_qin);
    cudaGetSymbolAddress((void**)&gk,      g_gk);
    cudaGetSymbolAddress((void**)&gv,      g_gv);
    cudaGetSymbolAddress((void**)&qkvh,    g_qkvh);
    cudaGetSymbolAddress((void**)&attouth, g_attouth);
    cudaGetSymbolAddress((void**)&xnew,    g_xnew);
    cudaGetSymbolAddress((void**)&xmh,     g_xmh);
    cudaGetSymbolAddress((void**)&hh,      g_hh);

    __half *wqkv, *wfc1, *wfc2, *wproj, *wkp, *wvp, *wck, *wcv;
    cudaGetSymbolAddress((void**)&wqkv,  g_wqkv);
    cudaGetSymbolAddress((void**)&wfc1,  g_wfc1);
    cudaGetSymbolAddress((void**)&wfc2,  g_wfc2);
    cudaGetSymbolAddress((void**)&wproj, g_wproj);
    cudaGetSymbolAddress((void**)&wkp,   g_wkp);
    cudaGetSymbolAddress((void**)&wvp,   g_wvp);
    cudaGetSymbolAddress((void**)&wck,   g_wck);
    cudaGetSymbolAddress((void**)&wcv,   g_wcv);

    static int smem_set = 0;
    if (!smem_set) {
        cudaFuncSetAttribute(mma_gemm<0,0,0>, cudaFuncAttributeMaxDynamicSharedMemorySize, GEMM_SMEM);
        cudaFuncSetAttribute(mma_gemm<1,0,0>, cudaFuncAttributeMaxDynamicSharedMemorySize, GEMM_SMEM);
        cudaFuncSetAttribute(mma_gemm<0,1,1>, cudaFuncAttributeMaxDynamicSharedMemorySize, GEMM_SMEM);
        cudaFuncSetAttribute(mma_gemm<2,1,1>, cudaFuncAttributeMaxDynamicSharedMemorySize, GEMM_SMEM);
        cudaFuncSetAttribute(mma_gemm<3,1,0>, cudaFuncAttributeMaxDynamicSharedMemorySize, GEMM_SMEM);
        smem_set = 1;
    }

    const int M = BATCH*NTOK;   // 65536

    // merged weight conversion (one launch)
    WC wc;
    wc.s[0]=qkv_w;  wc.d[0]=wqkv;  wc.n4[0]=49152;
    wc.s[1]=fc1_w;  wc.d[1]=wfc1;  wc.n4[1]=65536;
    wc.s[2]=fc2_w;  wc.d[2]=wfc2;  wc.n4[2]=65536;
    wc.s[3]=proj_w; wc.d[3]=wproj; wc.n4[3]=16384;
    wc.s[4]=kproj_w;wc.d[4]=wkp;   wc.n4[4]=16384;
    wc.s[5]=vproj_w;wc.d[5]=wvp;   wc.n4[5]=16384;
    wc.s[6]=ck_w;   wc.d[6]=wck;   wc.n4[6]=16384;
    wc.s[7]=cv_w;   wc.d[7]=wcv;   wc.n4[7]=16384;
    wconv_all<<<dim3(256, 8), 256>>>(wc);

    // LN1: fp32 (for pool) + fp16 (for qkv GEMM)
    layernorm_kernel<2><<<M/8, 256>>>(x, n1_g, n1_b, xn, xnh);
    pool_kernel<<<BATCH*HP2, 256>>>(xn, pooled);

    GP kp = {wkp, kproj_b, kpool, 0, kbn_m, kbn_v, kbn_g, kbn_b};
    GP vp = {wvp, vproj_b, vpool, 0, vbn_m, vbn_v, vbn_g, vbn_b};
    mma_gemm<1,0,0><<<dim3(2, 32, 2), 256, GEMM_SMEM>>>(pooled, BATCH*HP2, CH, CH, kp, vp);

    global_attn_kernel<<<BATCH*HEADS, 256>>>(kpool, vpool, qtok, qin);

    GP ckp = {wck, ck_b, gk, 0, 0, 0, 0, 0};
    GP cvp = {wcv, cv_b, gv, 0, 0, 0, 0, 0};
    mma_gemm<0,0,0><<<dim3(2, 1, 2), 256, GEMM_SMEM>>>(qin, BATCH*NQ, CH, CH, ckp, cvp);

    // qkv projection -> fp16 buffer
    GP qkvp = {wqkv, qkv_b, 0, qkvh, 0, 0, 0, 0};
    mma_gemm<0,1,1><<<dim3(6, 512, 1), 256, GEMM_SMEM>>>(xnh, M, CH, 3*CH, qkvp, qkvp);

    window_attn_kernel<<<BATCH*NWIN*HEADS, 256>>>(qkvh, gk, gv, rpb, out_attn, attouth);

    GP projp = {wproj, proj_b, xnew, 0, x, 0, 0, 0};
    mma_gemm<3,1,0><<<dim3(2, 512, 1), 256, GEMM_SMEM>>>(attouth, M, CH, CH, projp, projp);

    // LN2: fp16 only (consumed by fc1)
    layernorm_kernel<1><<<M/8, 256>>>(xnew, n2_g, n2_b, 0, xmh);

    GP fc1p = {wfc1, fc1_b, 0, hh, 0, 0, 0, 0};
    mma_gemm<2,1,1><<<dim3(8, 512, 1), 256, GEMM_SMEM>>>(xmh, M, CH, 4*CH, fc1p, fc1p);

    GP fc2p = {wfc2, fc2_b, out_x, 0, xnew, 0, 0, 0};
    mma_gemm<3,1,0><<<dim3(2, 512, 1), 256, GEMM_SMEM>>>(hh, M, 4*CH, CH, fc2p, fc2p);
}

// round 12
// speedup vs baseline: 4.4870x; 1.0206x over previous
#include <cuda_runtime.h>
#include <cuda_fp16.h>
#include <math.h>

// ---------------- problem constants ----------------
#define BATCH   16
#define CH      256
#define NTOK    4096
#define GRIDW   64
#define HEADS   8
#define HD      32
#define NQ      8
#define WS      8
#define NWIN    64
#define KVLEN   72
#define HP2     256
#define SCALE   0.17677669529663687f

// ---------------- scratch ----------------
__device__ float  g_xn   [(long)BATCH*NTOK*CH];
__device__ __half g_xnh  [(long)BATCH*NTOK*CH];
__device__ float  g_pooled[(long)BATCH*HP2*CH];
__device__ float  g_kpool [(long)BATCH*HP2*CH];
__device__ float  g_vpool [(long)BATCH*HP2*CH];
__device__ float  g_qin   [BATCH*NQ*CH];
__device__ float  g_gk    [BATCH*NQ*CH];
__device__ float  g_gv    [BATCH*NQ*CH];
__device__ __half g_qkvh [(long)BATCH*NTOK*3*CH];
__device__ __half g_attouth[(long)BATCH*NTOK*CH];
__device__ float  g_xnew [(long)BATCH*NTOK*CH];
__device__ __half g_xmh  [(long)BATCH*NTOK*CH];
__device__ __half g_hh   [(long)BATCH*NTOK*4*CH];

// fp16 weight copies
__device__ __half g_wqkv[768*256];
__device__ __half g_wfc1[1024*256];
__device__ __half g_wfc2[256*1024];
__device__ __half g_wproj[256*256];
__device__ __half g_wkp [256*256];
__device__ __half g_wvp [256*256];
__device__ __half g_wck [256*256];
__device__ __half g_wcv [256*256];

// ---------------- helpers ----------------
__device__ __forceinline__ void mma_f16(float* c, const unsigned* a, const unsigned* b) {
    asm volatile(
        "mma.sync.aligned.m16n8k16.row.col.f32.f16.f16.f32 "
        "{%0,%1,%2,%3}, {%4,%5,%6,%7}, {%8,%9}, {%0,%1,%2,%3};"
        : "+f"(c[0]), "+f"(c[1]), "+f"(c[2]), "+f"(c[3])
        : "r"(a[0]), "r"(a[1]), "r"(a[2]), "r"(a[3]), "r"(b[0]), "r"(b[1]));
}

__device__ __forceinline__ void ldsm_x4(unsigned* r, const void* p) {
    unsigned a = (unsigned)__cvta_generic_to_shared(p);
    asm volatile("ldmatrix.sync.aligned.m8n8.x4.shared.b16 {%0,%1,%2,%3}, [%4];"
                 : "=r"(r[0]), "=r"(r[1]), "=r"(r[2]), "=r"(r[3]) : "r"(a));
}

__device__ __forceinline__ void cp16(void* dst, const void* src) {
    unsigned d = (unsigned)__cvta_generic_to_shared(dst);
    asm volatile("cp.async.cg.shared.global [%0], [%1], 16;" :: "r"(d), "l"(src));
}
__device__ __forceinline__ void cp_commit() {
    asm volatile("cp.async.commit_group;");
}
__device__ __forceinline__ void cp_wait1() {
    asm volatile("cp.async.wait_group 1;");
}

// ---------------- merged weight fp32 -> fp16 conversion ----------------
struct WC { const float* s[8]; __half* d[8]; int n4[8]; };

__global__ void wconv_all(WC wc) {
    int seg = blockIdx.y;
    int i = blockIdx.x*256 + threadIdx.x;
    if (i < wc.n4[seg]) {
        float4 v = ((const float4*)wc.s[seg])[i];
        __half2 a = __floats2half2_rn(v.x, v.y);
        __half2 b = __floats2half2_rn(v.z, v.w);
        uint2 u;
        u.x = *(unsigned*)&a;
        u.y = *(unsigned*)&b;
        ((uint2*)wc.d[seg])[i] = u;
    }
}

// ---------------- layernorm: warp per row, shfl-only -------------------
// MODE 0: fp32 only, 1: half only, 2: both
template<int MODE>
__global__ void layernorm_kernel(const float* __restrict__ x,
                                 const float* __restrict__ g,
                                 const float* __restrict__ b,
                                 float* __restrict__ out,
                                 __half* __restrict__ outh) {
    long row = (long)blockIdx.x*8 + (threadIdx.x >> 5);
    int lane = threadIdx.x & 31;
    const float4* xr = (const float4*)(x + row*CH);
    float4 v0 = xr[lane], v1 = xr[lane + 32];
    float s = v0.x+v0.y+v0.z+v0.w + v1.x+v1.y+v1.z+v1.w;
    #pragma unroll
    for (int o = 16; o; o >>= 1) s += __shfl_xor_sync(~0u, s, o);
    float m = s * (1.f/CH);
    float d0x=v0.x-m, d0y=v0.y-m, d0z=v0.z-m, d0w=v0.w-m;
    float d1x=v1.x-m, d1y=v1.y-m, d1z=v1.z-m, d1w=v1.w-m;
    float q = d0x*d0x+d0y*d0y+d0z*d0z+d0w*d0w + d1x*d1x+d1y*d1y+d1z*d1z+d1w*d1w;
    #pragma unroll
    for (int o = 16; o; o >>= 1) q += __shfl_xor_sync(~0u, q, o);
    float r = rsqrtf(q * (1.f/CH) + 1e-5f);
    const float4* gr = (const float4*)g;
    const float4* br = (const float4*)b;
    float4 g0 = gr[lane], g1 = gr[lane+32], b0 = br[lane], b1 = br[lane+32];
    float4 o0, o1;
    o0.x = d0x*r*g0.x + b0.x; o0.y = d0y*r*g0.y + b0.y;
    o0.z = d0z*r*g0.z + b0.z; o0.w = d0w*r*g0.w + b0.w;
    o1.x = d1x*r*g1.x + b1.x; o1.y = d1y*r*g1.y + b1.y;
    o1.z = d1z*r*g1.z + b1.z; o1.w = d1w*r*g1.w + b1.w;
    if (MODE != 1) {
        float4* orow = (float4*)(out + row*CH);
        orow[lane] = o0; orow[lane+32] = o1;
    }
    if (MODE != 0) {
        __half2 h0 = __floats2half2_rn(o0.x, o0.y);
        __half2 h1 = __floats2half2_rn(o0.z, o0.w);
        __half2 h2 = __floats2half2_rn(o1.x, o1.y);
        __half2 h3 = __floats2half2_rn(o1.z, o1.w);
        uint2 u0, u1;
        u0.x = *(unsigned*)&h0; u0.y = *(unsigned*)&h1;
        u1.x = *(unsigned*)&h2; u1.y = *(unsigned*)&h3;
        uint2* hrow = (uint2*)(outh + row*CH);
        hrow[lane] = u0; hrow[lane+32] = u1;
    }
}

// ---------------- 4x4 avg pool ----------------
__global__ void pool_kernel(const float* __restrict__ xn, float* __restrict__ pooled) {
    int bidx = blockIdx.x;
    int b = bidx >> 8, hw = bidx & 255;
    int py = hw >> 4, px = hw & 15;
    int c = threadIdx.x;
    float s = 0.f;
    #pragma unroll
    for (int dy = 0; dy < 4; dy++)
        #pragma unroll
        for (int dx = 0; dx < 4; dx++) {
            int n = (py*4 + dy)*GRIDW + px*4 + dx;
            s += xn[((long)b*NTOK + n)*CH + c];
        }
    pooled[(long)bidx*CH + c] = s * (1.f/16.f);
}

// ---------------- fp16 double-buffered GEMM (mma.sync m16n8k16 + ldmatrix) --
#define PADH 40
#define TSTG (128*PADH)

struct GP {
    const __half* W; const float* bias; float* out; __half* outh;
    const float* e0; const float* e1; const float* e2; const float* e3;
};

template<int EPI, int AH, int OH>
__global__ void __launch_bounds__(256, 2)
mma_gemm(const void* Av, int M, int K, int O, GP p0, GP p1) {
    extern __shared__ __half hsm[];
    __half* Ah = hsm;              // [2][128][PADH]
    __half* Bh = hsm + 2*TSTG;     // [2][128][PADH]

    const GP* P = blockIdx.z ? &p1 : &p0;
    const __half* __restrict__ W = P->W;

    int tid  = threadIdx.x;
    int warp = tid >> 5, lane = tid & 31;
    int wm = warp >> 2, wn = warp & 3;
    int m_warp = wm * 64, n_warp = wn * 32;
    int g = lane >> 2, tg = lane & 3;

    int m0 = blockIdx.y * 128;
    int o0 = blockIdx.x * 128;

    int br_ = tid >> 2;
    int bg = tid & 3;

    // ldmatrix lane addressing
    int a_row = lane & 15;                 // row within 16-row tile
    int a_kh  = (lane >> 4) << 3;          // k-half (0 or 8)
    int b_row = ((lane >> 4) << 3) + (lane & 7);   // row within 16-row nt-pair
    int b_kh  = ((lane >> 3) & 1) << 3;            // k-half

    float acc[4][4][4] = {};
    int NC = K >> 5;

    if (AH) {
        const __half* Agh = (const __half*)Av;
        #pragma unroll
        for (int i = 0; i < 2; i++) {
            int row = br_ + i*64;
            cp16(Ah + row*PADH + bg*8, Agh + (long)(m0 + row)*K + bg*8);
            cp16(Bh + row*PADH + bg*8, W + (long)(o0 + row)*K + bg*8);
        }
        cp_commit();
        for (int c = 0; c < NC; c++) {
            int s = c & 1;
            if (c + 1 < NC) {
                int ns = s ^ 1;
                #pragma unroll
                for (int i = 0; i < 2; i++) {
                    int row = br_ + i*64;
                    cp16(Ah + ns*TSTG + row*PADH + bg*8,
                         Agh + (long)(m0 + row)*K + (c+1)*32 + bg*8);
                    cp16(Bh + ns*TSTG + row*PADH + bg*8,
                         W + (long)(o0 + row)*K + (c+1)*32 + bg*8);
                }
            }
            cp_commit();
            cp_wait1();
            __syncthreads();
            const __half* Ab = Ah + s*TSTG;
            const __half* Bb = Bh + s*TSTG;
            #pragma unroll
            for (int kt = 0; kt < 2; kt++) {
                int k0 = kt*16;
                unsigned af[4][4], bf[4][2];
                #pragma unroll
                for (int mt = 0; mt < 4; mt++)
                    ldsm_x4(af[mt], Ab + (m_warp + mt*16 + a_row)*PADH + k0 + a_kh);
                #pragma unroll
                for (int p2 = 0; p2 < 2; p2++) {
                    unsigned r[4];
                    ldsm_x4(r, Bb + (n_warp + p2*16 + b_row)*PADH + k0 + b_kh);
                    bf[p2*2+0][0] = r[0]; bf[p2*2+0][1] = r[1];
                    bf[p2*2+1][0] = r[2]; bf[p2*2+1][1] = r[3];
                }
                #pragma unroll
                for (int mt = 0; mt < 4; mt++)
                    #pragma unroll
                    for (int nt = 0; nt < 4; nt++)
                        mma_f16(acc[mt][nt], af[mt], bf[nt]);
            }
            __syncthreads();
        }
    } else {
        const float* A = (const float*)Av;
        int lr = tid >> 3;
        int lc4 = tid & 7;
        float4 pa[4];
        #pragma unroll
        for (int i = 0; i < 4; i++)
            pa[i] = *(const float4*)(A + (long)(m0 + lr + i*32)*K + lc4*4);
        #pragma unroll
        for (int i = 0; i < 2; i++) {
            int row = br_ + i*64;
            cp16((char*)(Bh + row*PADH) + bg*16, W + (long)(o0 + row)*K + bg*8);
        }
        cp_commit();

        for (int c = 0; c < NC; c++) {
            int s = c & 1;
            {
                __half* Ad = Ah + s*TSTG;
                #pragma unroll
                for (int i = 0; i < 4; i++) {
                    __half2 h01 = __floats2half2_rn(pa[i].x, pa[i].y);
                    __half2 h23 = __floats2half2_rn(pa[i].z, pa[i].w);
                    uint2 u;
                    u.x = *(unsigned*)&h01;
                    u.y = *(unsigned*)&h23;
                    *(uint2*)(Ad + (lr + i*32)*PADH + lc4*4) = u;
                }
            }
            if (c + 1 < NC) {
                __half* Bd = Bh + (s^1)*TSTG;
                #pragma unroll
                for (int i = 0; i < 2; i++) {
                    int row = br_ + i*64;
                    cp16((char*)(Bd + row*PADH) + bg*16,
                         W + (long)(o0 + row)*K + (c+1)*32 + bg*8);
                }
            }
            cp_commit();
            cp_wait1();
            __syncthreads();
            if (c + 1 < NC) {
                #pragma unroll
                for (int i = 0; i < 4; i++)
                    pa[i] = *(const float4*)(A + (long)(m0 + lr + i*32)*K + (c+1)*32 + lc4*4);
            }
            const __half* Ab = Ah + s*TSTG;
            const __half* Bb = Bh + s*TSTG;
            #pragma unroll
            for (int kt = 0; kt < 2; kt++) {
                int k0 = kt*16;
                unsigned af[4][4], bf[4][2];
                #pragma unroll
                for (int mt = 0; mt < 4; mt++)
                    ldsm_x4(af[mt], Ab + (m_warp + mt*16 + a_row)*PADH + k0 + a_kh);
                #pragma unroll
                for (int p2 = 0; p2 < 2; p2++) {
                    unsigned r[4];
                    ldsm_x4(r, Bb + (n_warp + p2*16 + b_row)*PADH + k0 + b_kh);
                    bf[p2*2+0][0] = r[0]; bf[p2*2+0][1] = r[1];
                    bf[p2*2+1][0] = r[2]; bf[p2*2+1][1] = r[3];
                }
                #pragma unroll
                for (int mt = 0; mt < 4; mt++)
                    #pragma unroll
                    for (int nt = 0; nt < 4; nt++)
                        mma_f16(acc[mt][nt], af[mt], bf[nt]);
            }
            __syncthreads();
        }
    }

    const float* __restrict__ bias = P->bias;
    float* __restrict__ out = P->out;
    __half* __restrict__ outh = P->outh;
    const float* e0 = P->e0;
    const float* e1 = P->e1;
    const float* e2 = P->e2;
    const float* e3 = P->e3;

    #pragma unroll
    for (int mt = 0; mt < 4; mt++) {
        #pragma unroll
        for (int nt = 0; nt < 4; nt++) {
            #pragma unroll
            for (int c2 = 0; c2 < 2; c2++) {
                int m = m0 + m_warp + mt*16 + g + c2*8;
                int o = o0 + n_warp + nt*8 + tg*2;
                float y0 = acc[mt][nt][c2*2+0] + bias[o];
                float y1 = acc[mt][nt][c2*2+1] + bias[o+1];
                if (EPI == 1) {
                    y0 = (y0 - e0[o])   * rsqrtf(e1[o]   + 1e-5f) * e2[o]   + e3[o];
                    y1 = (y1 - e0[o+1]) * rsqrtf(e1[o+1] + 1e-5f) * e2[o+1] + e3[o+1];
                } else if (EPI == 2) {
                    y0 = 0.5f*y0*(1.f + erff(y0*0.70710678118654752f));
                    y1 = 0.5f*y1*(1.f + erff(y1*0.70710678118654752f));
                } else if (EPI == 3) {
                    float2 rv = *(const float2*)(e0 + (long)m*O + o);
                    y0 += rv.x; y1 += rv.y;
                }
                if (OH) {
                    __half2 hv = __floats2half2_rn(y0, y1);
                    *(__half2*)(outh + (long)m*O + o) = hv;
                } else {
                    float2 v; v.x = y0; v.y = y1;
                    *(float2*)(out + (long)m*O + o) = v;
                }
            }
        }
    }
}

// ---------------- global cross-attention pooling path -----------------
__global__ void global_attn_kernel(const float* __restrict__ kpool,
                                   const float* __restrict__ vpool,
                                   const float* __restrict__ qtok,
                                   float* __restrict__ qin) {
    int b = blockIdx.x >> 3, h = blockIdx.x & 7;
    __shared__ float qs[NQ][HD];
    __shared__ float lg[NQ][HP2];
    __shared__ float vsm[HP2][HD];
    int tid = threadIdx.x;
    { int q = tid >> 5, d = tid & 31; qs[q][d] = qtok[q*CH + h*HD + d]; }
    for (int idx = tid; idx < HP2*HD; idx += 256) {
        int r = idx >> 5, d = idx & 31;
        vsm[r][d] = vpool[((long)b*HP2 + r)*CH + h*HD + d];
    }
    __syncthreads();
    float kreg[HD];
    const float* kr = kpool + ((long)b*HP2 + tid)*CH + h*HD;
    #pragma unroll
    for (int d = 0; d < HD; d++) kreg[d] = kr[d];
    #pragma unroll
    for (int q = 0; q < NQ; q++) {
        float s = 0.f;
        #pragma unroll
        for (int d = 0; d < HD; d++) s = fmaf(qs[q][d], kreg[d], s);
        lg[q][tid] = s * SCALE;
    }
    __syncthreads();
    int w = tid >> 5, lane = tid & 31;
    {
        float m = -1e30f;
        for (int j = lane; j < HP2; j += 32) m = fmaxf(m, lg[w][j]);
        #pragma unroll
        for (int o = 16; o; o >>= 1) m = fmaxf(m, __shfl_xor_sync(~0u, m, o));
        float s = 0.f;
        for (int j = lane; j < HP2; j += 32) { float e = __expf(lg[w][j] - m); lg[w][j] = e; s += e; }
        #pragma unroll
        for (int o = 16; o; o >>= 1) s += __shfl_xor_sync(~0u, s, o);
        float inv = 1.f / s;
        for (int j = lane; j < HP2; j += 32) lg[w][j] *= inv;
    }
    __syncthreads();
    int q = tid >> 5, d = tid & 31;
    float acc = 0.f;
    for (int kk = 0; kk < HP2; kk++) acc = fmaf(lg[q][kk], vsm[kk][d], acc);
    qin[(b*NQ + q)*CH + h*HD + d] = acc + qtok[q*CH + h*HD + d];
}

// ---------------- window attention (fp16 tensor-core) ------------------
#define PADQ 40
#define PADP 88

__global__ void __launch_bounds__(256)
window_attn_kernel(const __half* __restrict__ qkvh,
                   const float* __restrict__ gk,
                   const float* __restrict__ gv,
                   const float* __restrict__ rpb,
                   float* __restrict__ attn_out,
                   __half* __restrict__ attouth) {
    int h   = blockIdx.x & 7;
    int win = blockIdx.x >> 3;
    int wx = win & 7, wy = (win >> 3) & 7, b = win >> 6;
    int n_base = (wy*WS)*GRIDW + wx*WS;

    __shared__ __half qs[64][PADQ];
    __shared__ __half ks[80][PADQ];
    __shared__ __half vt[32][PADP];
    __shared__ __half ph[64][PADP];
    __shared__ float  lg[64][80];

    int tid = threadIdx.x;
    int warp = tid >> 5, lane = tid & 31;
    int g = lane >> 2, tg = lane & 3;

    for (int idx = tid; idx < 64*32; idx += 256) {
        int i = idx >> 5, d = idx & 31;
        int n = n_base + (i >> 3)*GRIDW + (i & 7);
        float qv = __half2float(qkvh[((long)b*NTOK + n)*(3*CH) + h*HD + d]);
        qs[i][d] = __float2half(qv * SCALE);
    }
    for (int idx = tid; idx < 80*32; idx += 256) {
        int j = idx >> 5, d = idx & 31;
        float kv = 0.f, vv = 0.f;
        if (j < 64) {
            int n = n_base + (j >> 3)*GRIDW + (j & 7);
            long base = ((long)b*NTOK + n)*(3*CH) + h*HD + d;
            kv = __half2float(qkvh[base + CH]);
            vv = __half2float(qkvh[base + 2*CH]);
        } else if (j < 72) {
            int nq = j - 64;
            kv = gk[(b*NQ + nq)*CH + h*HD + d];
            vv = gv[(b*NQ + nq)*CH + h*HD + d];
        }
        ks[j][d] = __float2half(kv);
        vt[d][j] = __float2half(vv);
    }
    for (int idx = tid; idx < 64*8; idx += 256) {
        int i = idx >> 3, jj = idx & 7;
        ph[i][72 + jj] = __float2half(0.f);
    }
    __syncthreads();

    {
        int mw = (warp >> 1)*16, np = (warp & 1)*40;
        float acc[5][4] = {};
        #pragma unroll
        for (int kt = 0; kt < 2; kt++) {
            int k0 = kt*16;
            unsigned a[4];
            a[0] = *(const unsigned*)(&qs[mw+g][k0 + tg*2]);
            a[1] = *(const unsigned*)(&qs[mw+g+8][k0 + tg*2]);
            a[2] = *(const unsigned*)(&qs[mw+g][k0 + tg*2 + 8]);
            a[3] = *(const unsigned*)(&qs[mw+g+8][k0 + tg*2 + 8]);
            #pragma unroll
            for (int nt = 0; nt < 5; nt++) {
                int nb = np + nt*8 + g;
                unsigned bb[2];
                bb[0] = *(const unsigned*)(&ks[nb][k0 + tg*2]);
                bb[1] = *(const unsigned*)(&ks[nb][k0 + tg*2 + 8]);
                mma_f16(acc[nt], a, bb);
            }
        }
        #pragma unroll
        for (int nt = 0; nt < 5; nt++) {
            #pragma unroll
            for (int c = 0; c < 4; c++) {
                int i = mw + g + (c >> 1)*8;
                int j = np + nt*8 + tg*2 + (c & 1);
                float s = acc[nt][c];
                if (j < 64) {
                    int diy = (i >> 3) - (j >> 3) + 7;
                    int dix = (i & 7) - (j & 7) + 7;
                    s += rpb[(diy*15 + dix)*HEADS + h];
                }
                lg[i][j] = s;
            }
        }
    }
    __syncthreads();

    for (int it = 0; it < 8; it++) {
        int i = it*8 + warp;
        float m = -1e30f;
        for (int j = lane; j < KVLEN; j += 32) m = fmaxf(m, lg[i][j]);
        #pragma unroll
        for (int o = 16; o; o >>= 1) m = fmaxf(m, __shfl_xor_sync(~0u, m, o));
        float s = 0.f;
        for (int j = lane; j < KVLEN; j += 32) { float e = __expf(lg[i][j] - m); lg[i][j] = e; s += e; }
        #pragma unroll
        for (int o = 16; o; o >>= 1) s += __shfl_xor_sync(~0u, s, o);
        float inv = 1.f / s;
        for (int j = lane; j < KVLEN; j += 32) lg[i][j] *= inv;
    }
    __syncthreads();

    long abase = ((long)(win*HEADS + h))*64*KVLEN;
    for (int idx = tid; idx < 64*KVLEN; idx += 256) {
        int i = idx / KVLEN, j = idx - i*KVLEN;
        float p = lg[i][j];
        attn_out[abase + idx] = p;
        ph[i][j] = __float2half(p);
    }
    __syncthreads();

    {
        int mw = (warp >> 1)*16, nv = (warp & 1)*16;
        float acc[2][4] = {};
        #pragma unroll
        for (int kt = 0; kt < 5; kt++) {
            int k0 = kt*16;
            unsigned a[4];
            a[0] = *(const unsigned*)(&ph[mw+g][k0 + tg*2]);
            a[1] = *(const unsigned*)(&ph[mw+g+8][k0 + tg*2]);
            a[2] = *(const unsigned*)(&ph[mw+g][k0 + tg*2 + 8]);
            a[3] = *(const unsigned*)(&ph[mw+g+8][k0 + tg*2 + 8]);
            #pragma unroll
            for (int nt = 0; nt < 2; nt++) {
                int nb = nv + nt*8 + g;
                unsigned bb[2];
                bb[0] = *(const unsigned*)(&vt[nb][k0 + tg*2]);
                bb[1] = *(const unsigned*)(&vt[nb][k0 + tg*2 + 8]);
                mma_f16(acc[nt], a, bb);
            }
        }
        #pragma unroll
        for (int nt = 0; nt < 2; nt++) {
            #pragma unroll
            for (int c = 0; c < 4; c++) {
                int i = mw + g + (c >> 1)*8;
                int d = nv + nt*8 + tg*2 + (c & 1);
                int n = n_base + (i >> 3)*GRIDW + (i & 7);
                attouth[((long)b*NTOK + n)*CH + h*HD + d] = __float2half(acc[nt][c]);
            }
        }
    }
}

// ---------------- host launch ------------------------------------------
#define GEMM_SMEM (4*TSTG*2)

extern "C" void kernel_launch(void* const* d_in, const int* in_sizes, int n_in,
                              void* d_out, int out_size) {
    const float* x       = (const float*)d_in[0];
    const float* qtok    = (const float*)d_in[1];
    const float* kproj_w = (const float*)d_in[2];
    const float* kproj_b = (const float*)d_in[3];
    const float* kbn_g   = (const float*)d_in[4];
    const float* kbn_b   = (const float*)d_in[5];
    const float* kbn_m   = (const float*)d_in[6];
    const float* kbn_v   = (const float*)d_in[7];
    const float* vproj_w = (const float*)d_in[8];
    const float* vproj_b = (const float*)d_in[9];
    const float* vbn_g   = (const float*)d_in[10];
    const float* vbn_b   = (const float*)d_in[11];
    const float* vbn_m   = (const float*)d_in[12];
    const float* vbn_v   = (const float*)d_in[13];
    const float* ck_w    = (const float*)d_in[14];
    const float* ck_b    = (const float*)d_in[15];
    const float* cv_w    = (const float*)d_in[16];
    const float* cv_b    = (const float*)d_in[17];
    const float* rpb     = (const float*)d_in[18];
    const float* qkv_w   = (const float*)d_in[19];
    const float* qkv_b   = (const float*)d_in[20];
    const float* proj_w  = (const float*)d_in[21];
    const float* proj_b  = (const float*)d_in[22];
    const float* n1_g    = (const float*)d_in[23];
    const float* n1_b    = (const float*)d_in[24];
    const float* n2_g    = (const float*)d_in[25];
    const float* n2_b    = (const float*)d_in[26];
    const float* fc1_w   = (const float*)d_in[27];
    const float* fc1_b   = (const float*)d_in[28];
    const float* fc2_w   = (const float*)d_in[29];
    const float* fc2_b   = (const float*)d_in[30];

    float* out_x    = (float*)d_out;
    float* out_attn = out_x + (long)BATCH*NTOK*CH;

    float *xn, *pooled, *kpool, *vpool, *qin, *gk, *gv, *xnew;
    __half *xnh, *xmh, *attouth, *hh, *qkvh;
    cudaGetSymbolAddress((void**)&xn,      g_xn);
    cudaGetSymbolAddress((void**)&xnh,     g_xnh);
    cudaGetSymbolAddress((void**)&pooled,  g_pooled);
    cudaGetSymbolAddress((void**)&kpool,   g_kpool);
    cudaGetSymbolAddress((void**)&vpool,   g_vpool);
    cudaGetSymbolAddress((void**)&qin,     g_qin);
    cudaGetSymbolAddress((void**)&gk,      g_gk);
    cudaGetSymbolAddress((void**)&gv,      g_gv);
    cudaGetSymbolAddress((void**)&qkvh,    g_qkvh);
    cudaGetSymbolAddress((void**)&attouth, g_attouth);
    cudaGetSymbolAddress((void**)&xnew,    g_xnew);
    cudaGetSymbolAddress((void**)&xmh,     g_xmh);
    cudaGetSymbolAddress((void**)&hh,      g_hh);

    __half *wqkv, *wfc1, *wfc2, *wproj, *wkp, *wvp, *wck, *wcv;
    cudaGetSymbolAddress((void**)&wqkv,  g_wqkv);
    cudaGetSymbolAddress((void**)&wfc1,  g_wfc1);
    cudaGetSymbolAddress((void**)&wfc2,  g_wfc2);
    cudaGetSymbolAddress((void**)&wproj, g_wproj);
    cudaGetSymbolAddress((void**)&wkp,   g_wkp);
    cudaGetSymbolAddress((void**)&wvp,   g_wvp);
    cudaGetSymbolAddress((void**)&wck,   g_wck);
    cudaGetSymbolAddress((void**)&wcv,   g_wcv);

    static int smem_set = 0;
    if (!smem_set) {
        cudaFuncSetAttribute(mma_gemm<0,0,0>, cudaFuncAttributeMaxDynamicSharedMemorySize, GEMM_SMEM);
        cudaFuncSetAttribute(mma_gemm<1,0,0>, cudaFuncAttributeMaxDynamicSharedMemorySize, GEMM_SMEM);
        cudaFuncSetAttribute(mma_gemm<0,1,1>, cudaFuncAttributeMaxDynamicSharedMemorySize, GEMM_SMEM);
        cudaFuncSetAttribute(mma_gemm<2,1,1>, cudaFuncAttributeMaxDynamicSharedMemorySize, GEMM_SMEM);
        cudaFuncSetAttribute(mma_gemm<3,1,0>, cudaFuncAttributeMaxDynamicSharedMemorySize, GEMM_SMEM);
        smem_set = 1;
    }

    const int M = BATCH*NTOK;   // 65536

    // merged weight conversion (one launch)
    WC wc;
    wc.s[0]=qkv_w;  wc.d[0]=wqkv;  wc.n4[0]=49152;
    wc.s[1]=fc1_w;  wc.d[1]=wfc1;  wc.n4[1]=65536;
    wc.s[2]=fc2_w;  wc.d[2]=wfc2;  wc.n4[2]=65536;
    wc.s[3]=proj_w; wc.d[3]=wproj; wc.n4[3]=16384;
    wc.s[4]=kproj_w;wc.d[4]=wkp;   wc.n4[4]=16384;
    wc.s[5]=vproj_w;wc.d[5]=wvp;   wc.n4[5]=16384;
    wc.s[6]=ck_w;   wc.d[6]=wck;   wc.n4[6]=16384;
    wc.s[7]=cv_w;   wc.d[7]=wcv;   wc.n4[7]=16384;
    wconv_all<<<dim3(256, 8), 256>>>(wc);

    // LN1: fp32 (for pool) + fp16 (for qkv GEMM)
    layernorm_kernel<2><<<M/8, 256>>>(x, n1_g, n1_b, xn, xnh);
    pool_kernel<<<BATCH*HP2, 256>>>(xn, pooled);

    GP kp = {wkp, kproj_b, kpool, 0, kbn_m, kbn_v, kbn_g, kbn_b};
    GP vp = {wvp, vproj_b, vpool, 0, vbn_m, vbn_v, vbn_g, vbn_b};
    mma_gemm<1,0,0><<<dim3(2, 32, 2), 256, GEMM_SMEM>>>(pooled, BATCH*HP2, CH, CH, kp, vp);

    global_attn_kernel<<<BATCH*HEADS, 256>>>(kpool, vpool, qtok, qin);

    GP ckp = {wck, ck_b, gk, 0, 0, 0, 0, 0};
    GP cvp = {wcv, cv_b, gv, 0, 0, 0, 0, 0};
    mma_gemm<0,0,0><<<dim3(2, 1, 2), 256, GEMM_SMEM>>>(qin, BATCH*NQ, CH, CH, ckp, cvp);

    // qkv projection -> fp16 buffer
    GP qkvp = {wqkv, qkv_b, 0, qkvh, 0, 0, 0, 0};
    mma_gemm<0,1,1><<<dim3(6, 512, 1), 256, GEMM_SMEM>>>(xnh, M, CH, 3*CH, qkvp, qkvp);

    window_attn_kernel<<<BATCH*NWIN*HEADS, 256>>>(qkvh, gk, gv, rpb, out_attn, attouth);

    GP projp = {wproj, proj_b, xnew, 0, x, 0, 0, 0};
    mma_gemm<3,1,0><<<dim3(2, 512, 1), 256, GEMM_SMEM>>>(attouth, M, CH, CH, projp, projp);

    // LN2: fp16 only (consumed by fc1)
    layernorm_kernel<1><<<M/8, 256>>>(xnew, n2_g, n2_b, 0, xmh);

    GP fc1p = {wfc1, fc1_b, 0, hh, 0, 0, 0, 0};
    mma_gemm<2,1,1><<<dim3(8, 512, 1), 256, GEMM_SMEM>>>(xmh, M, CH, 4*CH, fc1p, fc1p);

    GP fc2p = {wfc2, fc2_b, out_x, 0, xnew, 0, 0, 0};
    mma_gemm<3,1,0><<<dim3(2, 512, 1), 256, GEMM_SMEM>>>(hh, M, 4*CH, CH, fc2p, fc2p);
}

// round 13
// speedup vs baseline: 4.6123x; 1.0279x over previous
#include <cuda_runtime.h>
#include <cuda_fp16.h>
#include <math.h>

// ---------------- problem constants ----------------
#define BATCH   16
#define CH      256
#define NTOK    4096
#define GRIDW   64
#define HEADS   8
#define HD      32
#define NQ      8
#define WS      8
#define NWIN    64
#define KVLEN   72
#define HP2     256
#define SCALE   0.17677669529663687f

// ---------------- scratch ----------------
__device__ float  g_xn   [(long)BATCH*NTOK*CH];
__device__ __half g_xnh  [(long)BATCH*NTOK*CH];
__device__ __half g_pooledh[(long)BATCH*HP2*CH];
__device__ float  g_kpool [(long)BATCH*HP2*CH];
__device__ float  g_vpool [(long)BATCH*HP2*CH];
__device__ __half g_qinh  [BATCH*NQ*CH];
__device__ float  g_gk    [BATCH*NQ*CH];
__device__ float  g_gv    [BATCH*NQ*CH];
__device__ __half g_qkvh [(long)BATCH*NTOK*3*CH];
__device__ __half g_attouth[(long)BATCH*NTOK*CH];
__device__ float  g_xnew [(long)BATCH*NTOK*CH];
__device__ __half g_xmh  [(long)BATCH*NTOK*CH];
__device__ __half g_hh   [(long)BATCH*NTOK*4*CH];

// fp16 weight copies
__device__ __half g_wqkv[768*256];
__device__ __half g_wfc1[1024*256];
__device__ __half g_wfc2[256*1024];
__device__ __half g_wproj[256*256];
__device__ __half g_wkp [256*256];
__device__ __half g_wvp [256*256];
__device__ __half g_wck [256*256];
__device__ __half g_wcv [256*256];

// ---------------- helpers ----------------
__device__ __forceinline__ void mma_f16(float* c, const unsigned* a, const unsigned* b) {
    asm volatile(
        "mma.sync.aligned.m16n8k16.row.col.f32.f16.f16.f32 "
        "{%0,%1,%2,%3}, {%4,%5,%6,%7}, {%8,%9}, {%0,%1,%2,%3};"
        : "+f"(c[0]), "+f"(c[1]), "+f"(c[2]), "+f"(c[3])
        : "r"(a[0]), "r"(a[1]), "r"(a[2]), "r"(a[3]), "r"(b[0]), "r"(b[1]));
}

__device__ __forceinline__ void ldsm_x4(unsigned* r, const void* p) {
    unsigned a = (unsigned)__cvta_generic_to_shared(p);
    asm volatile("ldmatrix.sync.aligned.m8n8.x4.shared.b16 {%0,%1,%2,%3}, [%4];"
                 : "=r"(r[0]), "=r"(r[1]), "=r"(r[2]), "=r"(r[3]) : "r"(a));
}

__device__ __forceinline__ void cp16(void* dst, const void* src) {
    unsigned d = (unsigned)__cvta_generic_to_shared(dst);
    asm volatile("cp.async.cg.shared.global [%0], [%1], 16;" :: "r"(d), "l"(src));
}
__device__ __forceinline__ void cp_commit() {
    asm volatile("cp.async.commit_group;");
}
__device__ __forceinline__ void cp_wait2() {
    asm volatile("cp.async.wait_group 2;");
}

// ---------------- merged weight fp32 -> fp16 conversion ----------------
struct WC { const float* s[8]; __half* d[8]; int n4[8]; };

__global__ void wconv_all(WC wc) {
    int seg = blockIdx.y;
    int i = blockIdx.x*256 + threadIdx.x;
    if (i < wc.n4[seg]) {
        float4 v = ((const float4*)wc.s[seg])[i];
        __half2 a = __floats2half2_rn(v.x, v.y);
        __half2 b = __floats2half2_rn(v.z, v.w);
        uint2 u;
        u.x = *(unsigned*)&a;
        u.y = *(unsigned*)&b;
        ((uint2*)wc.d[seg])[i] = u;
    }
}

// ---------------- layernorm: warp per row, shfl-only -------------------
// MODE 0: fp32 only, 1: half only, 2: both
template<int MODE>
__global__ void layernorm_kernel(const float* __restrict__ x,
                                 const float* __restrict__ g,
                                 const float* __restrict__ b,
                                 float* __restrict__ out,
                                 __half* __restrict__ outh) {
    long row = (long)blockIdx.x*8 + (threadIdx.x >> 5);
    int lane = threadIdx.x & 31;
    const float4* xr = (const float4*)(x + row*CH);
    float4 v0 = xr[lane], v1 = xr[lane + 32];
    float s = v0.x+v0.y+v0.z+v0.w + v1.x+v1.y+v1.z+v1.w;
    #pragma unroll
    for (int o = 16; o; o >>= 1) s += __shfl_xor_sync(~0u, s, o);
    float m = s * (1.f/CH);
    float d0x=v0.x-m, d0y=v0.y-m, d0z=v0.z-m, d0w=v0.w-m;
    float d1x=v1.x-m, d1y=v1.y-m, d1z=v1.z-m, d1w=v1.w-m;
    float q = d0x*d0x+d0y*d0y+d0z*d0z+d0w*d0w + d1x*d1x+d1y*d1y+d1z*d1z+d1w*d1w;
    #pragma unroll
    for (int o = 16; o; o >>= 1) q += __shfl_xor_sync(~0u, q, o);
    float r = rsqrtf(q * (1.f/CH) + 1e-5f);
    const float4* gr = (const float4*)g;
    const float4* br = (const float4*)b;
    float4 g0 = gr[lane], g1 = gr[lane+32], b0 = br[lane], b1 = br[lane+32];
    float4 o0, o1;
    o0.x = d0x*r*g0.x + b0.x; o0.y = d0y*r*g0.y + b0.y;
    o0.z = d0z*r*g0.z + b0.z; o0.w = d0w*r*g0.w + b0.w;
    o1.x = d1x*r*g1.x + b1.x; o1.y = d1y*r*g1.y + b1.y;
    o1.z = d1z*r*g1.z + b1.z; o1.w = d1w*r*g1.w + b1.w;
    if (MODE != 1) {
        float4* orow = (float4*)(out + row*CH);
        orow[lane] = o0; orow[lane+32] = o1;
    }
    if (MODE != 0) {
        __half2 h0 = __floats2half2_rn(o0.x, o0.y);
        __half2 h1 = __floats2half2_rn(o0.z, o0.w);
        __half2 h2 = __floats2half2_rn(o1.x, o1.y);
        __half2 h3 = __floats2half2_rn(o1.z, o1.w);
        uint2 u0, u1;
        u0.x = *(unsigned*)&h0; u0.y = *(unsigned*)&h1;
        u1.x = *(unsigned*)&h2; u1.y = *(unsigned*)&h3;
        uint2* hrow = (uint2*)(outh + row*CH);
        hrow[lane] = u0; hrow[lane+32] = u1;
    }
}

// ---------------- 4x4 avg pool -> fp16 ----------------
__global__ void pool_kernel(const float* __restrict__ xn, __half* __restrict__ pooledh) {
    int bidx = blockIdx.x;
    int b = bidx >> 8, hw = bidx & 255;
    int py = hw >> 4, px = hw & 15;
    int c = threadIdx.x;
    float s = 0.f;
    #pragma unroll
    for (int dy = 0; dy < 4; dy++)
        #pragma unroll
        for (int dx = 0; dx < 4; dx++) {
            int n = (py*4 + dy)*GRIDW + px*4 + dx;
            s += xn[((long)b*NTOK + n)*CH + c];
        }
    pooledh[(long)bidx*CH + c] = __float2half(s * (1.f/16.f));
}

// ---------------- fp16 4-stage GEMM (mma.sync m16n8k16 + ldmatrix) -----
// out[M,O] = A[M,K]fp16 @ Wh[O,K]^T + bias. BM=BN=128, BK=32. 256 thr.
// 4-stage cp.async ring, one __syncthreads per chunk.
// OH=1: store fp16 to outh. EPI: 0 bias; 1 BN; 2 GELU; 3 residual(e0).
#define PADH 40
#define TSTG (128*PADH)          // halves per matrix per stage
#define STG2 (2*TSTG)            // halves per stage (A+B)

struct GP {
    const __half* W; const float* bias; float* out; __half* outh;
    const float* e0; const float* e1; const float* e2; const float* e3;
};

template<int EPI, int OH>
__global__ void __launch_bounds__(256, 2)
mma_gemm(const __half* __restrict__ Agh, int M, int K, int O, GP p0, GP p1) {
    extern __shared__ __half hsm[];   // [4][A 128*PADH | B 128*PADH]

    const GP* P = blockIdx.z ? &p1 : &p0;
    const __half* __restrict__ W = P->W;

    int tid  = threadIdx.x;
    int warp = tid >> 5, lane = tid & 31;
    int wm = warp >> 2, wn = warp & 3;
    int m_warp = wm * 64, n_warp = wn * 32;
    int g = lane >> 2, tg = lane & 3;

    int m0 = blockIdx.y * 128;
    int o0 = blockIdx.x * 128;

    int br_ = tid >> 2;      // 0..63
    int bg = tid & 3;        // 16B granule

    // ldmatrix lane addressing
    int a_row = lane & 15;
    int a_kh  = (lane >> 4) << 3;
    int b_row = ((lane >> 4) << 3) + (lane & 7);
    int b_kh  = ((lane >> 3) & 1) << 3;

    float acc[4][4][4] = {};
    int NC = K >> 5;

    // prologue: issue chunks 0,1,2 into stages 0,1,2
    #pragma unroll
    for (int p = 0; p < 3; p++) {
        __half* As = hsm + p*STG2;
        __half* Bs = As + TSTG;
        #pragma unroll
        for (int i = 0; i < 2; i++) {
            int row = br_ + i*64;
            cp16(As + row*PADH + bg*8, Agh + (long)(m0 + row)*K + p*32 + bg*8);
            cp16(Bs + row*PADH + bg*8, W + (long)(o0 + row)*K + p*32 + bg*8);
        }
        cp_commit();
    }

    for (int c = 0; c < NC; c++) {
        cp_wait2();          // chunk c resident
        __syncthreads();     // all warps done with stage (c-1)%4, chunk c visible

        // issue chunk c+3 into stage (c+3)&3 (== stage (c-1)&3, now free)
        if (c + 3 < NC) {
            __half* As = hsm + ((c+3) & 3)*STG2;
            __half* Bs = As + TSTG;
            #pragma unroll
            for (int i = 0; i < 2; i++) {
                int row = br_ + i*64;
                cp16(As + row*PADH + bg*8, Agh + (long)(m0 + row)*K + (c+3)*32 + bg*8);
                cp16(Bs + row*PADH + bg*8, W + (long)(o0 + row)*K + (c+3)*32 + bg*8);
            }
        }
        cp_commit();         // commit every iteration (possibly empty group)

        const __half* Ab = hsm + (c & 3)*STG2;
        const __half* Bb = Ab + TSTG;
        #pragma unroll
        for (int kt = 0; kt < 2; kt++) {
            int k0 = kt*16;
            unsigned af[4][4], bf[4][2];
            #pragma unroll
            for (int mt = 0; mt < 4; mt++)
                ldsm_x4(af[mt], Ab + (m_warp + mt*16 + a_row)*PADH + k0 + a_kh);
            #pragma unroll
            for (int p2 = 0; p2 < 2; p2++) {
                unsigned r[4];
                ldsm_x4(r, Bb + (n_warp + p2*16 + b_row)*PADH + k0 + b_kh);
                bf[p2*2+0][0] = r[0]; bf[p2*2+0][1] = r[1];
                bf[p2*2+1][0] = r[2]; bf[p2*2+1][1] = r[3];
            }
            #pragma unroll
            for (int mt = 0; mt < 4; mt++)
                #pragma unroll
                for (int nt = 0; nt < 4; nt++)
                    mma_f16(acc[mt][nt], af[mt], bf[nt]);
        }
    }

    const float* __restrict__ bias = P->bias;
    float* __restrict__ out = P->out;
    __half* __restrict__ outh = P->outh;
    const float* e0 = P->e0;
    const float* e1 = P->e1;
    const float* e2 = P->e2;
    const float* e3 = P->e3;

    #pragma unroll
    for (int mt = 0; mt < 4; mt++) {
        #pragma unroll
        for (int nt = 0; nt < 4; nt++) {
            #pragma unroll
            for (int c2 = 0; c2 < 2; c2++) {
                int m = m0 + m_warp + mt*16 + g + c2*8;
                int o = o0 + n_warp + nt*8 + tg*2;
                float y0 = acc[mt][nt][c2*2+0] + bias[o];
                float y1 = acc[mt][nt][c2*2+1] + bias[o+1];
                if (EPI == 1) {
                    y0 = (y0 - e0[o])   * rsqrtf(e1[o]   + 1e-5f) * e2[o]   + e3[o];
                    y1 = (y1 - e0[o+1]) * rsqrtf(e1[o+1] + 1e-5f) * e2[o+1] + e3[o+1];
                } else if (EPI == 2) {
                    y0 = 0.5f*y0*(1.f + erff(y0*0.70710678118654752f));
                    y1 = 0.5f*y1*(1.f + erff(y1*0.70710678118654752f));
                } else if (EPI == 3) {
                    float2 rv = *(const float2*)(e0 + (long)m*O + o);
                    y0 += rv.x; y1 += rv.y;
                }
                if (OH) {
                    __half2 hv = __floats2half2_rn(y0, y1);
                    *(__half2*)(outh + (long)m*O + o) = hv;
                } else {
                    float2 v; v.x = y0; v.y = y1;
                    *(float2*)(out + (long)m*O + o) = v;
                }
            }
        }
    }
}

// ---------------- global cross-attention pooling path -----------------
__global__ void global_attn_kernel(const float* __restrict__ kpool,
                                   const float* __restrict__ vpool,
                                   const float* __restrict__ qtok,
                                   __half* __restrict__ qinh) {
    int b = blockIdx.x >> 3, h = blockIdx.x & 7;
    __shared__ float qs[NQ][HD];
    __shared__ float lg[NQ][HP2];
    __shared__ float vsm[HP2][HD];
    int tid = threadIdx.x;
    { int q = tid >> 5, d = tid & 31; qs[q][d] = qtok[q*CH + h*HD + d]; }
    for (int idx = tid; idx < HP2*HD; idx += 256) {
        int r = idx >> 5, d = idx & 31;
        vsm[r][d] = vpool[((long)b*HP2 + r)*CH + h*HD + d];
    }
    __syncthreads();
    float kreg[HD];
    const float* kr = kpool + ((long)b*HP2 + tid)*CH + h*HD;
    #pragma unroll
    for (int d = 0; d < HD; d++) kreg[d] = kr[d];
    #pragma unroll
    for (int q = 0; q < NQ; q++) {
        float s = 0.f;
        #pragma unroll
        for (int d = 0; d < HD; d++) s = fmaf(qs[q][d], kreg[d], s);
        lg[q][tid] = s * SCALE;
    }
    __syncthreads();
    int w = tid >> 5, lane = tid & 31;
    {
        float m = -1e30f;
        for (int j = lane; j < HP2; j += 32) m = fmaxf(m, lg[w][j]);
        #pragma unroll
        for (int o = 16; o; o >>= 1) m = fmaxf(m, __shfl_xor_sync(~0u, m, o));
        float s = 0.f;
        for (int j = lane; j < HP2; j += 32) { float e = __expf(lg[w][j] - m); lg[w][j] = e; s += e; }
        #pragma unroll
        for (int o = 16; o; o >>= 1) s += __shfl_xor_sync(~0u, s, o);
        float inv = 1.f / s;
        for (int j = lane; j < HP2; j += 32) lg[w][j] *= inv;
    }
    __syncthreads();
    int q = tid >> 5, d = tid & 31;
    float acc = 0.f;
    for (int kk = 0; kk < HP2; kk++) acc = fmaf(lg[q][kk], vsm[kk][d], acc);
    qinh[(b*NQ + q)*CH + h*HD + d] = __float2half(acc + qtok[q*CH + h*HD + d]);
}

// ---------------- window attention (fp16 tensor-core) ------------------
#define PADQ 40
#define PADP 88

__global__ void __launch_bounds__(256)
window_attn_kernel(const __half* __restrict__ qkvh,
                   const float* __restrict__ gk,
                   const float* __restrict__ gv,
                   const float* __restrict__ rpb,
                   float* __restrict__ attn_out,
                   __half* __restrict__ attouth) {
    int h   = blockIdx.x & 7;
    int win = blockIdx.x >> 3;
    int wx = win & 7, wy = (win >> 3) & 7, b = win >> 6;
    int n_base = (wy*WS)*GRIDW + wx*WS;

    __shared__ __half qs[64][PADQ];
    __shared__ __half ks[80][PADQ];
    __shared__ __half vt[32][PADP];
    __shared__ __half ph[64][PADP];
    __shared__ float  lg[64][80];

    int tid = threadIdx.x;
    int warp = tid >> 5, lane = tid & 31;
    int g = lane >> 2, tg = lane & 3;

    for (int idx = tid; idx < 64*32; idx += 256) {
        int i = idx >> 5, d = idx & 31;
        int n = n_base + (i >> 3)*GRIDW + (i & 7);
        float qv = __half2float(qkvh[((long)b*NTOK + n)*(3*CH) + h*HD + d]);
        qs[i][d] = __float2half(qv * SCALE);
    }
    for (int idx = tid; idx < 80*32; idx += 256) {
        int j = idx >> 5, d = idx & 31;
        float kv = 0.f, vv = 0.f;
        if (j < 64) {
            int n = n_base + (j >> 3)*GRIDW + (j & 7);
            long base = ((long)b*NTOK + n)*(3*CH) + h*HD + d;
            kv = __half2float(qkvh[base + CH]);
            vv = __half2float(qkvh[base + 2*CH]);
        } else if (j < 72) {
            int nq = j - 64;
            kv = gk[(b*NQ + nq)*CH + h*HD + d];
            vv = gv[(b*NQ + nq)*CH + h*HD + d];
        }
        ks[j][d] = __float2half(kv);
        vt[d][j] = __float2half(vv);
    }
    for (int idx = tid; idx < 64*8; idx += 256) {
        int i = idx >> 3, jj = idx & 7;
        ph[i][72 + jj] = __float2half(0.f);
    }
    __syncthreads();

    {
        int mw = (warp >> 1)*16, np = (warp & 1)*40;
        float acc[5][4] = {};
        #pragma unroll
        for (int kt = 0; kt < 2; kt++) {
            int k0 = kt*16;
            unsigned a[4];
            a[0] = *(const unsigned*)(&qs[mw+g][k0 + tg*2]);
            a[1] = *(const unsigned*)(&qs[mw+g+8][k0 + tg*2]);
            a[2] = *(const unsigned*)(&qs[mw+g][k0 + tg*2 + 8]);
            a[3] = *(const unsigned*)(&qs[mw+g+8][k0 + tg*2 + 8]);
            #pragma unroll
            for (int nt = 0; nt < 5; nt++) {
                int nb = np + nt*8 + g;
                unsigned bb[2];
                bb[0] = *(const unsigned*)(&ks[nb][k0 + tg*2]);
                bb[1] = *(const unsigned*)(&ks[nb][k0 + tg*2 + 8]);
                mma_f16(acc[nt], a, bb);
            }
        }
        #pragma unroll
        for (int nt = 0; nt < 5; nt++) {
            #pragma unroll
            for (int c = 0; c < 4; c++) {
                int i = mw + g + (c >> 1)*8;
                int j = np + nt*8 + tg*2 + (c & 1);
                float s = acc[nt][c];
                if (j < 64) {
                    int diy = (i >> 3) - (j >> 3) + 7;
                    int dix = (i & 7) - (j & 7) + 7;
                    s += rpb[(diy*15 + dix)*HEADS + h];
                }
                lg[i][j] = s;
            }
        }
    }
    __syncthreads();

    for (int it = 0; it < 8; it++) {
        int i = it*8 + warp;
        float m = -1e30f;
        for (int j = lane; j < KVLEN; j += 32) m = fmaxf(m, lg[i][j]);
        #pragma unroll
        for (int o = 16; o; o >>= 1) m = fmaxf(m, __shfl_xor_sync(~0u, m, o));
        float s = 0.f;
        for (int j = lane; j < KVLEN; j += 32) { float e = __expf(lg[i][j] - m); lg[i][j] = e; s += e; }
        #pragma unroll
        for (int o = 16; o; o >>= 1) s += __shfl_xor_sync(~0u, s, o);
        float inv = 1.f / s;
        for (int j = lane; j < KVLEN; j += 32) lg[i][j] *= inv;
    }
    __syncthreads();

    long abase = ((long)(win*HEADS + h))*64*KVLEN;
    for (int idx = tid; idx < 64*KVLEN; idx += 256) {
        int i = idx / KVLEN, j = idx - i*KVLEN;
        float p = lg[i][j];
        attn_out[abase + idx] = p;
        ph[i][j] = __float2half(p);
    }
    __syncthreads();

    {
        int mw = (warp >> 1)*16, nv = (warp & 1)*16;
        float acc[2][4] = {};
        #pragma unroll
        for (int kt = 0; kt < 5; kt++) {
            int k0 = kt*16;
            unsigned a[4];
            a[0] = *(const unsigned*)(&ph[mw+g][k0 + tg*2]);
            a[1] = *(const unsigned*)(&ph[mw+g+8][k0 + tg*2]);
            a[2] = *(const unsigned*)(&ph[mw+g][k0 + tg*2 + 8]);
            a[3] = *(const unsigned*)(&ph[mw+g+8][k0 + tg*2 + 8]);
            #pragma unroll
            for (int nt = 0; nt < 2; nt++) {
                int nb = nv + nt*8 + g;
                unsigned bb[2];
                bb[0] = *(const unsigned*)(&vt[nb][k0 + tg*2]);
                bb[1] = *(const unsigned*)(&vt[nb][k0 + tg*2 + 8]);
                mma_f16(acc[nt], a, bb);
            }
        }
        #pragma unroll
        for (int nt = 0; nt < 2; nt++) {
            #pragma unroll
            for (int c = 0; c < 4; c++) {
                int i = mw + g + (c >> 1)*8;
                int d = nv + nt*8 + tg*2 + (c & 1);
                int n = n_base + (i >> 3)*GRIDW + (i & 7);
                attouth[((long)b*NTOK + n)*CH + h*HD + d] = __float2half(acc[nt][c]);
            }
        }
    }
}

// ---------------- host launch ------------------------------------------
#define GEMM_SMEM (4*STG2*2)   // bytes: 4 stages x (A+B) halves

extern "C" void kernel_launch(void* const* d_in, const int* in_sizes, int n_in,
                              void* d_out, int out_size) {
    const float* x       = (const float*)d_in[0];
    const float* qtok    = (const float*)d_in[1];
    const float* kproj_w = (const float*)d_in[2];
    const float* kproj_b = (const float*)d_in[3];
    const float* kbn_g   = (const float*)d_in[4];
    const float* kbn_b   = (const float*)d_in[5];
    const float* kbn_m   = (const float*)d_in[6];
    const float* kbn_v   = (const float*)d_in[7];
    const float* vproj_w = (const float*)d_in[8];
    const float* vproj_b = (const float*)d_in[9];
    const float* vbn_g   = (const float*)d_in[10];
    const float* vbn_b   = (const float*)d_in[11];
    const float* vbn_m   = (const float*)d_in[12];
    const float* vbn_v   = (const float*)d_in[13];
    const float* ck_w    = (const float*)d_in[14];
    const float* ck_b    = (const float*)d_in[15];
    const float* cv_w    = (const float*)d_in[16];
    const float* cv_b    = (const float*)d_in[17];
    const float* rpb     = (const float*)d_in[18];
    const float* qkv_w   = (const float*)d_in[19];
    const float* qkv_b   = (const float*)d_in[20];
    const float* proj_w  = (const float*)d_in[21];
    const float* proj_b  = (const float*)d_in[22];
    const float* n1_g    = (const float*)d_in[23];
    const float* n1_b    = (const float*)d_in[24];
    const float* n2_g    = (const float*)d_in[25];
    const float* n2_b    = (const float*)d_in[26];
    const float* fc1_w   = (const float*)d_in[27];
    const float* fc1_b   = (const float*)d_in[28];
    const float* fc2_w   = (const float*)d_in[29];
    const float* fc2_b   = (const float*)d_in[30];

    float* out_x    = (float*)d_out;
    float* out_attn = out_x + (long)BATCH*NTOK*CH;

    float *xn, *kpool, *vpool, *gk, *gv, *xnew;
    __half *xnh, *xmh, *attouth, *hh, *qkvh, *pooledh, *qinh;
    cudaGetSymbolAddress((void**)&xn,      g_xn);
    cudaGetSymbolAddress((void**)&xnh,     g_xnh);
    cudaGetSymbolAddress((void**)&pooledh, g_pooledh);
    cudaGetSymbolAddress((void**)&kpool,   g_kpool);
    cudaGetSymbolAddress((void**)&vpool,   g_vpool);
    cudaGetSymbolAddress((void**)&qinh,    g_qinh);
    cudaGetSymbolAddress((void**)&gk,      g_gk);
    cudaGetSymbolAddress((void**)&gv,      g_gv);
    cudaGetSymbolAddress((void**)&qkvh,    g_qkvh);
    cudaGetSymbolAddress((void**)&attouth, g_attouth);
    cudaGetSymbolAddress((void**)&xnew,    g_xnew);
    cudaGetSymbolAddress((void**)&xmh,     g_xmh);
    cudaGetSymbolAddress((void**)&hh,      g_hh);

    __half *wqkv, *wfc1, *wfc2, *wproj, *wkp, *wvp, *wck, *wcv;
    cudaGetSymbolAddress((void**)&wqkv,  g_wqkv);
    cudaGetSymbolAddress((void**)&wfc1,  g_wfc1);
    cudaGetSymbolAddress((void**)&wfc2,  g_wfc2);
    cudaGetSymbolAddress((void**)&wproj, g_wproj);
    cudaGetSymbolAddress((void**)&wkp,   g_wkp);
    cudaGetSymbolAddress((void**)&wvp,   g_wvp);
    cudaGetSymbolAddress((void**)&wck,   g_wck);
    cudaGetSymbolAddress((void**)&wcv,   g_wcv);

    static int smem_set = 0;
    if (!smem_set) {
        cudaFuncSetAttribute(mma_gemm<0,1>, cudaFuncAttributeMaxDynamicSharedMemorySize, GEMM_SMEM);
        cudaFuncSetAttribute(mma_gemm<0,0>, cudaFuncAttributeMaxDynamicSharedMemorySize, GEMM_SMEM);
        cudaFuncSetAttribute(mma_gemm<1,0>, cudaFuncAttributeMaxDynamicSharedMemorySize, GEMM_SMEM);
        cudaFuncSetAttribute(mma_gemm<2,1>, cudaFuncAttributeMaxDynamicSharedMemorySize, GEMM_SMEM);
        cudaFuncSetAttribute(mma_gemm<3,0>, cudaFuncAttributeMaxDynamicSharedMemorySize, GEMM_SMEM);
        smem_set = 1;
    }

    const int M = BATCH*NTOK;   // 65536

    // merged weight conversion (one launch)
    WC wc;
    wc.s[0]=qkv_w;  wc.d[0]=wqkv;  wc.n4[0]=49152;
    wc.s[1]=fc1_w;  wc.d[1]=wfc1;  wc.n4[1]=65536;
    wc.s[2]=fc2_w;  wc.d[2]=wfc2;  wc.n4[2]=65536;
    wc.s[3]=proj_w; wc.d[3]=wproj; wc.n4[3]=16384;
    wc.s[4]=kproj_w;wc.d[4]=wkp;   wc.n4[4]=16384;
    wc.s[5]=vproj_w;wc.d[5]=wvp;   wc.n4[5]=16384;
    wc.s[6]=ck_w;   wc.d[6]=wck;   wc.n4[6]=16384;
    wc.s[7]=cv_w;   wc.d[7]=wcv;   wc.n4[7]=16384;
    wconv_all<<<dim3(256, 8), 256>>>(wc);

    // LN1: fp32 (for pool) + fp16 (for qkv GEMM)
    layernorm_kernel<2><<<M/8, 256>>>(x, n1_g, n1_b, xn, xnh);
    pool_kernel<<<BATCH*HP2, 256>>>(xn, pooledh);

    GP kp = {wkp, kproj_b, kpool, 0, kbn_m, kbn_v, kbn_g, kbn_b};
    GP vp = {wvp, vproj_b, vpool, 0, vbn_m, vbn_v, vbn_g, vbn_b};
    mma_gemm<1,0><<<dim3(2, 32, 2), 256, GEMM_SMEM>>>(pooledh, BATCH*HP2, CH, CH, kp, vp);

    global_attn_kernel<<<BATCH*HEADS, 256>>>(kpool, vpool, qtok, qinh);

    GP ckp = {wck, ck_b, gk, 0, 0, 0, 0, 0};
    GP cvp = {wcv, cv_b, gv, 0, 0, 0, 0, 0};
    mma_gemm<0,0><<<dim3(2, 1, 2), 256, GEMM_SMEM>>>(qinh, BATCH*NQ, CH, CH, ckp, cvp);

    // qkv projection -> fp16 buffer
    GP qkvp = {wqkv, qkv_b, 0, qkvh, 0, 0, 0, 0};
    mma_gemm<0,1><<<dim3(6, 512, 1), 256, GEMM_SMEM>>>(xnh, M, CH, 3*CH, qkvp, qkvp);

    window_attn_kernel<<<BATCH*NWIN*HEADS, 256>>>(qkvh, gk, gv, rpb, out_attn, attouth);

    GP projp = {wproj, proj_b, xnew, 0, x, 0, 0, 0};
    mma_gemm<3,0><<<dim3(2, 512, 1), 256, GEMM_SMEM>>>(attouth, M, CH, CH, projp, projp);

    // LN2: fp16 only (consumed by fc1)
    layernorm_kernel<1><<<M/8, 256>>>(xnew, n2_g, n2_b, 0, xmh);

    GP fc1p = {wfc1, fc1_b, 0, hh, 0, 0, 0, 0};
    mma_gemm<2,1><<<dim3(8, 512, 1), 256, GEMM_SMEM>>>(xmh, M, CH, 4*CH, fc1p, fc1p);

    GP fc2p = {wfc2, fc2_b, out_x, 0, xnew, 0, 0, 0};
    mma_gemm<3,0><<<dim3(2, 512, 1), 256, GEMM_SMEM>>>(hh, M, 4*CH, CH, fc2p, fc2p);
}

// round 14
// speedup vs baseline: 4.6236x; 1.0025x over previous
#include <cuda_runtime.h>
#include <cuda_fp16.h>
#include <math.h>

// ---------------- problem constants ----------------
#define BATCH   16
#define CH      256
#define NTOK    4096
#define GRIDW   64
#define HEADS   8
#define HD      32
#define NQ      8
#define WS      8
#define NWIN    64
#define KVLEN   72
#define HP2     256
#define SCALE   0.17677669529663687f

// ---------------- scratch ----------------
__device__ __half g_xnh  [(long)BATCH*NTOK*CH];
__device__ __half g_pooledh[(long)BATCH*HP2*CH];
__device__ float  g_kpool [(long)BATCH*HP2*CH];
__device__ float  g_vpool [(long)BATCH*HP2*CH];
__device__ __half g_qinh  [BATCH*NQ*CH];
__device__ float  g_gk    [BATCH*NQ*CH];
__device__ float  g_gv    [BATCH*NQ*CH];
__device__ __half g_qkvh [(long)BATCH*NTOK*3*CH];
__device__ __half g_attouth[(long)BATCH*NTOK*CH];
__device__ float  g_xnew [(long)BATCH*NTOK*CH];
__device__ __half g_xmh  [(long)BATCH*NTOK*CH];
__device__ __half g_hh   [(long)BATCH*NTOK*4*CH];

// fp16 weight copies
__device__ __half g_wqkv[768*256];
__device__ __half g_wfc1[1024*256];
__device__ __half g_wfc2[256*1024];
__device__ __half g_wproj[256*256];
__device__ __half g_wkp [256*256];
__device__ __half g_wvp [256*256];
__device__ __half g_wck [256*256];
__device__ __half g_wcv [256*256];

// ---------------- helpers ----------------
__device__ __forceinline__ void mma_f16(float* c, const unsigned* a, const unsigned* b) {
    asm volatile(
        "mma.sync.aligned.m16n8k16.row.col.f32.f16.f16.f32 "
        "{%0,%1,%2,%3}, {%4,%5,%6,%7}, {%8,%9}, {%0,%1,%2,%3};"
        : "+f"(c[0]), "+f"(c[1]), "+f"(c[2]), "+f"(c[3])
        : "r"(a[0]), "r"(a[1]), "r"(a[2]), "r"(a[3]), "r"(b[0]), "r"(b[1]));
}

__device__ __forceinline__ void ldsm_x4(unsigned* r, const void* p) {
    unsigned a = (unsigned)__cvta_generic_to_shared(p);
    asm volatile("ldmatrix.sync.aligned.m8n8.x4.shared.b16 {%0,%1,%2,%3}, [%4];"
                 : "=r"(r[0]), "=r"(r[1]), "=r"(r[2]), "=r"(r[3]) : "r"(a));
}

__device__ __forceinline__ void cp16(void* dst, const void* src) {
    unsigned d = (unsigned)__cvta_generic_to_shared(dst);
    asm volatile("cp.async.cg.shared.global [%0], [%1], 16;" :: "r"(d), "l"(src));
}
__device__ __forceinline__ void cp_commit() {
    asm volatile("cp.async.commit_group;");
}
__device__ __forceinline__ void cp_wait3() {
    asm volatile("cp.async.wait_group 3;");
}

// ---------------- merged weight fp32 -> fp16 conversion ----------------
struct WC { const float* s[8]; __half* d[8]; int n4[8]; };

__global__ void wconv_all(WC wc) {
    int seg = blockIdx.y;
    int i = blockIdx.x*256 + threadIdx.x;
    if (i < wc.n4[seg]) {
        float4 v = ((const float4*)wc.s[seg])[i];
        __half2 a = __floats2half2_rn(v.x, v.y);
        __half2 b = __floats2half2_rn(v.z, v.w);
        uint2 u;
        u.x = *(unsigned*)&a;
        u.y = *(unsigned*)&b;
        ((uint2*)wc.d[seg])[i] = u;
    }
}

// ---------------- layernorm: warp per row, shfl-only, fp16 out ---------
__global__ void layernorm_kernel(const float* __restrict__ x,
                                 const float* __restrict__ g,
                                 const float* __restrict__ b,
                                 __half* __restrict__ outh) {
    long row = (long)blockIdx.x*8 + (threadIdx.x >> 5);
    int lane = threadIdx.x & 31;
    const float4* xr = (const float4*)(x + row*CH);
    float4 v0 = xr[lane], v1 = xr[lane + 32];
    float s = v0.x+v0.y+v0.z+v0.w + v1.x+v1.y+v1.z+v1.w;
    #pragma unroll
    for (int o = 16; o; o >>= 1) s += __shfl_xor_sync(~0u, s, o);
    float m = s * (1.f/CH);
    float d0x=v0.x-m, d0y=v0.y-m, d0z=v0.z-m, d0w=v0.w-m;
    float d1x=v1.x-m, d1y=v1.y-m, d1z=v1.z-m, d1w=v1.w-m;
    float q = d0x*d0x+d0y*d0y+d0z*d0z+d0w*d0w + d1x*d1x+d1y*d1y+d1z*d1z+d1w*d1w;
    #pragma unroll
    for (int o = 16; o; o >>= 1) q += __shfl_xor_sync(~0u, q, o);
    float r = rsqrtf(q * (1.f/CH) + 1e-5f);
    const float4* gr = (const float4*)g;
    const float4* br = (const float4*)b;
    float4 g0 = gr[lane], g1 = gr[lane+32], b0 = br[lane], b1 = br[lane+32];
    float o0x = d0x*r*g0.x + b0.x, o0y = d0y*r*g0.y + b0.y;
    float o0z = d0z*r*g0.z + b0.z, o0w = d0w*r*g0.w + b0.w;
    float o1x = d1x*r*g1.x + b1.x, o1y = d1y*r*g1.y + b1.y;
    float o1z = d1z*r*g1.z + b1.z, o1w = d1w*r*g1.w + b1.w;
    __half2 h0 = __floats2half2_rn(o0x, o0y);
    __half2 h1 = __floats2half2_rn(o0z, o0w);
    __half2 h2 = __floats2half2_rn(o1x, o1y);
    __half2 h3 = __floats2half2_rn(o1z, o1w);
    uint2 u0, u1;
    u0.x = *(unsigned*)&h0; u0.y = *(unsigned*)&h1;
    u1.x = *(unsigned*)&h2; u1.y = *(unsigned*)&h3;
    uint2* hrow = (uint2*)(outh + row*CH);
    hrow[lane] = u0; hrow[lane+32] = u1;
}

// ---------------- 4x4 avg pool (fp16 in/out) ----------------
__global__ void pool_kernel(const __half* __restrict__ xnh, __half* __restrict__ pooledh) {
    int bidx = blockIdx.x;
    int b = bidx >> 8, hw = bidx & 255;
    int py = hw >> 4, px = hw & 15;
    int c = threadIdx.x;
    float s = 0.f;
    #pragma unroll
    for (int dy = 0; dy < 4; dy++)
        #pragma unroll
        for (int dx = 0; dx < 4; dx++) {
            int n = (py*4 + dy)*GRIDW + px*4 + dx;
            s += __half2float(xnh[((long)b*NTOK + n)*CH + c]);
        }
    pooledh[(long)bidx*CH + c] = __float2half(s * (1.f/16.f));
}

// ---------------- fp16 5-stage GEMM (mma.sync m16n8k16 + ldmatrix) -----
// out[M,O] = A[M,K]fp16 @ Wh[O,K]^T + bias. BM=BN=128, BK=32. 256 thr.
// 5-stage cp.async ring, wait_group 3, one __syncthreads per chunk.
#define PADH 40
#define TSTG (128*PADH)
#define STG2 (2*TSTG)
#define NSTAGE 5

struct GP {
    const __half* W; const float* bias; float* out; __half* outh;
    const float* e0; const float* e1; const float* e2; const float* e3;
};

template<int EPI, int OH>
__global__ void __launch_bounds__(256, 2)
mma_gemm(const __half* __restrict__ Agh, int M, int K, int O, GP p0, GP p1) {
    extern __shared__ __half hsm[];   // [NSTAGE][A | B]

    const GP* P = blockIdx.z ? &p1 : &p0;
    const __half* __restrict__ W = P->W;

    int tid  = threadIdx.x;
    int warp = tid >> 5, lane = tid & 31;
    int wm = warp >> 2, wn = warp & 3;
    int m_warp = wm * 64, n_warp = wn * 32;
    int g = lane >> 2, tg = lane & 3;

    int m0 = blockIdx.y * 128;
    int o0 = blockIdx.x * 128;

    int br_ = tid >> 2;
    int bg = tid & 3;

    int a_row = lane & 15;
    int a_kh  = (lane >> 4) << 3;
    int b_row = ((lane >> 4) << 3) + (lane & 7);
    int b_kh  = ((lane >> 3) & 1) << 3;

    float acc[4][4][4] = {};
    int NC = K >> 5;

    // prologue: issue chunks 0..3 into stages 0..3
    #pragma unroll
    for (int p = 0; p < 4; p++) {
        __half* As = hsm + p*STG2;
        __half* Bs = As + TSTG;
        #pragma unroll
        for (int i = 0; i < 2; i++) {
            int row = br_ + i*64;
            cp16(As + row*PADH + bg*8, Agh + (long)(m0 + row)*K + p*32 + bg*8);
            cp16(Bs + row*PADH + bg*8, W + (long)(o0 + row)*K + p*32 + bg*8);
        }
        cp_commit();
    }

    int sidx = 0;                 // stage of chunk c
    int fidx = 4;                 // stage for chunk c+4
    for (int c = 0; c < NC; c++) {
        cp_wait3();
        __syncthreads();

        if (c + 4 < NC) {
            __half* As = hsm + fidx*STG2;
            __half* Bs = As + TSTG;
            #pragma unroll
            for (int i = 0; i < 2; i++) {
                int row = br_ + i*64;
                cp16(As + row*PADH + bg*8, Agh + (long)(m0 + row)*K + (c+4)*32 + bg*8);
                cp16(Bs + row*PADH + bg*8, W + (long)(o0 + row)*K + (c+4)*32 + bg*8);
            }
        }
        cp_commit();

        const __half* Ab = hsm + sidx*STG2;
        const __half* Bb = Ab + TSTG;
        #pragma unroll
        for (int kt = 0; kt < 2; kt++) {
            int k0 = kt*16;
            unsigned af[4][4], bf[4][2];
            #pragma unroll
            for (int mt = 0; mt < 4; mt++)
                ldsm_x4(af[mt], Ab + (m_warp + mt*16 + a_row)*PADH + k0 + a_kh);
            #pragma unroll
            for (int p2 = 0; p2 < 2; p2++) {
                unsigned r[4];
                ldsm_x4(r, Bb + (n_warp + p2*16 + b_row)*PADH + k0 + b_kh);
                bf[p2*2+0][0] = r[0]; bf[p2*2+0][1] = r[1];
                bf[p2*2+1][0] = r[2]; bf[p2*2+1][1] = r[3];
            }
            #pragma unroll
            for (int mt = 0; mt < 4; mt++)
                #pragma unroll
                for (int nt = 0; nt < 4; nt++)
                    mma_f16(acc[mt][nt], af[mt], bf[nt]);
        }
        if (++sidx == NSTAGE) sidx = 0;
        if (++fidx == NSTAGE) fidx = 0;
    }

    const float* __restrict__ bias = P->bias;
    float* __restrict__ out = P->out;
    __half* __restrict__ outh = P->outh;
    const float* e0 = P->e0;
    const float* e1 = P->e1;
    const float* e2 = P->e2;
    const float* e3 = P->e3;

    #pragma unroll
    for (int mt = 0; mt < 4; mt++) {
        #pragma unroll
        for (int nt = 0; nt < 4; nt++) {
            #pragma unroll
            for (int c2 = 0; c2 < 2; c2++) {
                int m = m0 + m_warp + mt*16 + g + c2*8;
                int o = o0 + n_warp + nt*8 + tg*2;
                float y0 = acc[mt][nt][c2*2+0] + bias[o];
                float y1 = acc[mt][nt][c2*2+1] + bias[o+1];
                if (EPI == 1) {
                    y0 = (y0 - e0[o])   * rsqrtf(e1[o]   + 1e-5f) * e2[o]   + e3[o];
                    y1 = (y1 - e0[o+1]) * rsqrtf(e1[o+1] + 1e-5f) * e2[o+1] + e3[o+1];
                } else if (EPI == 2) {
                    y0 = 0.5f*y0*(1.f + erff(y0*0.70710678118654752f));
                    y1 = 0.5f*y1*(1.f + erff(y1*0.70710678118654752f));
                } else if (EPI == 3) {
                    float2 rv = *(const float2*)(e0 + (long)m*O + o);
                    y0 += rv.x; y1 += rv.y;
                }
                if (OH) {
                    __half2 hv = __floats2half2_rn(y0, y1);
                    *(__half2*)(outh + (long)m*O + o) = hv;
                } else {
                    float2 v; v.x = y0; v.y = y1;
                    *(float2*)(out + (long)m*O + o) = v;
                }
            }
        }
    }
}

// ---------------- global cross-attention pooling path -----------------
__global__ void global_attn_kernel(const float* __restrict__ kpool,
                                   const float* __restrict__ vpool,
                                   const float* __restrict__ qtok,
                                   __half* __restrict__ qinh) {
    int b = blockIdx.x >> 3, h = blockIdx.x & 7;
    __shared__ float qs[NQ][HD];
    __shared__ float lg[NQ][HP2];
    __shared__ float vsm[HP2][HD];
    int tid = threadIdx.x;
    { int q = tid >> 5, d = tid & 31; qs[q][d] = qtok[q*CH + h*HD + d]; }
    for (int idx = tid; idx < HP2*HD; idx += 256) {
        int r = idx >> 5, d = idx & 31;
        vsm[r][d] = vpool[((long)b*HP2 + r)*CH + h*HD + d];
    }
    __syncthreads();
    float kreg[HD];
    const float* kr = kpool + ((long)b*HP2 + tid)*CH + h*HD;
    #pragma unroll
    for (int d = 0; d < HD; d++) kreg[d] = kr[d];
    #pragma unroll
    for (int q = 0; q < NQ; q++) {
        float s = 0.f;
        #pragma unroll
        for (int d = 0; d < HD; d++) s = fmaf(qs[q][d], kreg[d], s);
        lg[q][tid] = s * SCALE;
    }
    __syncthreads();
    int w = tid >> 5, lane = tid & 31;
    {
        float m = -1e30f;
        for (int j = lane; j < HP2; j += 32) m = fmaxf(m, lg[w][j]);
        #pragma unroll
        for (int o = 16; o; o >>= 1) m = fmaxf(m, __shfl_xor_sync(~0u, m, o));
        float s = 0.f;
        for (int j = lane; j < HP2; j += 32) { float e = __expf(lg[w][j] - m); lg[w][j] = e; s += e; }
        #pragma unroll
        for (int o = 16; o; o >>= 1) s += __shfl_xor_sync(~0u, s, o);
        float inv = 1.f / s;
        for (int j = lane; j < HP2; j += 32) lg[w][j] *= inv;
    }
    __syncthreads();
    int q = tid >> 5, d = tid & 31;
    float acc = 0.f;
    for (int kk = 0; kk < HP2; kk++) acc = fmaf(lg[q][kk], vsm[kk][d], acc);
    qinh[(b*NQ + q)*CH + h*HD + d] = __float2half(acc + qtok[q*CH + h*HD + d]);
}

// ---------------- window attention (fp16 tensor-core) ------------------
#define PADQ 40
#define PADP 88

__global__ void __launch_bounds__(256)
window_attn_kernel(const __half* __restrict__ qkvh,
                   const float* __restrict__ gk,
                   const float* __restrict__ gv,
                   const float* __restrict__ rpb,
                   float* __restrict__ attn_out,
                   __half* __restrict__ attouth) {
    int h   = blockIdx.x & 7;
    int win = blockIdx.x >> 3;
    int wx = win & 7, wy = (win >> 3) & 7, b = win >> 6;
    int n_base = (wy*WS)*GRIDW + wx*WS;

    __shared__ __half qs[64][PADQ];
    __shared__ __half ks[80][PADQ];
    __shared__ __half vt[32][PADP];
    __shared__ __half ph[64][PADP];
    __shared__ float  lg[64][80];

    int tid = threadIdx.x;
    int warp = tid >> 5, lane = tid & 31;
    int g = lane >> 2, tg = lane & 3;

    for (int idx = tid; idx < 64*32; idx += 256) {
        int i = idx >> 5, d = idx & 31;
        int n = n_base + (i >> 3)*GRIDW + (i & 7);
        float qv = __half2float(qkvh[((long)b*NTOK + n)*(3*CH) + h*HD + d]);
        qs[i][d] = __float2half(qv * SCALE);
    }
    for (int idx = tid; idx < 80*32; idx += 256) {
        int j = idx >> 5, d = idx & 31;
        float kv = 0.f, vv = 0.f;
        if (j < 64) {
            int n = n_base + (j >> 3)*GRIDW + (j & 7);
            long base = ((long)b*NTOK + n)*(3*CH) + h*HD + d;
            kv = __half2float(qkvh[base + CH]);
            vv = __half2float(qkvh[base + 2*CH]);
        } else if (j < 72) {
            int nq = j - 64;
            kv = gk[(b*NQ + nq)*CH + h*HD + d];
            vv = gv[(b*NQ + nq)*CH + h*HD + d];
        }
        ks[j][d] = __float2half(kv);
        vt[d][j] = __float2half(vv);
    }
    for (int idx = tid; idx < 64*8; idx += 256) {
        int i = idx >> 3, jj = idx & 7;
        ph[i][72 + jj] = __float2half(0.f);
    }
    __syncthreads();

    {
        int mw = (warp >> 1)*16, np = (warp & 1)*40;
        float acc[5][4] = {};
        #pragma unroll
        for (int kt = 0; kt < 2; kt++) {
            int k0 = kt*16;
            unsigned a[4];
            a[0] = *(const unsigned*)(&qs[mw+g][k0 + tg*2]);
            a[1] = *(const unsigned*)(&qs[mw+g+8][k0 + tg*2]);
            a[2] = *(const unsigned*)(&qs[mw+g][k0 + tg*2 + 8]);
            a[3] = *(const unsigned*)(&qs[mw+g+8][k0 + tg*2 + 8]);
            #pragma unroll
            for (int nt = 0; nt < 5; nt++) {
                int nb = np + nt*8 + g;
                unsigned bb[2];
                bb[0] = *(const unsigned*)(&ks[nb][k0 + tg*2]);
                bb[1] = *(const unsigned*)(&ks[nb][k0 + tg*2 + 8]);
                mma_f16(acc[nt], a, bb);
            }
        }
        #pragma unroll
        for (int nt = 0; nt < 5; nt++) {
            #pragma unroll
            for (int c = 0; c < 4; c++) {
                int i = mw + g + (c >> 1)*8;
                int j = np + nt*8 + tg*2 + (c & 1);
                float s = acc[nt][c];
                if (j < 64) {
                    int diy = (i >> 3) - (j >> 3) + 7;
                    int dix = (i & 7) - (j & 7) + 7;
                    s += rpb[(diy*15 + dix)*HEADS + h];
                }
                lg[i][j] = s;
            }
        }
    }
    __syncthreads();

    for (int it = 0; it < 8; it++) {
        int i = it*8 + warp;
        float m = -1e30f;
        for (int j = lane; j < KVLEN; j += 32) m = fmaxf(m, lg[i][j]);
        #pragma unroll
        for (int o = 16; o; o >>= 1) m = fmaxf(m, __shfl_xor_sync(~0u, m, o));
        float s = 0.f;
        for (int j = lane; j < KVLEN; j += 32) { float e = __expf(lg[i][j] - m); lg[i][j] = e; s += e; }
        #pragma unroll
        for (int o = 16; o; o >>= 1) s += __shfl_xor_sync(~0u, s, o);
        float inv = 1.f / s;
        for (int j = lane; j < KVLEN; j += 32) lg[i][j] *= inv;
    }
    __syncthreads();

    long abase = ((long)(win*HEADS + h))*64*KVLEN;
    for (int idx = tid; idx < 64*KVLEN; idx += 256) {
        int i = idx / KVLEN, j = idx - i*KVLEN;
        float p = lg[i][j];
        attn_out[abase + idx] = p;
        ph[i][j] = __float2half(p);
    }
    __syncthreads();

    {
        int mw = (warp >> 1)*16, nv = (warp & 1)*16;
        float acc[2][4] = {};
        #pragma unroll
        for (int kt = 0; kt < 5; kt++) {
            int k0 = kt*16;
            unsigned a[4];
            a[0] = *(const unsigned*)(&ph[mw+g][k0 + tg*2]);
            a[1] = *(const unsigned*)(&ph[mw+g+8][k0 + tg*2]);
            a[2] = *(const unsigned*)(&ph[mw+g][k0 + tg*2 + 8]);
            a[3] = *(const unsigned*)(&ph[mw+g+8][k0 + tg*2 + 8]);
            #pragma unroll
            for (int nt = 0; nt < 2; nt++) {
                int nb = nv + nt*8 + g;
                unsigned bb[2];
                bb[0] = *(const unsigned*)(&vt[nb][k0 + tg*2]);
                bb[1] = *(const unsigned*)(&vt[nb][k0 + tg*2 + 8]);
                mma_f16(acc[nt], a, bb);
            }
        }
        #pragma unroll
        for (int nt = 0; nt < 2; nt++) {
            #pragma unroll
            for (int c = 0; c < 4; c++) {
                int i = mw + g + (c >> 1)*8;
                int d = nv + nt*8 + tg*2 + (c & 1);
                int n = n_base + (i >> 3)*GRIDW + (i & 7);
                attouth[((long)b*NTOK + n)*CH + h*HD + d] = __float2half(acc[nt][c]);
            }
        }
    }
}

// ---------------- host launch ------------------------------------------
#define GEMM_SMEM (NSTAGE*STG2*2)   // bytes

extern "C" void kernel_launch(void* const* d_in, const int* in_sizes, int n_in,
                              void* d_out, int out_size) {
    const float* x       = (const float*)d_in[0];
    const float* qtok    = (const float*)d_in[1];
    const float* kproj_w = (const float*)d_in[2];
    const float* kproj_b = (const float*)d_in[3];
    const float* kbn_g   = (const float*)d_in[4];
    const float* kbn_b   = (const float*)d_in[5];
    const float* kbn_m   = (const float*)d_in[6];
    const float* kbn_v   = (const float*)d_in[7];
    const float* vproj_w = (const float*)d_in[8];
    const float* vproj_b = (const float*)d_in[9];
    const float* vbn_g   = (const float*)d_in[10];
    const float* vbn_b   = (const float*)d_in[11];
    const float* vbn_m   = (const float*)d_in[12];
    const float* vbn_v   = (const float*)d_in[13];
    const float* ck_w    = (const float*)d_in[14];
    const float* ck_b    = (const float*)d_in[15];
    const float* cv_w    = (const float*)d_in[16];
    const float* cv_b    = (const float*)d_in[17];
    const float* rpb     = (const float*)d_in[18];
    const float* qkv_w   = (const float*)d_in[19];
    const float* qkv_b   = (const float*)d_in[20];
    const float* proj_w  = (const float*)d_in[21];
    const float* proj_b  = (const float*)d_in[22];
    const float* n1_g    = (const float*)d_in[23];
    const float* n1_b    = (const float*)d_in[24];
    const float* n2_g    = (const float*)d_in[25];
    const float* n2_b    = (const float*)d_in[26];
    const float* fc1_w   = (const float*)d_in[27];
    const float* fc1_b   = (const float*)d_in[28];
    const float* fc2_w   = (const float*)d_in[29];
    const float* fc2_b   = (const float*)d_in[30];

    float* out_x    = (float*)d_out;
    float* out_attn = out_x + (long)BATCH*NTOK*CH;

    float *kpool, *vpool, *gk, *gv, *xnew;
    __half *xnh, *xmh, *attouth, *hh, *qkvh, *pooledh, *qinh;
    cudaGetSymbolAddress((void**)&xnh,     g_xnh);
    cudaGetSymbolAddress((void**)&pooledh, g_pooledh);
    cudaGetSymbolAddress((void**)&kpool,   g_kpool);
    cudaGetSymbolAddress((void**)&vpool,   g_vpool);
    cudaGetSymbolAddress((void**)&qinh,    g_qinh);
    cudaGetSymbolAddress((void**)&gk,      g_gk);
    cudaGetSymbolAddress((void**)&gv,      g_gv);
    cudaGetSymbolAddress((void**)&qkvh,    g_qkvh);
    cudaGetSymbolAddress((void**)&attouth, g_attouth);
    cudaGetSymbolAddress((void**)&xnew,    g_xnew);
    cudaGetSymbolAddress((void**)&xmh,     g_xmh);
    cudaGetSymbolAddress((void**)&hh,      g_hh);

    __half *wqkv, *wfc1, *wfc2, *wproj, *wkp, *wvp, *wck, *wcv;
    cudaGetSymbolAddress((void**)&wqkv,  g_wqkv);
    cudaGetSymbolAddress((void**)&wfc1,  g_wfc1);
    cudaGetSymbolAddress((void**)&wfc2,  g_wfc2);
    cudaGetSymbolAddress((void**)&wproj, g_wproj);
    cudaGetSymbolAddress((void**)&wkp,   g_wkp);
    cudaGetSymbolAddress((void**)&wvp,   g_wvp);
    cudaGetSymbolAddress((void**)&wck,   g_wck);
    cudaGetSymbolAddress((void**)&wcv,   g_wcv);

    static int smem_set = 0;
    if (!smem_set) {
        cudaFuncSetAttribute(mma_gemm<0,1>, cudaFuncAttributeMaxDynamicSharedMemorySize, GEMM_SMEM);
        cudaFuncSetAttribute(mma_gemm<0,0>, cudaFuncAttributeMaxDynamicSharedMemorySize, GEMM_SMEM);
        cudaFuncSetAttribute(mma_gemm<1,0>, cudaFuncAttributeMaxDynamicSharedMemorySize, GEMM_SMEM);
        cudaFuncSetAttribute(mma_gemm<2,1>, cudaFuncAttributeMaxDynamicSharedMemorySize, GEMM_SMEM);
        cudaFuncSetAttribute(mma_gemm<3,0>, cudaFuncAttributeMaxDynamicSharedMemorySize, GEMM_SMEM);
        smem_set = 1;
    }

    const int M = BATCH*NTOK;   // 65536

    // merged weight conversion (one launch)
    WC wc;
    wc.s[0]=qkv_w;  wc.d[0]=wqkv;  wc.n4[0]=49152;
    wc.s[1]=fc1_w;  wc.d[1]=wfc1;  wc.n4[1]=65536;
    wc.s[2]=fc2_w;  wc.d[2]=wfc2;  wc.n4[2]=65536;
    wc.s[3]=proj_w; wc.d[3]=wproj; wc.n4[3]=16384;
    wc.s[4]=kproj_w;wc.d[4]=wkp;   wc.n4[4]=16384;
    wc.s[5]=vproj_w;wc.d[5]=wvp;   wc.n4[5]=16384;
    wc.s[6]=ck_w;   wc.d[6]=wck;   wc.n4[6]=16384;
    wc.s[7]=cv_w;   wc.d[7]=wcv;   wc.n4[7]=16384;
    wconv_all<<<dim3(256, 8), 256>>>(wc);

    // LN1 -> fp16 only
    layernorm_kernel<<<M/8, 256>>>(x, n1_g, n1_b, xnh);
    pool_kernel<<<BATCH*HP2, 256>>>(xnh, pooledh);

    GP kp = {wkp, kproj_b, kpool, 0, kbn_m, kbn_v, kbn_g, kbn_b};
    GP vp = {wvp, vproj_b, vpool, 0, vbn_m, vbn_v, vbn_g, vbn_b};
    mma_gemm<1,0><<<dim3(2, 32, 2), 256, GEMM_SMEM>>>(pooledh, BATCH*HP2, CH, CH, kp, vp);

    global_attn_kernel<<<BATCH*HEADS, 256>>>(kpool, vpool, qtok, qinh);

    GP ckp = {wck, ck_b, gk, 0, 0, 0, 0, 0};
    GP cvp = {wcv, cv_b, gv, 0, 0, 0, 0, 0};
    mma_gemm<0,0><<<dim3(2, 1, 2), 256, GEMM_SMEM>>>(qinh, BATCH*NQ, CH, CH, ckp, cvp);

    // qkv projection -> fp16 buffer
    GP qkvp = {wqkv, qkv_b, 0, qkvh, 0, 0, 0, 0};
    mma_gemm<0,1><<<dim3(6, 512, 1), 256, GEMM_SMEM>>>(xnh, M, CH, 3*CH, qkvp, qkvp);

    window_attn_kernel<<<BATCH*NWIN*HEADS, 256>>>(qkvh, gk, gv, rpb, out_attn, attouth);

    GP projp = {wproj, proj_b, xnew, 0, x, 0, 0, 0};
    mma_gemm<3,0><<<dim3(2, 512, 1), 256, GEMM_SMEM>>>(attouth, M, CH, CH, projp, projp);

    // LN2 -> fp16 (consumed by fc1)
    layernorm_kernel<<<M/8, 256>>>(xnew, n2_g, n2_b, xmh);

    GP fc1p = {wfc1, fc1_b, 0, hh, 0, 0, 0, 0};
    mma_gemm<2,1><<<dim3(8, 512, 1), 256, GEMM_SMEM>>>(xmh, M, CH, 4*CH, fc1p, fc1p);

    GP fc2p = {wfc2, fc2_b, out_x, 0, xnew, 0, 0, 0};
    mma_gemm<3,0><<<dim3(2, 512, 1), 256, GEMM_SMEM>>>(hh, M, 4*CH, CH, fc2p, fc2p);
}

// round 15
// speedup vs baseline: 4.6591x; 1.0077x over previous
#include <cuda_runtime.h>
#include <cuda_fp16.h>
#include <math.h>

// ---------------- problem constants ----------------
#define BATCH   16
#define CH      256
#define NTOK    4096
#define GRIDW   64
#define HEADS   8
#define HD      32
#define NQ      8
#define WS      8
#define NWIN    64
#define KVLEN   72
#define HP2     256
#define SCALE   0.17677669529663687f

// ---------------- scratch ----------------
__device__ __half g_xnh  [(long)BATCH*NTOK*CH];
__device__ __half g_pooledh[(long)BATCH*HP2*CH];
__device__ float  g_kpool [(long)BATCH*HP2*CH];
__device__ float  g_vpool [(long)BATCH*HP2*CH];
__device__ __half g_qinh  [BATCH*NQ*CH];
__device__ float  g_gk    [BATCH*NQ*CH];
__device__ float  g_gv    [BATCH*NQ*CH];
__device__ __half g_qkvh [(long)BATCH*NTOK*3*CH];
__device__ __half g_attouth[(long)BATCH*NTOK*CH];
__device__ float  g_xnew [(long)BATCH*NTOK*CH];
__device__ __half g_xmh  [(long)BATCH*NTOK*CH];
__device__ __half g_hh   [(long)BATCH*NTOK*4*CH];

// fp16 weight copies
__device__ __half g_wqkv[768*256];
__device__ __half g_wfc1[1024*256];
__device__ __half g_wfc2[256*1024];
__device__ __half g_wproj[256*256];
__device__ __half g_wkp [256*256];
__device__ __half g_wvp [256*256];
__device__ __half g_wck [256*256];
__device__ __half g_wcv [256*256];

// ---------------- helpers ----------------
__device__ __forceinline__ void mma_f16(float* c, const unsigned* a, const unsigned* b) {
    asm volatile(
        "mma.sync.aligned.m16n8k16.row.col.f32.f16.f16.f32 "
        "{%0,%1,%2,%3}, {%4,%5,%6,%7}, {%8,%9}, {%0,%1,%2,%3};"
        : "+f"(c[0]), "+f"(c[1]), "+f"(c[2]), "+f"(c[3])
        : "r"(a[0]), "r"(a[1]), "r"(a[2]), "r"(a[3]), "r"(b[0]), "r"(b[1]));
}

__device__ __forceinline__ void ldsm_x4(unsigned* r, const void* p) {
    unsigned a = (unsigned)__cvta_generic_to_shared(p);
    asm volatile("ldmatrix.sync.aligned.m8n8.x4.shared.b16 {%0,%1,%2,%3}, [%4];"
                 : "=r"(r[0]), "=r"(r[1]), "=r"(r[2]), "=r"(r[3]) : "r"(a));
}

__device__ __forceinline__ void cp16(void* dst, const void* src) {
    unsigned d = (unsigned)__cvta_generic_to_shared(dst);
    asm volatile("cp.async.cg.shared.global [%0], [%1], 16;" :: "r"(d), "l"(src));
}
__device__ __forceinline__ void cp_commit() {
    asm volatile("cp.async.commit_group;");
}
__device__ __forceinline__ void cp_wait3() {
    asm volatile("cp.async.wait_group 3;");
}

// ---------------- merged weight fp32 -> fp16 conversion ----------------
struct WC { const float* s[8]; __half* d[8]; int n4[8]; };

__global__ void wconv_all(WC wc) {
    int seg = blockIdx.y;
    int i = blockIdx.x*256 + threadIdx.x;
    if (i < wc.n4[seg]) {
        float4 v = ((const float4*)wc.s[seg])[i];
        __half2 a = __floats2half2_rn(v.x, v.y);
        __half2 b = __floats2half2_rn(v.z, v.w);
        uint2 u;
        u.x = *(unsigned*)&a;
        u.y = *(unsigned*)&b;
        ((uint2*)wc.d[seg])[i] = u;
    }
}

// ---------------- layernorm: warp per row, shfl-only, fp16 out ---------
__global__ void layernorm_kernel(const float* __restrict__ x,
                                 const float* __restrict__ g,
                                 const float* __restrict__ b,
                                 __half* __restrict__ outh) {
    long row = (long)blockIdx.x*8 + (threadIdx.x >> 5);
    int lane = threadIdx.x & 31;
    const float4* xr = (const float4*)(x + row*CH);
    float4 v0 = xr[lane], v1 = xr[lane + 32];
    float s = v0.x+v0.y+v0.z+v0.w + v1.x+v1.y+v1.z+v1.w;
    #pragma unroll
    for (int o = 16; o; o >>= 1) s += __shfl_xor_sync(~0u, s, o);
    float m = s * (1.f/CH);
    float d0x=v0.x-m, d0y=v0.y-m, d0z=v0.z-m, d0w=v0.w-m;
    float d1x=v1.x-m, d1y=v1.y-m, d1z=v1.z-m, d1w=v1.w-m;
    float q = d0x*d0x+d0y*d0y+d0z*d0z+d0w*d0w + d1x*d1x+d1y*d1y+d1z*d1z+d1w*d1w;
    #pragma unroll
    for (int o = 16; o; o >>= 1) q += __shfl_xor_sync(~0u, q, o);
    float r = rsqrtf(q * (1.f/CH) + 1e-5f);
    const float4* gr = (const float4*)g;
    const float4* br = (const float4*)b;
    float4 g0 = gr[lane], g1 = gr[lane+32], b0 = br[lane], b1 = br[lane+32];
    float o0x = d0x*r*g0.x + b0.x, o0y = d0y*r*g0.y + b0.y;
    float o0z = d0z*r*g0.z + b0.z, o0w = d0w*r*g0.w + b0.w;
    float o1x = d1x*r*g1.x + b1.x, o1y = d1y*r*g1.y + b1.y;
    float o1z = d1z*r*g1.z + b1.z, o1w = d1w*r*g1.w + b1.w;
    __half2 h0 = __floats2half2_rn(o0x, o0y);
    __half2 h1 = __floats2half2_rn(o0z, o0w);
    __half2 h2 = __floats2half2_rn(o1x, o1y);
    __half2 h3 = __floats2half2_rn(o1z, o1w);
    uint2 u0, u1;
    u0.x = *(unsigned*)&h0; u0.y = *(unsigned*)&h1;
    u1.x = *(unsigned*)&h2; u1.y = *(unsigned*)&h3;
    uint2* hrow = (uint2*)(outh + row*CH);
    hrow[lane] = u0; hrow[lane+32] = u1;
}

// ---------------- 4x4 avg pool (fp16 in/out) ----------------
__global__ void pool_kernel(const __half* __restrict__ xnh, __half* __restrict__ pooledh) {
    int bidx = blockIdx.x;
    int b = bidx >> 8, hw = bidx & 255;
    int py = hw >> 4, px = hw & 15;
    int c = threadIdx.x;
    float s = 0.f;
    #pragma unroll
    for (int dy = 0; dy < 4; dy++)
        #pragma unroll
        for (int dx = 0; dx < 4; dx++) {
            int n = (py*4 + dy)*GRIDW + px*4 + dx;
            s += __half2float(xnh[((long)b*NTOK + n)*CH + c]);
        }
    pooledh[(long)bidx*CH + c] = __float2half(s * (1.f/16.f));
}

// ---------------- fp16 5-stage GEMM (mma.sync m16n8k16 + ldmatrix) -----
#define PADH 40
#define TSTG (128*PADH)
#define STG2 (2*TSTG)
#define NSTAGE 5

struct GP {
    const __half* W; const float* bias; float* out; __half* outh;
    const float* e0; const float* e1; const float* e2; const float* e3;
};

template<int EPI, int OH>
__global__ void __launch_bounds__(256, 2)
mma_gemm(const __half* __restrict__ Agh, int M, int K, int O, GP p0, GP p1) {
    extern __shared__ __half hsm[];   // [NSTAGE][A | B]

    const GP* P = blockIdx.z ? &p1 : &p0;
    const __half* __restrict__ W = P->W;

    int tid  = threadIdx.x;
    int warp = tid >> 5, lane = tid & 31;
    int wm = warp >> 2, wn = warp & 3;
    int m_warp = wm * 64, n_warp = wn * 32;
    int g = lane >> 2, tg = lane & 3;

    int m0 = blockIdx.y * 128;
    int o0 = blockIdx.x * 128;

    int br_ = tid >> 2;
    int bg = tid & 3;

    int a_row = lane & 15;
    int a_kh  = (lane >> 4) << 3;
    int b_row = ((lane >> 4) << 3) + (lane & 7);
    int b_kh  = ((lane >> 3) & 1) << 3;

    float acc[4][4][4] = {};
    int NC = K >> 5;

    #pragma unroll
    for (int p = 0; p < 4; p++) {
        __half* As = hsm + p*STG2;
        __half* Bs = As + TSTG;
        #pragma unroll
        for (int i = 0; i < 2; i++) {
            int row = br_ + i*64;
            cp16(As + row*PADH + bg*8, Agh + (long)(m0 + row)*K + p*32 + bg*8);
            cp16(Bs + row*PADH + bg*8, W + (long)(o0 + row)*K + p*32 + bg*8);
        }
        cp_commit();
    }

    int sidx = 0;
    int fidx = 4;
    for (int c = 0; c < NC; c++) {
        cp_wait3();
        __syncthreads();

        if (c + 4 < NC) {
            __half* As = hsm + fidx*STG2;
            __half* Bs = As + TSTG;
            #pragma unroll
            for (int i = 0; i < 2; i++) {
                int row = br_ + i*64;
                cp16(As + row*PADH + bg*8, Agh + (long)(m0 + row)*K + (c+4)*32 + bg*8);
                cp16(Bs + row*PADH + bg*8, W + (long)(o0 + row)*K + (c+4)*32 + bg*8);
            }
        }
        cp_commit();

        const __half* Ab = hsm + sidx*STG2;
        const __half* Bb = Ab + TSTG;
        #pragma unroll
        for (int kt = 0; kt < 2; kt++) {
            int k0 = kt*16;
            unsigned af[4][4], bf[4][2];
            #pragma unroll
            for (int mt = 0; mt < 4; mt++)
                ldsm_x4(af[mt], Ab + (m_warp + mt*16 + a_row)*PADH + k0 + a_kh);
            #pragma unroll
            for (int p2 = 0; p2 < 2; p2++) {
                unsigned r[4];
                ldsm_x4(r, Bb + (n_warp + p2*16 + b_row)*PADH + k0 + b_kh);
                bf[p2*2+0][0] = r[0]; bf[p2*2+0][1] = r[1];
                bf[p2*2+1][0] = r[2]; bf[p2*2+1][1] = r[3];
            }
            #pragma unroll
            for (int mt = 0; mt < 4; mt++)
                #pragma unroll
                for (int nt = 0; nt < 4; nt++)
                    mma_f16(acc[mt][nt], af[mt], bf[nt]);
        }
        if (++sidx == NSTAGE) sidx = 0;
        if (++fidx == NSTAGE) fidx = 0;
    }

    const float* __restrict__ bias = P->bias;
    float* __restrict__ out = P->out;
    __half* __restrict__ outh = P->outh;
    const float* e0 = P->e0;
    const float* e1 = P->e1;
    const float* e2 = P->e2;
    const float* e3 = P->e3;

    #pragma unroll
    for (int mt = 0; mt < 4; mt++) {
        #pragma unroll
        for (int nt = 0; nt < 4; nt++) {
            #pragma unroll
            for (int c2 = 0; c2 < 2; c2++) {
                int m = m0 + m_warp + mt*16 + g + c2*8;
                int o = o0 + n_warp + nt*8 + tg*2;
                float y0 = acc[mt][nt][c2*2+0] + bias[o];
                float y1 = acc[mt][nt][c2*2+1] + bias[o+1];
                if (EPI == 1) {
                    y0 = (y0 - e0[o])   * rsqrtf(e1[o]   + 1e-5f) * e2[o]   + e3[o];
                    y1 = (y1 - e0[o+1]) * rsqrtf(e1[o+1] + 1e-5f) * e2[o+1] + e3[o+1];
                } else if (EPI == 2) {
                    y0 = 0.5f*y0*(1.f + erff(y0*0.70710678118654752f));
                    y1 = 0.5f*y1*(1.f + erff(y1*0.70710678118654752f));
                } else if (EPI == 3) {
                    float2 rv = *(const float2*)(e0 + (long)m*O + o);
                    y0 += rv.x; y1 += rv.y;
                }
                if (OH) {
                    __half2 hv = __floats2half2_rn(y0, y1);
                    *(__half2*)(outh + (long)m*O + o) = hv;
                } else {
                    float2 v; v.x = y0; v.y = y1;
                    *(float2*)(out + (long)m*O + o) = v;
                }
            }
        }
    }
}

// ---------------- global cross-attention pooling path -----------------
__global__ void global_attn_kernel(const float* __restrict__ kpool,
                                   const float* __restrict__ vpool,
                                   const float* __restrict__ qtok,
                                   __half* __restrict__ qinh) {
    int b = blockIdx.x >> 3, h = blockIdx.x & 7;
    __shared__ float qs[NQ][HD];
    __shared__ float lg[NQ][HP2];
    __shared__ float vsm[HP2][HD];
    int tid = threadIdx.x;
    { int q = tid >> 5, d = tid & 31; qs[q][d] = qtok[q*CH + h*HD + d]; }
    for (int idx = tid; idx < HP2*HD; idx += 256) {
        int r = idx >> 5, d = idx & 31;
        vsm[r][d] = vpool[((long)b*HP2 + r)*CH + h*HD + d];
    }
    __syncthreads();
    float kreg[HD];
    const float* kr = kpool + ((long)b*HP2 + tid)*CH + h*HD;
    #pragma unroll
    for (int d = 0; d < HD; d++) kreg[d] = kr[d];
    #pragma unroll
    for (int q = 0; q < NQ; q++) {
        float s = 0.f;
        #pragma unroll
        for (int d = 0; d < HD; d++) s = fmaf(qs[q][d], kreg[d], s);
        lg[q][tid] = s * SCALE;
    }
    __syncthreads();
    int w = tid >> 5, lane = tid & 31;
    {
        float m = -1e30f;
        for (int j = lane; j < HP2; j += 32) m = fmaxf(m, lg[w][j]);
        #pragma unroll
        for (int o = 16; o; o >>= 1) m = fmaxf(m, __shfl_xor_sync(~0u, m, o));
        float s = 0.f;
        for (int j = lane; j < HP2; j += 32) { float e = __expf(lg[w][j] - m); lg[w][j] = e; s += e; }
        #pragma unroll
        for (int o = 16; o; o >>= 1) s += __shfl_xor_sync(~0u, s, o);
        float inv = 1.f / s;
        for (int j = lane; j < HP2; j += 32) lg[w][j] *= inv;
    }
    __syncthreads();
    int q = tid >> 5, d = tid & 31;
    float acc = 0.f;
    for (int kk = 0; kk < HP2; kk++) acc = fmaf(lg[q][kk], vsm[kk][d], acc);
    qinh[(b*NQ + q)*CH + h*HD + d] = __float2half(acc + qtok[q*CH + h*HD + d]);
}

// ---------------- window attention (fp16 tensor-core) ------------------
#define PADQ 40
#define PADP 88

__global__ void __launch_bounds__(256)
window_attn_kernel(const __half* __restrict__ qkvh,
                   const float* __restrict__ gk,
                   const float* __restrict__ gv,
                   const float* __restrict__ rpb,
                   float* __restrict__ attn_out,
                   __half* __restrict__ attouth) {
    int h   = blockIdx.x & 7;
    int win = blockIdx.x >> 3;
    int wx = win & 7, wy = (win >> 3) & 7, b = win >> 6;
    int n_base = (wy*WS)*GRIDW + wx*WS;

    __shared__ __half qs[64][PADQ];
    __shared__ __half ks[80][PADQ];
    __shared__ __half vt[32][PADP];
    __shared__ __half ph[64][PADP];
    __shared__ float  lg[64][80];

    int tid = threadIdx.x;
    int warp = tid >> 5, lane = tid & 31;
    int g = lane >> 2, tg = lane & 3;

    for (int idx = tid; idx < 64*32; idx += 256) {
        int i = idx >> 5, d = idx & 31;
        int n = n_base + (i >> 3)*GRIDW + (i & 7);
        float qv = __half2float(qkvh[((long)b*NTOK + n)*(3*CH) + h*HD + d]);
        qs[i][d] = __float2half(qv * SCALE);
    }
    for (int idx = tid; idx < 80*32; idx += 256) {
        int j = idx >> 5, d = idx & 31;
        float kv = 0.f, vv = 0.f;
        if (j < 64) {
            int n = n_base + (j >> 3)*GRIDW + (j & 7);
            long base = ((long)b*NTOK + n)*(3*CH) + h*HD + d;
            kv = __half2float(qkvh[base + CH]);
            vv = __half2float(qkvh[base + 2*CH]);
        } else if (j < 72) {
            int nq = j - 64;
            kv = gk[(b*NQ + nq)*CH + h*HD + d];
            vv = gv[(b*NQ + nq)*CH + h*HD + d];
        }
        ks[j][d] = __float2half(kv);
        vt[d][j] = __float2half(vv);
    }
    for (int idx = tid; idx < 64*8; idx += 256) {
        int i = idx >> 3, jj = idx & 7;
        ph[i][72 + jj] = __float2half(0.f);
    }
    __syncthreads();

    {
        int mw = (warp >> 1)*16, np = (warp & 1)*40;
        float acc[5][4] = {};
        #pragma unroll
        for (int kt = 0; kt < 2; kt++) {
            int k0 = kt*16;
            unsigned a[4];
            a[0] = *(const unsigned*)(&qs[mw+g][k0 + tg*2]);
            a[1] = *(const unsigned*)(&qs[mw+g+8][k0 + tg*2]);
            a[2] = *(const unsigned*)(&qs[mw+g][k0 + tg*2 + 8]);
            a[3] = *(const unsigned*)(&qs[mw+g+8][k0 + tg*2 + 8]);
            #pragma unroll
            for (int nt = 0; nt < 5; nt++) {
                int nb = np + nt*8 + g;
                unsigned bb[2];
                bb[0] = *(const unsigned*)(&ks[nb][k0 + tg*2]);
                bb[1] = *(const unsigned*)(&ks[nb][k0 + tg*2 + 8]);
                mma_f16(acc[nt], a, bb);
            }
        }
        #pragma unroll
        for (int nt = 0; nt < 5; nt++) {
            #pragma unroll
            for (int c = 0; c < 4; c++) {
                int i = mw + g + (c >> 1)*8;
                int j = np + nt*8 + tg*2 + (c & 1);
                float s = acc[nt][c];
                if (j < 64) {
                    int diy = (i >> 3) - (j >> 3) + 7;
                    int dix = (i & 7) - (j & 7) + 7;
                    s += rpb[(diy*15 + dix)*HEADS + h];
                }
                lg[i][j] = s;
            }
        }
    }
    __syncthreads();

    for (int it = 0; it < 8; it++) {
        int i = it*8 + warp;
        float m = -1e30f;
        for (int j = lane; j < KVLEN; j += 32) m = fmaxf(m, lg[i][j]);
        #pragma unroll
        for (int o = 16; o; o >>= 1) m = fmaxf(m, __shfl_xor_sync(~0u, m, o));
        float s = 0.f;
        for (int j = lane; j < KVLEN; j += 32) { float e = __expf(lg[i][j] - m); lg[i][j] = e; s += e; }
        #pragma unroll
        for (int o = 16; o; o >>= 1) s += __shfl_xor_sync(~0u, s, o);
        float inv = 1.f / s;
        for (int j = lane; j < KVLEN; j += 32) lg[i][j] *= inv;
    }
    __syncthreads();

    long abase = ((long)(win*HEADS + h))*64*KVLEN;
    for (int idx = tid; idx < 64*KVLEN; idx += 256) {
        int i = idx / KVLEN, j = idx - i*KVLEN;
        float p = lg[i][j];
        attn_out[abase + idx] = p;
        ph[i][j] = __float2half(p);
    }
    __syncthreads();

    {
        int mw = (warp >> 1)*16, nv = (warp & 1)*16;
        float acc[2][4] = {};
        #pragma unroll
        for (int kt = 0; kt < 5; kt++) {
            int k0 = kt*16;
            unsigned a[4];
            a[0] = *(const unsigned*)(&ph[mw+g][k0 + tg*2]);
            a[1] = *(const unsigned*)(&ph[mw+g+8][k0 + tg*2]);
            a[2] = *(const unsigned*)(&ph[mw+g][k0 + tg*2 + 8]);
            a[3] = *(const unsigned*)(&ph[mw+g+8][k0 + tg*2 + 8]);
            #pragma unroll
            for (int nt = 0; nt < 2; nt++) {
                int nb = nv + nt*8 + g;
                unsigned bb[2];
                bb[0] = *(const unsigned*)(&vt[nb][k0 + tg*2]);
                bb[1] = *(const unsigned*)(&vt[nb][k0 + tg*2 + 8]);
                mma_f16(acc[nt], a, bb);
            }
        }
        #pragma unroll
        for (int nt = 0; nt < 2; nt++) {
            #pragma unroll
            for (int c = 0; c < 4; c++) {
                int i = mw + g + (c >> 1)*8;
                int d = nv + nt*8 + tg*2 + (c & 1);
                int n = n_base + (i >> 3)*GRIDW + (i & 7);
                attouth[((long)b*NTOK + n)*CH + h*HD + d] = __float2half(acc[nt][c]);
            }
        }
    }
}

// ---------------- host launch ------------------------------------------
#define GEMM_SMEM (NSTAGE*STG2*2)

extern "C" void kernel_launch(void* const* d_in, const int* in_sizes, int n_in,
                              void* d_out, int out_size) {
    const float* x       = (const float*)d_in[0];
    const float* qtok    = (const float*)d_in[1];
    const float* kproj_w = (const float*)d_in[2];
    const float* kproj_b = (const float*)d_in[3];
    const float* kbn_g   = (const float*)d_in[4];
    const float* kbn_b   = (const float*)d_in[5];
    const float* kbn_m   = (const float*)d_in[6];
    const float* kbn_v   = (const float*)d_in[7];
    const float* vproj_w = (const float*)d_in[8];
    const float* vproj_b = (const float*)d_in[9];
    const float* vbn_g   = (const float*)d_in[10];
    const float* vbn_b   = (const float*)d_in[11];
    const float* vbn_m   = (const float*)d_in[12];
    const float* vbn_v   = (const float*)d_in[13];
    const float* ck_w    = (const float*)d_in[14];
    const float* ck_b    = (const float*)d_in[15];
    const float* cv_w    = (const float*)d_in[16];
    const float* cv_b    = (const float*)d_in[17];
    const float* rpb     = (const float*)d_in[18];
    const float* qkv_w   = (const float*)d_in[19];
    const float* qkv_b   = (const float*)d_in[20];
    const float* proj_w  = (const float*)d_in[21];
    const float* proj_b  = (const float*)d_in[22];
    const float* n1_g    = (const float*)d_in[23];
    const float* n1_b    = (const float*)d_in[24];
    const float* n2_g    = (const float*)d_in[25];
    const float* n2_b    = (const float*)d_in[26];
    const float* fc1_w   = (const float*)d_in[27];
    const float* fc1_b   = (const float*)d_in[28];
    const float* fc2_w   = (const float*)d_in[29];
    const float* fc2_b   = (const float*)d_in[30];

    float* out_x    = (float*)d_out;
    float* out_attn = out_x + (long)BATCH*NTOK*CH;

    float *kpool, *vpool, *gk, *gv, *xnew;
    __half *xnh, *xmh, *attouth, *hh, *qkvh, *pooledh, *qinh;
    cudaGetSymbolAddress((void**)&xnh,     g_xnh);
    cudaGetSymbolAddress((void**)&pooledh, g_pooledh);
    cudaGetSymbolAddress((void**)&kpool,   g_kpool);
    cudaGetSymbolAddress((void**)&vpool,   g_vpool);
    cudaGetSymbolAddress((void**)&qinh,    g_qinh);
    cudaGetSymbolAddress((void**)&gk,      g_gk);
    cudaGetSymbolAddress((void**)&gv,      g_gv);
    cudaGetSymbolAddress((void**)&qkvh,    g_qkvh);
    cudaGetSymbolAddress((void**)&attouth, g_attouth);
    cudaGetSymbolAddress((void**)&xnew,    g_xnew);
    cudaGetSymbolAddress((void**)&xmh,     g_xmh);
    cudaGetSymbolAddress((void**)&hh,      g_hh);

    __half *wqkv, *wfc1, *wfc2, *wproj, *wkp, *wvp, *wck, *wcv;
    cudaGetSymbolAddress((void**)&wqkv,  g_wqkv);
    cudaGetSymbolAddress((void**)&wfc1,  g_wfc1);
    cudaGetSymbolAddress((void**)&wfc2,  g_wfc2);
    cudaGetSymbolAddress((void**)&wproj, g_wproj);
    cudaGetSymbolAddress((void**)&wkp,   g_wkp);
    cudaGetSymbolAddress((void**)&wvp,   g_wvp);
    cudaGetSymbolAddress((void**)&wck,   g_wck);
    cudaGetSymbolAddress((void**)&wcv,   g_wcv);

    static int init_done = 0;
    static cudaStream_t s_side;
    static cudaEvent_t ev_fork, ev_join;
    if (!init_done) {
        cudaFuncSetAttribute(mma_gemm<0,1>, cudaFuncAttributeMaxDynamicSharedMemorySize, GEMM_SMEM);
        cudaFuncSetAttribute(mma_gemm<0,0>, cudaFuncAttributeMaxDynamicSharedMemorySize, GEMM_SMEM);
        cudaFuncSetAttribute(mma_gemm<1,0>, cudaFuncAttributeMaxDynamicSharedMemorySize, GEMM_SMEM);
        cudaFuncSetAttribute(mma_gemm<2,1>, cudaFuncAttributeMaxDynamicSharedMemorySize, GEMM_SMEM);
        cudaFuncSetAttribute(mma_gemm<3,0>, cudaFuncAttributeMaxDynamicSharedMemorySize, GEMM_SMEM);
        cudaStreamCreateWithFlags(&s_side, cudaStreamNonBlocking);
        cudaEventCreateWithFlags(&ev_fork, cudaEventDisableTiming);
        cudaEventCreateWithFlags(&ev_join, cudaEventDisableTiming);
        init_done = 1;
    }

    const int M = BATCH*NTOK;   // 65536

    // merged weight conversion (one launch)
    WC wc;
    wc.s[0]=qkv_w;  wc.d[0]=wqkv;  wc.n4[0]=49152;
    wc.s[1]=fc1_w;  wc.d[1]=wfc1;  wc.n4[1]=65536;
    wc.s[2]=fc2_w;  wc.d[2]=wfc2;  wc.n4[2]=65536;
    wc.s[3]=proj_w; wc.d[3]=wproj; wc.n4[3]=16384;
    wc.s[4]=kproj_w;wc.d[4]=wkp;   wc.n4[4]=16384;
    wc.s[5]=vproj_w;wc.d[5]=wvp;   wc.n4[5]=16384;
    wc.s[6]=ck_w;   wc.d[6]=wck;   wc.n4[6]=16384;
    wc.s[7]=cv_w;   wc.d[7]=wcv;   wc.n4[7]=16384;
    wconv_all<<<dim3(256, 8), 256>>>(wc);

    // LN1 -> fp16
    layernorm_kernel<<<M/8, 256>>>(x, n1_g, n1_b, xnh);

    // ---- fork: side stream runs the global-token branch ----
    cudaEventRecord(ev_fork, 0);
    cudaStreamWaitEvent(s_side, ev_fork, 0);

    pool_kernel<<<BATCH*HP2, 256, 0, s_side>>>(xnh, pooledh);
    GP kp = {wkp, kproj_b, kpool, 0, kbn_m, kbn_v, kbn_g, kbn_b};
    GP vp = {wvp, vproj_b, vpool, 0, vbn_m, vbn_v, vbn_g, vbn_b};
    mma_gemm<1,0><<<dim3(2, 32, 2), 256, GEMM_SMEM, s_side>>>(pooledh, BATCH*HP2, CH, CH, kp, vp);
    global_attn_kernel<<<BATCH*HEADS, 256, 0, s_side>>>(kpool, vpool, qtok, qinh);
    GP ckp = {wck, ck_b, gk, 0, 0, 0, 0, 0};
    GP cvp = {wcv, cv_b, gv, 0, 0, 0, 0, 0};
    mma_gemm<0,0><<<dim3(2, 1, 2), 256, GEMM_SMEM, s_side>>>(qinh, BATCH*NQ, CH, CH, ckp, cvp);
    cudaEventRecord(ev_join, s_side);

    // ---- main stream: qkv projection (overlaps with side branch) ----
    GP qkvp = {wqkv, qkv_b, 0, qkvh, 0, 0, 0, 0};
    mma_gemm<0,1><<<dim3(6, 512, 1), 256, GEMM_SMEM>>>(xnh, M, CH, 3*CH, qkvp, qkvp);

    // ---- join ----
    cudaStreamWaitEvent(0, ev_join, 0);

    window_attn_kernel<<<BATCH*NWIN*HEADS, 256>>>(qkvh, gk, gv, rpb, out_attn, attouth);

    GP projp = {wproj, proj_b, xnew, 0, x, 0, 0, 0};
    mma_gemm<3,0><<<dim3(2, 512, 1), 256, GEMM_SMEM>>>(attouth, M, CH, CH, projp, projp);

    layernorm_kernel<<<M/8, 256>>>(xnew, n2_g, n2_b, xmh);

    GP fc1p = {wfc1, fc1_b, 0, hh, 0, 0, 0, 0};
    mma_gemm<2,1><<<dim3(8, 512, 1), 256, GEMM_SMEM>>>(xmh, M, CH, 4*CH, fc1p, fc1p);

    GP fc2p = {wfc2, fc2_b, out_x, 0, xnew, 0, 0, 0};
    mma_gemm<3,0><<<dim3(2, 512, 1), 256, GEMM_SMEM>>>(hh, M, 4*CH, CH, fc2p, fc2p);
}

// round 16
// speedup vs baseline: 4.9544x; 1.0634x over previous
#include <cuda_runtime.h>
#include <cuda_fp16.h>
#include <math.h>

// ---------------- problem constants ----------------
#define BATCH   16
#define CH      256
#define NTOK    4096
#define GRIDW   64
#define HEADS   8
#define HD      32
#define NQ      8
#define WS      8
#define NWIN    64
#define KVLEN   72
#define HP2     256
#define SCALE   0.17677669529663687f

// ---------------- scratch ----------------
__device__ __half g_xnh  [(long)BATCH*NTOK*CH];
__device__ __half g_pooledh[(long)BATCH*HP2*CH];
__device__ float  g_kpool [(long)BATCH*HP2*CH];
__device__ float  g_vpool [(long)BATCH*HP2*CH];
__device__ __half g_qinh  [BATCH*NQ*CH];
__device__ float  g_gk    [BATCH*NQ*CH];
__device__ float  g_gv    [BATCH*NQ*CH];
__device__ __half g_qkvh [(long)BATCH*NTOK*3*CH];
__device__ __half g_attouth[(long)BATCH*NTOK*CH];
__device__ float  g_xnew [(long)BATCH*NTOK*CH];
__device__ __half g_xmh  [(long)BATCH*NTOK*CH];
__device__ __half g_hh   [(long)BATCH*NTOK*4*CH];

// fp16 weight copies
__device__ __half g_wqkv[768*256];
__device__ __half g_wfc1[1024*256];
__device__ __half g_wfc2[256*1024];
__device__ __half g_wproj[256*256];
__device__ __half g_wkp [256*256];
__device__ __half g_wvp [256*256];
__device__ __half g_wck [256*256];
__device__ __half g_wcv [256*256];

// ---------------- helpers ----------------
__device__ __forceinline__ void mma_f16(float* c, const unsigned* a, const unsigned* b) {
    asm volatile(
        "mma.sync.aligned.m16n8k16.row.col.f32.f16.f16.f32 "
        "{%0,%1,%2,%3}, {%4,%5,%6,%7}, {%8,%9}, {%0,%1,%2,%3};"
        : "+f"(c[0]), "+f"(c[1]), "+f"(c[2]), "+f"(c[3])
        : "r"(a[0]), "r"(a[1]), "r"(a[2]), "r"(a[3]), "r"(b[0]), "r"(b[1]));
}

__device__ __forceinline__ void ldsm_x4(unsigned* r, const void* p) {
    unsigned a = (unsigned)__cvta_generic_to_shared(p);
    asm volatile("ldmatrix.sync.aligned.m8n8.x4.shared.b16 {%0,%1,%2,%3}, [%4];"
                 : "=r"(r[0]), "=r"(r[1]), "=r"(r[2]), "=r"(r[3]) : "r"(a));
}

__device__ __forceinline__ void cp16(void* dst, const void* src) {
    unsigned d = (unsigned)__cvta_generic_to_shared(dst);
    asm volatile("cp.async.cg.shared.global [%0], [%1], 16;" :: "r"(d), "l"(src));
}
__device__ __forceinline__ void cp_commit() {
    asm volatile("cp.async.commit_group;");
}
__device__ __forceinline__ void cp_wait1() {
    asm volatile("cp.async.wait_group 1;");
}

// ---------------- merged weight fp32 -> fp16 conversion ----------------
struct WC { const float* s[8]; __half* d[8]; int n4[8]; };

__global__ void wconv_all(WC wc) {
    int seg = blockIdx.y;
    int i = blockIdx.x*256 + threadIdx.x;
    if (i < wc.n4[seg]) {
        float4 v = ((const float4*)wc.s[seg])[i];
        __half2 a = __floats2half2_rn(v.x, v.y);
        __half2 b = __floats2half2_rn(v.z, v.w);
        uint2 u;
        u.x = *(unsigned*)&a;
        u.y = *(unsigned*)&b;
        ((uint2*)wc.d[seg])[i] = u;
    }
}

// ---------------- layernorm: warp per row, shfl-only, fp16 out ---------
__global__ void layernorm_kernel(const float* __restrict__ x,
                                 const float* __restrict__ g,
                                 const float* __restrict__ b,
                                 __half* __restrict__ outh) {
    long row = (long)blockIdx.x*8 + (threadIdx.x >> 5);
    int lane = threadIdx.x & 31;
    const float4* xr = (const float4*)(x + row*CH);
    float4 v0 = xr[lane], v1 = xr[lane + 32];
    float s = v0.x+v0.y+v0.z+v0.w + v1.x+v1.y+v1.z+v1.w;
    #pragma unroll
    for (int o = 16; o; o >>= 1) s += __shfl_xor_sync(~0u, s, o);
    float m = s * (1.f/CH);
    float d0x=v0.x-m, d0y=v0.y-m, d0z=v0.z-m, d0w=v0.w-m;
    float d1x=v1.x-m, d1y=v1.y-m, d1z=v1.z-m, d1w=v1.w-m;
    float q = d0x*d0x+d0y*d0y+d0z*d0z+d0w*d0w + d1x*d1x+d1y*d1y+d1z*d1z+d1w*d1w;
    #pragma unroll
    for (int o = 16; o; o >>= 1) q += __shfl_xor_sync(~0u, q, o);
    float r = rsqrtf(q * (1.f/CH) + 1e-5f);
    const float4* gr = (const float4*)g;
    const float4* br = (const float4*)b;
    float4 g0 = gr[lane], g1 = gr[lane+32], b0 = br[lane], b1 = br[lane+32];
    float o0x = d0x*r*g0.x + b0.x, o0y = d0y*r*g0.y + b0.y;
    float o0z = d0z*r*g0.z + b0.z, o0w = d0w*r*g0.w + b0.w;
    float o1x = d1x*r*g1.x + b1.x, o1y = d1y*r*g1.y + b1.y;
    float o1z = d1z*r*g1.z + b1.z, o1w = d1w*r*g1.w + b1.w;
    __half2 h0 = __floats2half2_rn(o0x, o0y);
    __half2 h1 = __floats2half2_rn(o0z, o0w);
    __half2 h2 = __floats2half2_rn(o1x, o1y);
    __half2 h3 = __floats2half2_rn(o1z, o1w);
    uint2 u0, u1;
    u0.x = *(unsigned*)&h0; u0.y = *(unsigned*)&h1;
    u1.x = *(unsigned*)&h2; u1.y = *(unsigned*)&h3;
    uint2* hrow = (uint2*)(outh + row*CH);
    hrow[lane] = u0; hrow[lane+32] = u1;
}

// ---------------- 4x4 avg pool (fp16 in/out) ----------------
__global__ void pool_kernel(const __half* __restrict__ xnh, __half* __restrict__ pooledh) {
    int bidx = blockIdx.x;
    int b = bidx >> 8, hw = bidx & 255;
    int py = hw >> 4, px = hw & 15;
    int c = threadIdx.x;
    float s = 0.f;
    #pragma unroll
    for (int dy = 0; dy < 4; dy++)
        #pragma unroll
        for (int dx = 0; dx < 4; dx++) {
            int n = (py*4 + dy)*GRIDW + px*4 + dx;
            s += __half2float(xnh[((long)b*NTOK + n)*CH + c]);
        }
    pooledh[(long)bidx*CH + c] = __float2half(s * (1.f/16.f));
}

// ---------------- fp16 3-stage GEMM, BK=64 (mma.sync + ldmatrix) -------
// out[M,O] = A[M,K]fp16 @ Wh[O,K]^T + bias. BM=BN=128, BK=64. 256 thr.
// 3-stage cp.async ring, wait_group 1, one __syncthreads per chunk.
#define PADH 72                  // 64 + 8 halves pad (144B row)
#define TSTG (128*PADH)          // halves per matrix per stage
#define STG2 (2*TSTG)
#define NSTAGE 3

struct GP {
    const __half* W; const float* bias; float* out; __half* outh;
    const float* e0; const float* e1; const float* e2; const float* e3;
};

template<int EPI, int OH>
__global__ void __launch_bounds__(256, 2)
mma_gemm(const __half* __restrict__ Agh, int M, int K, int O, GP p0, GP p1) {
    extern __shared__ __half hsm[];   // [NSTAGE][A | B]

    const GP* P = blockIdx.z ? &p1 : &p0;
    const __half* __restrict__ W = P->W;

    int tid  = threadIdx.x;
    int warp = tid >> 5, lane = tid & 31;
    int wm = warp >> 2, wn = warp & 3;
    int m_warp = wm * 64, n_warp = wn * 32;
    int g = lane >> 2, tg = lane & 3;

    int m0 = blockIdx.y * 128;
    int o0 = blockIdx.x * 128;

    // loader: 128 rows x 8 granules (16B) per matrix; 4 iters A + 4 iters B
    int lrow = tid >> 1;              // two threads per row... no: 1024 granules
    // idx = tid + i*256; row = idx >> 3; gran = idx & 7
    int bg = tid & 7;
    int br_ = tid >> 3;               // 0..31, +32 per iter

    int a_row = lane & 15;
    int a_kh  = (lane >> 4) << 3;
    int b_row = ((lane >> 4) << 3) + (lane & 7);
    int b_kh  = ((lane >> 3) & 1) << 3;
    (void)lrow;

    float acc[4][4][4] = {};
    int NC = K >> 6;                  // chunks of 64

    // prologue: chunks 0,1 into stages 0,1
    #pragma unroll
    for (int p = 0; p < 2; p++) {
        __half* As = hsm + p*STG2;
        __half* Bs = As + TSTG;
        #pragma unroll
        for (int i = 0; i < 4; i++) {
            int row = br_ + i*32;
            cp16(As + row*PADH + bg*8, Agh + (long)(m0 + row)*K + p*64 + bg*8);
            cp16(Bs + row*PADH + bg*8, W + (long)(o0 + row)*K + p*64 + bg*8);
        }
        cp_commit();
    }

    int sidx = 0;
    int fidx = 2;
    for (int c = 0; c < NC; c++) {
        cp_wait1();
        __syncthreads();

        if (c + 2 < NC) {
            __half* As = hsm + fidx*STG2;
            __half* Bs = As + TSTG;
            #pragma unroll
            for (int i = 0; i < 4; i++) {
                int row = br_ + i*32;
                cp16(As + row*PADH + bg*8, Agh + (long)(m0 + row)*K + (c+2)*64 + bg*8);
                cp16(Bs + row*PADH + bg*8, W + (long)(o0 + row)*K + (c+2)*64 + bg*8);
            }
        }
        cp_commit();

        const __half* Ab = hsm + sidx*STG2;
        const __half* Bb = Ab + TSTG;
        #pragma unroll
        for (int kt = 0; kt < 4; kt++) {
            int k0 = kt*16;
            unsigned af[4][4], bf[4][2];
            #pragma unroll
            for (int mt = 0; mt < 4; mt++)
                ldsm_x4(af[mt], Ab + (m_warp + mt*16 + a_row)*PADH + k0 + a_kh);
            #pragma unroll
            for (int p2 = 0; p2 < 2; p2++) {
                unsigned r[4];
                ldsm_x4(r, Bb + (n_warp + p2*16 + b_row)*PADH + k0 + b_kh);
                bf[p2*2+0][0] = r[0]; bf[p2*2+0][1] = r[1];
                bf[p2*2+1][0] = r[2]; bf[p2*2+1][1] = r[3];
            }
            #pragma unroll
            for (int mt = 0; mt < 4; mt++)
                #pragma unroll
                for (int nt = 0; nt < 4; nt++)
                    mma_f16(acc[mt][nt], af[mt], bf[nt]);
        }
        if (++sidx == NSTAGE) sidx = 0;
        if (++fidx == NSTAGE) fidx = 0;
    }

    const float* __restrict__ bias = P->bias;
    float* __restrict__ out = P->out;
    __half* __restrict__ outh = P->outh;
    const float* e0 = P->e0;
    const float* e1 = P->e1;
    const float* e2 = P->e2;
    const float* e3 = P->e3;

    #pragma unroll
    for (int mt = 0; mt < 4; mt++) {
        #pragma unroll
        for (int nt = 0; nt < 4; nt++) {
            #pragma unroll
            for (int c2 = 0; c2 < 2; c2++) {
                int m = m0 + m_warp + mt*16 + g + c2*8;
                int o = o0 + n_warp + nt*8 + tg*2;
                float y0 = acc[mt][nt][c2*2+0] + bias[o];
                float y1 = acc[mt][nt][c2*2+1] + bias[o+1];
                if (EPI == 1) {
                    y0 = (y0 - e0[o])   * rsqrtf(e1[o]   + 1e-5f) * e2[o]   + e3[o];
                    y1 = (y1 - e0[o+1]) * rsqrtf(e1[o+1] + 1e-5f) * e2[o+1] + e3[o+1];
                } else if (EPI == 2) {
                    y0 = 0.5f*y0*(1.f + erff(y0*0.70710678118654752f));
                    y1 = 0.5f*y1*(1.f + erff(y1*0.70710678118654752f));
                } else if (EPI == 3) {
                    float2 rv = *(const float2*)(e0 + (long)m*O + o);
                    y0 += rv.x; y1 += rv.y;
                }
                if (OH) {
                    __half2 hv = __floats2half2_rn(y0, y1);
                    *(__half2*)(outh + (long)m*O + o) = hv;
                } else {
                    float2 v; v.x = y0; v.y = y1;
                    *(float2*)(out + (long)m*O + o) = v;
                }
            }
        }
    }
}

// ---------------- global cross-attention pooling path -----------------
__global__ void global_attn_kernel(const float* __restrict__ kpool,
                                   const float* __restrict__ vpool,
                                   const float* __restrict__ qtok,
                                   __half* __restrict__ qinh) {
    int b = blockIdx.x >> 3, h = blockIdx.x & 7;
    __shared__ float qs[NQ][HD];
    __shared__ float lg[NQ][HP2];
    __shared__ float vsm[HP2][HD];
    int tid = threadIdx.x;
    { int q = tid >> 5, d = tid & 31; qs[q][d] = qtok[q*CH + h*HD + d]; }
    for (int idx = tid; idx < HP2*HD; idx += 256) {
        int r = idx >> 5, d = idx & 31;
        vsm[r][d] = vpool[((long)b*HP2 + r)*CH + h*HD + d];
    }
    __syncthreads();
    float kreg[HD];
    const float* kr = kpool + ((long)b*HP2 + tid)*CH + h*HD;
    #pragma unroll
    for (int d = 0; d < HD; d++) kreg[d] = kr[d];
    #pragma unroll
    for (int q = 0; q < NQ; q++) {
        float s = 0.f;
        #pragma unroll
        for (int d = 0; d < HD; d++) s = fmaf(qs[q][d], kreg[d], s);
        lg[q][tid] = s * SCALE;
    }
    __syncthreads();
    int w = tid >> 5, lane = tid & 31;
    {
        float m = -1e30f;
        for (int j = lane; j < HP2; j += 32) m = fmaxf(m, lg[w][j]);
        #pragma unroll
        for (int o = 16; o; o >>= 1) m = fmaxf(m, __shfl_xor_sync(~0u, m, o));
        float s = 0.f;
        for (int j = lane; j < HP2; j += 32) { float e = __expf(lg[w][j] - m); lg[w][j] = e; s += e; }
        #pragma unroll
        for (int o = 16; o; o >>= 1) s += __shfl_xor_sync(~0u, s, o);
        float inv = 1.f / s;
        for (int j = lane; j < HP2; j += 32) lg[w][j] *= inv;
    }
    __syncthreads();
    int q = tid >> 5, d = tid & 31;
    float acc = 0.f;
    for (int kk = 0; kk < HP2; kk++) acc = fmaf(lg[q][kk], vsm[kk][d], acc);
    qinh[(b*NQ + q)*CH + h*HD + d] = __float2half(acc + qtok[q*CH + h*HD + d]);
}

// ---------------- window attention (fp16 tensor-core) ------------------
#define PADQ 40
#define PADP 88

__global__ void __launch_bounds__(256)
window_attn_kernel(const __half* __restrict__ qkvh,
                   const float* __restrict__ gk,
                   const float* __restrict__ gv,
                   const float* __restrict__ rpb,
                   float* __restrict__ attn_out,
                   __half* __restrict__ attouth) {
    int h   = blockIdx.x & 7;
    int win = blockIdx.x >> 3;
    int wx = win & 7, wy = (win >> 3) & 7, b = win >> 6;
    int n_base = (wy*WS)*GRIDW + wx*WS;

    __shared__ __half qs[64][PADQ];
    __shared__ __half ks[80][PADQ];
    __shared__ __half vt[32][PADP];
    __shared__ __half ph[64][PADP];
    __shared__ float  lg[64][80];

    int tid = threadIdx.x;
    int warp = tid >> 5, lane = tid & 31;
    int g = lane >> 2, tg = lane & 3;

    for (int idx = tid; idx < 64*32; idx += 256) {
        int i = idx >> 5, d = idx & 31;
        int n = n_base + (i >> 3)*GRIDW + (i & 7);
        float qv = __half2float(qkvh[((long)b*NTOK + n)*(3*CH) + h*HD + d]);
        qs[i][d] = __float2half(qv * SCALE);
    }
    for (int idx = tid; idx < 80*32; idx += 256) {
        int j = idx >> 5, d = idx & 31;
        float kv = 0.f, vv = 0.f;
        if (j < 64) {
            int n = n_base + (j >> 3)*GRIDW + (j & 7);
            long base = ((long)b*NTOK + n)*(3*CH) + h*HD + d;
            kv = __half2float(qkvh[base + CH]);
            vv = __half2float(qkvh[base + 2*CH]);
        } else if (j < 72) {
            int nq = j - 64;
            kv = gk[(b*NQ + nq)*CH + h*HD + d];
            vv = gv[(b*NQ + nq)*CH + h*HD + d];
        }
        ks[j][d] = __float2half(kv);
        vt[d][j] = __float2half(vv);
    }
    for (int idx = tid; idx < 64*8; idx += 256) {
        int i = idx >> 3, jj = idx & 7;
        ph[i][72 + jj] = __float2half(0.f);
    }
    __syncthreads();

    {
        int mw = (warp >> 1)*16, np = (warp & 1)*40;
        float acc[5][4] = {};
        #pragma unroll
        for (int kt = 0; kt < 2; kt++) {
            int k0 = kt*16;
            unsigned a[4];
            a[0] = *(const unsigned*)(&qs[mw+g][k0 + tg*2]);
            a[1] = *(const unsigned*)(&qs[mw+g+8][k0 + tg*2]);
            a[2] = *(const unsigned*)(&qs[mw+g][k0 + tg*2 + 8]);
            a[3] = *(const unsigned*)(&qs[mw+g+8][k0 + tg*2 + 8]);
            #pragma unroll
            for (int nt = 0; nt < 5; nt++) {
                int nb = np + nt*8 + g;
                unsigned bb[2];
                bb[0] = *(const unsigned*)(&ks[nb][k0 + tg*2]);
                bb[1] = *(const unsigned*)(&ks[nb][k0 + tg*2 + 8]);
                mma_f16(acc[nt], a, bb);
            }
        }
        #pragma unroll
        for (int nt = 0; nt < 5; nt++) {
            #pragma unroll
            for (int c = 0; c < 4; c++) {
                int i = mw + g + (c >> 1)*8;
                int j = np + nt*8 + tg*2 + (c & 1);
                float s = acc[nt][c];
                if (j < 64) {
                    int diy = (i >> 3) - (j >> 3) + 7;
                    int dix = (i & 7) - (j & 7) + 7;
                    s += rpb[(diy*15 + dix)*HEADS + h];
                }
                lg[i][j] = s;
            }
        }
    }
    __syncthreads();

    for (int it = 0; it < 8; it++) {
        int i = it*8 + warp;
        float m = -1e30f;
        for (int j = lane; j < KVLEN; j += 32) m = fmaxf(m, lg[i][j]);
        #pragma unroll
        for (int o = 16; o; o >>= 1) m = fmaxf(m, __shfl_xor_sync(~0u, m, o));
        float s = 0.f;
        for (int j = lane; j < KVLEN; j += 32) { float e = __expf(lg[i][j] - m); lg[i][j] = e; s += e; }
        #pragma unroll
        for (int o = 16; o; o >>= 1) s += __shfl_xor_sync(~0u, s, o);
        float inv = 1.f / s;
        for (int j = lane; j < KVLEN; j += 32) lg[i][j] *= inv;
    }
    __syncthreads();

    long abase = ((long)(win*HEADS + h))*64*KVLEN;
    for (int idx = tid; idx < 64*KVLEN; idx += 256) {
        int i = idx / KVLEN, j = idx - i*KVLEN;
        float p = lg[i][j];
        attn_out[abase + idx] = p;
        ph[i][j] = __float2half(p);
    }
    __syncthreads();

    {
        int mw = (warp >> 1)*16, nv = (warp & 1)*16;
        float acc[2][4] = {};
        #pragma unroll
        for (int kt = 0; kt < 5; kt++) {
            int k0 = kt*16;
            unsigned a[4];
            a[0] = *(const unsigned*)(&ph[mw+g][k0 + tg*2]);
            a[1] = *(const unsigned*)(&ph[mw+g+8][k0 + tg*2]);
            a[2] = *(const unsigned*)(&ph[mw+g][k0 + tg*2 + 8]);
            a[3] = *(const unsigned*)(&ph[mw+g+8][k0 + tg*2 + 8]);
            #pragma unroll
            for (int nt = 0; nt < 2; nt++) {
                int nb = nv + nt*8 + g;
                unsigned bb[2];
                bb[0] = *(const unsigned*)(&vt[nb][k0 + tg*2]);
                bb[1] = *(const unsigned*)(&vt[nb][k0 + tg*2 + 8]);
                mma_f16(acc[nt], a, bb);
            }
        }
        #pragma unroll
        for (int nt = 0; nt < 2; nt++) {
            #pragma unroll
            for (int c = 0; c < 4; c++) {
                int i = mw + g + (c >> 1)*8;
                int d = nv + nt*8 + tg*2 + (c & 1);
                int n = n_base + (i >> 3)*GRIDW + (i & 7);
                attouth[((long)b*NTOK + n)*CH + h*HD + d] = __float2half(acc[nt][c]);
            }
        }
    }
}

// ---------------- host launch ------------------------------------------
#define GEMM_SMEM (NSTAGE*STG2*2)

extern "C" void kernel_launch(void* const* d_in, const int* in_sizes, int n_in,
                              void* d_out, int out_size) {
    const float* x       = (const float*)d_in[0];
    const float* qtok    = (const float*)d_in[1];
    const float* kproj_w = (const float*)d_in[2];
    const float* kproj_b = (const float*)d_in[3];
    const float* kbn_g   = (const float*)d_in[4];
    const float* kbn_b   = (const float*)d_in[5];
    const float* kbn_m   = (const float*)d_in[6];
    const float* kbn_v   = (const float*)d_in[7];
    const float* vproj_w = (const float*)d_in[8];
    const float* vproj_b = (const float*)d_in[9];
    const float* vbn_g   = (const float*)d_in[10];
    const float* vbn_b   = (const float*)d_in[11];
    const float* vbn_m   = (const float*)d_in[12];
    const float* vbn_v   = (const float*)d_in[13];
    const float* ck_w    = (const float*)d_in[14];
    const float* ck_b    = (const float*)d_in[15];
    const float* cv_w    = (const float*)d_in[16];
    const float* cv_b    = (const float*)d_in[17];
    const float* rpb     = (const float*)d_in[18];
    const float* qkv_w   = (const float*)d_in[19];
    const float* qkv_b   = (const float*)d_in[20];
    const float* proj_w  = (const float*)d_in[21];
    const float* proj_b  = (const float*)d_in[22];
    const float* n1_g    = (const float*)d_in[23];
    const float* n1_b    = (const float*)d_in[24];
    const float* n2_g    = (const float*)d_in[25];
    const float* n2_b    = (const float*)d_in[26];
    const float* fc1_w   = (const float*)d_in[27];
    const float* fc1_b   = (const float*)d_in[28];
    const float* fc2_w   = (const float*)d_in[29];
    const float* fc2_b   = (const float*)d_in[30];

    float* out_x    = (float*)d_out;
    float* out_attn = out_x + (long)BATCH*NTOK*CH;

    float *kpool, *vpool, *gk, *gv, *xnew;
    __half *xnh, *xmh, *attouth, *hh, *qkvh, *pooledh, *qinh;
    cudaGetSymbolAddress((void**)&xnh,     g_xnh);
    cudaGetSymbolAddress((void**)&pooledh, g_pooledh);
    cudaGetSymbolAddress((void**)&kpool,   g_kpool);
    cudaGetSymbolAddress((void**)&vpool,   g_vpool);
    cudaGetSymbolAddress((void**)&qinh,    g_qinh);
    cudaGetSymbolAddress((void**)&gk,      g_gk);
    cudaGetSymbolAddress((void**)&gv,      g_gv);
    cudaGetSymbolAddress((void**)&qkvh,    g_qkvh);
    cudaGetSymbolAddress((void**)&attouth, g_attouth);
    cudaGetSymbolAddress((void**)&xnew,    g_xnew);
    cudaGetSymbolAddress((void**)&xmh,     g_xmh);
    cudaGetSymbolAddress((void**)&hh,      g_hh);

    __half *wqkv, *wfc1, *wfc2, *wproj, *wkp, *wvp, *wck, *wcv;
    cudaGetSymbolAddress((void**)&wqkv,  g_wqkv);
    cudaGetSymbolAddress((void**)&wfc1,  g_wfc1);
    cudaGetSymbolAddress((void**)&wfc2,  g_wfc2);
    cudaGetSymbolAddress((void**)&wproj, g_wproj);
    cudaGetSymbolAddress((void**)&wkp,   g_wkp);
    cudaGetSymbolAddress((void**)&wvp,   g_wvp);
    cudaGetSymbolAddress((void**)&wck,   g_wck);
    cudaGetSymbolAddress((void**)&wcv,   g_wcv);

    static int init_done = 0;
    static cudaStream_t s_side;
    static cudaEvent_t ev_fork, ev_join;
    if (!init_done) {
        cudaFuncSetAttribute(mma_gemm<0,1>, cudaFuncAttributeMaxDynamicSharedMemorySize, GEMM_SMEM);
        cudaFuncSetAttribute(mma_gemm<0,0>, cudaFuncAttributeMaxDynamicSharedMemorySize, GEMM_SMEM);
        cudaFuncSetAttribute(mma_gemm<1,0>, cudaFuncAttributeMaxDynamicSharedMemorySize, GEMM_SMEM);
        cudaFuncSetAttribute(mma_gemm<2,1>, cudaFuncAttributeMaxDynamicSharedMemorySize, GEMM_SMEM);
        cudaFuncSetAttribute(mma_gemm<3,0>, cudaFuncAttributeMaxDynamicSharedMemorySize, GEMM_SMEM);
        cudaStreamCreateWithFlags(&s_side, cudaStreamNonBlocking);
        cudaEventCreateWithFlags(&ev_fork, cudaEventDisableTiming);
        cudaEventCreateWithFlags(&ev_join, cudaEventDisableTiming);
        init_done = 1;
    }

    const int M = BATCH*NTOK;   // 65536

    WC wc;
    wc.s[0]=qkv_w;  wc.d[0]=wqkv;  wc.n4[0]=49152;
    wc.s[1]=fc1_w;  wc.d[1]=wfc1;  wc.n4[1]=65536;
    wc.s[2]=fc2_w;  wc.d[2]=wfc2;  wc.n4[2]=65536;
    wc.s[3]=proj_w; wc.d[3]=wproj; wc.n4[3]=16384;
    wc.s[4]=kproj_w;wc.d[4]=wkp;   wc.n4[4]=16384;
    wc.s[5]=vproj_w;wc.d[5]=wvp;   wc.n4[5]=16384;
    wc.s[6]=ck_w;   wc.d[6]=wck;   wc.n4[6]=16384;
    wc.s[7]=cv_w;   wc.d[7]=wcv;   wc.n4[7]=16384;
    wconv_all<<<dim3(256, 8), 256>>>(wc);

    layernorm_kernel<<<M/8, 256>>>(x, n1_g, n1_b, xnh);

    // ---- fork: side stream runs the global-token branch ----
    cudaEventRecord(ev_fork, 0);
    cudaStreamWaitEvent(s_side, ev_fork, 0);

    pool_kernel<<<BATCH*HP2, 256, 0, s_side>>>(xnh, pooledh);
    GP kp = {wkp, kproj_b, kpool, 0, kbn_m, kbn_v, kbn_g, kbn_b};
    GP vp = {wvp, vproj_b, vpool, 0, vbn_m, vbn_v, vbn_g, vbn_b};
    mma_gemm<1,0><<<dim3(2, 32, 2), 256, GEMM_SMEM, s_side>>>(pooledh, BATCH*HP2, CH, CH, kp, vp);
    global_attn_kernel<<<BATCH*HEADS, 256, 0, s_side>>>(kpool, vpool, qtok, qinh);
    GP ckp = {wck, ck_b, gk, 0, 0, 0, 0, 0};
    GP cvp = {wcv, cv_b, gv, 0, 0, 0, 0, 0};
    mma_gemm<0,0><<<dim3(2, 1, 2), 256, GEMM_SMEM, s_side>>>(qinh, BATCH*NQ, CH, CH, ckp, cvp);
    cudaEventRecord(ev_join, s_side);

    // ---- main stream: qkv projection ----
    GP qkvp = {wqkv, qkv_b, 0, qkvh, 0, 0, 0, 0};
    mma_gemm<0,1><<<dim3(6, 512, 1), 256, GEMM_SMEM>>>(xnh, M, CH, 3*CH, qkvp, qkvp);

    cudaStreamWaitEvent(0, ev_join, 0);

    window_attn_kernel<<<BATCH*NWIN*HEADS, 256>>>(qkvh, gk, gv, rpb, out_attn, attouth);

    GP projp = {wproj, proj_b, xnew, 0, x, 0, 0, 0};
    mma_gemm<3,0><<<dim3(2, 512, 1), 256, GEMM_SMEM>>>(attouth, M, CH, CH, projp, projp);

    layernorm_kernel<<<M/8, 256>>>(xnew, n2_g, n2_b, xmh);

    GP fc1p = {wfc1, fc1_b, 0, hh, 0, 0, 0, 0};
    mma_gemm<2,1><<<dim3(8, 512, 1), 256, GEMM_SMEM>>>(xmh, M, CH, 4*CH, fc1p, fc1p);

    GP fc2p = {wfc2, fc2_b, out_x, 0, xnew, 0, 0, 0};
    mma_gemm<3,0><<<dim3(2, 512, 1), 256, GEMM_SMEM>>>(hh, M, 4*CH, CH, fc2p, fc2p);
}